// round 1
// baseline (speedup 1.0000x reference)
#include <cuda_runtime.h>
#include <cuda_bf16.h>
#include <math.h>

// Problem constants
#define BATCH 2
#define SEQ   2048
#define DIM   2048
#define HEADS 16
#define DHEAD 128

// Scratch (allocation-free rule: __device__ globals)
__device__ float g_Q[BATCH * SEQ * DIM];
__device__ float g_K[BATCH * SEQ * DIM];
__device__ float g_V[BATCH * SEQ * DIM];
__device__ float g_A[BATCH * SEQ * DIM];

// ---------------------------------------------------------------------------
// SGEMM:  Y[m][n] = sum_k X[m][k] * W[n][k] + bias[n]
// Both operands are K-major (row-major [rows, K]) so tiles load identically.
// 128x128 block tile, TK=8, 256 threads, 8x8 register microtile per thread.
// ---------------------------------------------------------------------------
#define GTM 128
#define GTN 128
#define GTK 8
#define GPAD 132  // smem row stride (floats), keeps 16B alignment, kills ld/st conflicts

__global__ __launch_bounds__(256) void sgemm_bias_kernel(
    const float* __restrict__ X, const float* __restrict__ W,
    const float* __restrict__ bias, float* __restrict__ Y,
    int M, int N, int K)
{
    __shared__ float As[GTK][GPAD];
    __shared__ float Bs[GTK][GPAD];

    const int tid = threadIdx.x;
    const int tx  = tid & 15;     // 0..15 -> N direction
    const int ty  = tid >> 4;     // 0..15 -> M direction
    const int bm  = blockIdx.y;
    const int bn  = blockIdx.x;

    const int lr  = tid >> 1;          // 0..127 row within tile
    const int c4  = (tid & 1) << 2;    // 0 or 4 (k offset)

    const float* Xp = X + (size_t)(bm * GTM + lr) * K + c4;
    const float* Wp = W + (size_t)(bn * GTN + lr) * K + c4;

    float acc[8][8];
    #pragma unroll
    for (int i = 0; i < 8; i++)
        #pragma unroll
        for (int j = 0; j < 8; j++) acc[i][j] = 0.f;

    for (int kt = 0; kt < K; kt += GTK) {
        float4 av = *(const float4*)(Xp + kt);
        float4 bv = *(const float4*)(Wp + kt);
        __syncthreads();
        As[c4 + 0][lr] = av.x; As[c4 + 1][lr] = av.y;
        As[c4 + 2][lr] = av.z; As[c4 + 3][lr] = av.w;
        Bs[c4 + 0][lr] = bv.x; Bs[c4 + 1][lr] = bv.y;
        Bs[c4 + 2][lr] = bv.z; Bs[c4 + 3][lr] = bv.w;
        __syncthreads();

        #pragma unroll
        for (int k = 0; k < GTK; k++) {
            float4 a0 = *(const float4*)&As[k][ty << 3];
            float4 a1 = *(const float4*)&As[k][(ty << 3) + 4];
            float4 b0 = *(const float4*)&Bs[k][tx << 3];
            float4 b1 = *(const float4*)&Bs[k][(tx << 3) + 4];
            float a[8] = {a0.x, a0.y, a0.z, a0.w, a1.x, a1.y, a1.z, a1.w};
            float b[8] = {b0.x, b0.y, b0.z, b0.w, b1.x, b1.y, b1.z, b1.w};
            #pragma unroll
            for (int i = 0; i < 8; i++)
                #pragma unroll
                for (int j = 0; j < 8; j++)
                    acc[i][j] = fmaf(a[i], b[j], acc[i][j]);
        }
    }

    const int row0 = bm * GTM + (ty << 3);
    const int col0 = bn * GTN + (tx << 3);
    float bb[8];
    #pragma unroll
    for (int j = 0; j < 8; j++) bb[j] = bias[col0 + j];

    #pragma unroll
    for (int i = 0; i < 8; i++) {
        float* yp = Y + (size_t)(row0 + i) * N + col0;
        float4 o0 = {acc[i][0] + bb[0], acc[i][1] + bb[1], acc[i][2] + bb[2], acc[i][3] + bb[3]};
        float4 o1 = {acc[i][4] + bb[4], acc[i][5] + bb[5], acc[i][6] + bb[6], acc[i][7] + bb[7]};
        *(float4*)(yp)     = o0;
        *(float4*)(yp + 4) = o1;
    }
}

// ---------------------------------------------------------------------------
// Causal flash attention (fp32).
// Grid: (S/64 q-tiles, H, B). 256 threads.
// Per block: 64 queries, loop over 64-key tiles up to (and incl.) the diagonal.
// Thread (tx,ty), tx=tid&15, ty=tid>>4:
//   S rows owned: ty + 16*ii (ii=0..3), cols: tx + 16*jj (jj=0..3)
//   O rows same, cols: tx + 16*c (c=0..7)
// Strided (x16) index maps + odd smem strides -> conflict-free LDS.
// ---------------------------------------------------------------------------
#define AQS 129  // Q/K/V smem row stride (floats)
#define APS 65   // P smem row stride
#define ATTN_SMEM_BYTES ((3 * 64 * AQS + 64 * APS) * 4)

__global__ __launch_bounds__(256) void attn_kernel(
    const float* __restrict__ Q, const float* __restrict__ K,
    const float* __restrict__ V, float* __restrict__ O)
{
    extern __shared__ float sm[];
    float* Qs = sm;                    // 64 x AQS
    float* Ks = Qs + 64 * AQS;         // 64 x AQS
    float* Vs = Ks + 64 * AQS;         // 64 x AQS
    float* Ps = Vs + 64 * AQS;         // 64 x APS

    const int tid = threadIdx.x;
    const int tx  = tid & 15;
    const int ty  = tid >> 4;
    const int qt  = blockIdx.x;
    const int h   = blockIdx.y;
    const int b   = blockIdx.z;

    const int q0 = qt * 64;
    const size_t baseBH = (size_t)b * SEQ * DIM + (size_t)h * DHEAD;
    const float* Qb = Q + baseBH;
    const float* Kb = K + baseBH;
    const float* Vb = V + baseBH;
    float*       Ob = O + baseBH;

    const float SCALE = 0.08838834764831843f;  // 1/sqrt(128)

    // Load + pre-scale Q tile
    for (int t = tid; t < 64 * 32; t += 256) {
        int r = t >> 5;
        int c = (t & 31) << 2;
        float4 v = *(const float4*)(Qb + (size_t)(q0 + r) * DIM + c);
        float* d = &Qs[r * AQS + c];
        d[0] = v.x * SCALE; d[1] = v.y * SCALE; d[2] = v.z * SCALE; d[3] = v.w * SCALE;
    }

    float m_i[4], l_i[4], o[4][8];
    #pragma unroll
    for (int ii = 0; ii < 4; ii++) {
        m_i[ii] = -INFINITY; l_i[ii] = 0.f;
        #pragma unroll
        for (int c = 0; c < 8; c++) o[ii][c] = 0.f;
    }

    for (int kt = 0; kt <= qt; kt++) {
        const int k0 = kt * 64;
        __syncthreads();  // previous iter's reads of Ks/Vs/Ps done; Qs ready (1st iter)
        for (int t = tid; t < 64 * 32; t += 256) {
            int r = t >> 5;
            int c = (t & 31) << 2;
            size_t g = (size_t)(k0 + r) * DIM + c;
            float4 kv = *(const float4*)(Kb + g);
            float4 vv = *(const float4*)(Vb + g);
            float* dk = &Ks[r * AQS + c];
            float* dv = &Vs[r * AQS + c];
            dk[0] = kv.x; dk[1] = kv.y; dk[2] = kv.z; dk[3] = kv.w;
            dv[0] = vv.x; dv[1] = vv.y; dv[2] = vv.z; dv[3] = vv.w;
        }
        __syncthreads();

        // S = (Q*scale) K^T   [4x4 per thread]
        float s[4][4];
        #pragma unroll
        for (int ii = 0; ii < 4; ii++)
            #pragma unroll
            for (int jj = 0; jj < 4; jj++) s[ii][jj] = 0.f;

        #pragma unroll 8
        for (int d = 0; d < DHEAD; d++) {
            float a[4], bb[4];
            #pragma unroll
            for (int ii = 0; ii < 4; ii++) a[ii]  = Qs[(ty + 16 * ii) * AQS + d];
            #pragma unroll
            for (int jj = 0; jj < 4; jj++) bb[jj] = Ks[(tx + 16 * jj) * AQS + d];
            #pragma unroll
            for (int ii = 0; ii < 4; ii++)
                #pragma unroll
                for (int jj = 0; jj < 4; jj++)
                    s[ii][jj] = fmaf(a[ii], bb[jj], s[ii][jj]);
        }

        // Causal mask (only needed on the diagonal tile)
        if (kt == qt) {
            #pragma unroll
            for (int ii = 0; ii < 4; ii++) {
                int rg = ty + 16 * ii;  // local row == global offset diff is same (q0==k0)
                #pragma unroll
                for (int jj = 0; jj < 4; jj++) {
                    int cg = tx + 16 * jj;
                    if (cg > rg) s[ii][jj] = -1e30f;
                }
            }
        }

        // Online softmax per row (reduce across the 16 tx lanes)
        #pragma unroll
        for (int ii = 0; ii < 4; ii++) {
            float mx = fmaxf(fmaxf(s[ii][0], s[ii][1]), fmaxf(s[ii][2], s[ii][3]));
            #pragma unroll
            for (int off = 1; off < 16; off <<= 1)
                mx = fmaxf(mx, __shfl_xor_sync(0xffffffffu, mx, off));
            float mnew = fmaxf(m_i[ii], mx);
            float corr = __expf(m_i[ii] - mnew);
            m_i[ii] = mnew;

            float rs = 0.f;
            #pragma unroll
            for (int jj = 0; jj < 4; jj++) {
                float p = __expf(s[ii][jj] - mnew);
                Ps[(ty + 16 * ii) * APS + (tx + 16 * jj)] = p;
                rs += p;
            }
            #pragma unroll
            for (int off = 1; off < 16; off <<= 1)
                rs += __shfl_xor_sync(0xffffffffu, rs, off);
            l_i[ii] = l_i[ii] * corr + rs;

            #pragma unroll
            for (int c = 0; c < 8; c++) o[ii][c] *= corr;
        }
        __syncthreads();  // Ps visible to all

        // O += P @ V
        #pragma unroll 4
        for (int j = 0; j < 64; j++) {
            float p[4], v[8];
            #pragma unroll
            for (int ii = 0; ii < 4; ii++) p[ii] = Ps[(ty + 16 * ii) * APS + j];
            #pragma unroll
            for (int c = 0; c < 8; c++)   v[c]  = Vs[j * AQS + tx + 16 * c];
            #pragma unroll
            for (int ii = 0; ii < 4; ii++)
                #pragma unroll
                for (int c = 0; c < 8; c++)
                    o[ii][c] = fmaf(p[ii], v[c], o[ii][c]);
        }
    }

    // Normalize + write
    #pragma unroll
    for (int ii = 0; ii < 4; ii++) {
        float inv = 1.f / l_i[ii];
        int row = q0 + ty + 16 * ii;
        float* op = Ob + (size_t)row * DIM;
        #pragma unroll
        for (int c = 0; c < 8; c++)
            op[tx + 16 * c] = o[ii][c] * inv;
    }
}

// ---------------------------------------------------------------------------
extern "C" void kernel_launch(void* const* d_in, const int* in_sizes, int n_in,
                              void* d_out, int out_size)
{
    const float* x  = (const float*)d_in[0];
    const float* Wq = (const float*)d_in[1];
    const float* bq = (const float*)d_in[2];
    const float* Wk = (const float*)d_in[3];
    const float* bk = (const float*)d_in[4];
    const float* Wv = (const float*)d_in[5];
    const float* bv = (const float*)d_in[6];
    const float* Wo = (const float*)d_in[7];
    const float* bo = (const float*)d_in[8];
    float* out = (float*)d_out;

    float *Qs, *Ks, *Vs, *As;
    cudaGetSymbolAddress((void**)&Qs, g_Q);
    cudaGetSymbolAddress((void**)&Ks, g_K);
    cudaGetSymbolAddress((void**)&Vs, g_V);
    cudaGetSymbolAddress((void**)&As, g_A);

    const int M = BATCH * SEQ;   // 4096
    const int N = DIM;           // 2048
    const int Kd = DIM;          // 2048
    dim3 ggrid(N / GTN, M / GTM);

    // QKV projections
    sgemm_bias_kernel<<<ggrid, 256>>>(x, Wq, bq, Qs, M, N, Kd);
    sgemm_bias_kernel<<<ggrid, 256>>>(x, Wk, bk, Ks, M, N, Kd);
    sgemm_bias_kernel<<<ggrid, 256>>>(x, Wv, bv, Vs, M, N, Kd);

    // Attention (dynamic smem > 48KB)
    static int smem_set = 0;
    cudaFuncSetAttribute(attn_kernel, cudaFuncAttributeMaxDynamicSharedMemorySize,
                         ATTN_SMEM_BYTES);
    (void)smem_set;
    dim3 agrid(SEQ / 64, HEADS, BATCH);
    attn_kernel<<<agrid, 256, ATTN_SMEM_BYTES>>>(Qs, Ks, Vs, As);

    // Output projection
    sgemm_bias_kernel<<<ggrid, 256>>>(As, Wo, bo, out, M, N, Kd);
}

// round 3
// speedup vs baseline: 1.9847x; 1.9847x over previous
#include <cuda_runtime.h>
#include <cuda_fp16.h>
#include <math.h>
#include <stdint.h>

// Problem constants
#define BATCH 2
#define SEQ   2048
#define DIM   2048
#define HEADS 16
#define DHEAD 128
#define MTOT  (BATCH * SEQ)   // 4096

// ---------------------------------------------------------------------------
// Scratch (allocation-free rule: __device__ globals)
// ---------------------------------------------------------------------------
__device__ float g_Q[MTOT * DIM];
__device__ float g_K[MTOT * DIM];
__device__ float g_V[MTOT * DIM];
__device__ float g_A[MTOT * DIM];

__device__ __half g_Xhi[MTOT * DIM];
__device__ __half g_Xlo[MTOT * DIM];
__device__ __half g_Whi[4][DIM * DIM];
__device__ __half g_Wlo[4][DIM * DIM];
__device__ __half g_Ahi[MTOT * DIM];
__device__ __half g_Alo[MTOT * DIM];

// ---------------------------------------------------------------------------
// PTX helpers (portable sm_80+ : cp.async, ldmatrix, mma.sync)
// ---------------------------------------------------------------------------
__device__ __forceinline__ uint32_t smem_u32(const void* p) {
    uint32_t a;
    asm("{ .reg .u64 t; cvta.to.shared.u64 t, %1; cvt.u32.u64 %0, t; }" : "=r"(a) : "l"(p));
    return a;
}

#define CP_ASYNC_16(dst_u32, src_ptr) \
    asm volatile("cp.async.cg.shared.global [%0], [%1], 16;" \
                 :: "r"(dst_u32), "l"(src_ptr) : "memory")
#define CP_ASYNC_COMMIT() asm volatile("cp.async.commit_group;" ::: "memory")
#define CP_ASYNC_WAIT_1() asm volatile("cp.async.wait_group 1;" ::: "memory")

__device__ __forceinline__ void ldmatrix_x4(uint32_t* r, uint32_t addr) {
    asm volatile("ldmatrix.sync.aligned.m8n8.x4.shared.b16 {%0,%1,%2,%3}, [%4];"
        : "=r"(r[0]), "=r"(r[1]), "=r"(r[2]), "=r"(r[3]) : "r"(addr));
}

__device__ __forceinline__ void mma16816(float* d, const uint32_t* a, const uint32_t* b) {
    asm volatile(
        "mma.sync.aligned.m16n8k16.row.col.f32.f16.f16.f32 "
        "{%0,%1,%2,%3}, {%4,%5,%6,%7}, {%8,%9}, {%0,%1,%2,%3};"
        : "+f"(d[0]), "+f"(d[1]), "+f"(d[2]), "+f"(d[3])
        : "r"(a[0]), "r"(a[1]), "r"(a[2]), "r"(a[3]), "r"(b[0]), "r"(b[1]));
}

// 128B-row XOR swizzle: 16B-granular, conflict-free for ldmatrix over 8 rows
#define SWZ(x) ((x) ^ (((x) >> 3) & 0x70))

// ---------------------------------------------------------------------------
// Split fp32 -> (hi, lo) fp16 pair
// ---------------------------------------------------------------------------
__global__ __launch_bounds__(256) void split_kernel(
    const float* __restrict__ in, __half* __restrict__ hi,
    __half* __restrict__ lo, int n4)
{
    int i = blockIdx.x * 256 + threadIdx.x;
    if (i >= n4) return;
    float4 v = ((const float4*)in)[i];
    __half hx = __float2half_rn(v.x), hy = __float2half_rn(v.y);
    __half hz = __float2half_rn(v.z), hw = __float2half_rn(v.w);
    __half lx = __float2half_rn(v.x - __half2float(hx));
    __half ly = __float2half_rn(v.y - __half2float(hy));
    __half lz = __float2half_rn(v.z - __half2float(hz));
    __half lw = __float2half_rn(v.w - __half2float(hw));
    ((__half2*)hi)[2 * i]     = __halves2half2(hx, hy);
    ((__half2*)hi)[2 * i + 1] = __halves2half2(hz, hw);
    ((__half2*)lo)[2 * i]     = __halves2half2(lx, ly);
    ((__half2*)lo)[2 * i + 1] = __halves2half2(lz, lw);
}

// ---------------------------------------------------------------------------
// HMMA split-fp16 GEMM:  Y[m][n] = sum_k X[m][k]*W[n][k] + bias[n]
// CTA tile 128x128, 8 warps (4m x 2n), warp tile 32x64, K chunk 64.
// 3-stage cp.async ring. 3 MMAs per k-step: hi*hi + hi*lo + lo*hi.
// ---------------------------------------------------------------------------
#define TM 128
#define TN 128
#define TKC 64
#define NCHUNK (DIM / TKC)         // 32
#define TILE_BYTES 16384           // 128 rows x 128 bytes
#define SM_A_HI 0
#define SM_A_LO 16384
#define SM_B_HI 32768
#define SM_B_LO 49152
#define STAGE_BYTES 65536
#define NSTAGE 3
#define GEMM_SMEM (NSTAGE * STAGE_BYTES)   // 196608

__device__ __forceinline__ void load_stage(
    uint32_t sb, const __half* __restrict__ Ahi, const __half* __restrict__ Alo,
    const __half* __restrict__ Bhi, const __half* __restrict__ Blo,
    int m0, int n0, int k0, int tid)
{
    #pragma unroll
    for (int it = 0; it < 4; it++) {
        int t = tid + it * 256;            // 0..1023
        int row = t >> 3;
        int kk = (t & 7) * 8;              // half offset within chunk
        uint32_t soff = SWZ((uint32_t)(row * 128 + kk * 2));
        CP_ASYNC_16(sb + SM_A_HI + soff, Ahi + (size_t)(m0 + row) * DIM + k0 + kk);
        CP_ASYNC_16(sb + SM_A_LO + soff, Alo + (size_t)(m0 + row) * DIM + k0 + kk);
        CP_ASYNC_16(sb + SM_B_HI + soff, Bhi + (size_t)(n0 + row) * DIM + k0 + kk);
        CP_ASYNC_16(sb + SM_B_LO + soff, Blo + (size_t)(n0 + row) * DIM + k0 + kk);
    }
}

__global__ __launch_bounds__(256, 1) void gemm_tc_kernel(
    const __half* __restrict__ Ahi, const __half* __restrict__ Alo,
    const __half* __restrict__ Bhi, const __half* __restrict__ Blo,
    const float* __restrict__ bias, float* __restrict__ Y)
{
    extern __shared__ char smem[];
    const uint32_t smem_base = smem_u32(smem);
    const int tid = threadIdx.x;
    const int wid = tid >> 5;
    const int lane = tid & 31;
    const int warp_m = wid & 3;        // 0..3  -> m base warp_m*32
    const int warp_n = wid >> 2;       // 0..1  -> n base warp_n*64
    const int m0 = blockIdx.x * TM;
    const int n0 = blockIdx.y * TN;

    float acc[2][8][4];
    #pragma unroll
    for (int mi = 0; mi < 2; mi++)
        #pragma unroll
        for (int ni = 0; ni < 8; ni++)
            #pragma unroll
            for (int r = 0; r < 4; r++) acc[mi][ni][r] = 0.f;

    // Prologue: stages 0 and 1
    load_stage(smem_base, Ahi, Alo, Bhi, Blo, m0, n0, 0, tid);
    CP_ASYNC_COMMIT();
    load_stage(smem_base + STAGE_BYTES, Ahi, Alo, Bhi, Blo, m0, n0, TKC, tid);
    CP_ASYNC_COMMIT();

    // Per-thread ldmatrix address offsets (within a tile)
    const int a_row = (lane & 15);              // + mi*16 + warp_m*32
    const int a_kb  = (lane >> 4) << 4;         // 0 or 16 bytes
    const int b_row = ((lane >> 4) << 3) + (lane & 7);   // + pi*16 + warp_n*64
    const int b_kb  = ((lane >> 3) & 1) << 4;   // 0 or 16 bytes

    int slot = 0;
    for (int c = 0; c < NCHUNK; c++) {
        CP_ASYNC_WAIT_1();
        __syncthreads();

        if (c + 2 < NCHUNK) {
            int s2 = slot + 2; if (s2 >= NSTAGE) s2 -= NSTAGE;
            load_stage(smem_base + s2 * STAGE_BYTES, Ahi, Alo, Bhi, Blo,
                       m0, n0, (c + 2) * TKC, tid);
        }
        CP_ASYNC_COMMIT();

        const uint32_t sb = smem_base + slot * STAGE_BYTES;
        #pragma unroll
        for (int ks = 0; ks < 4; ks++) {
            const int kbyte = ks * 32;
            uint32_t a_hi[2][4], a_lo[2][4], b_hi[4][4], b_lo[4][4];
            #pragma unroll
            for (int mi = 0; mi < 2; mi++) {
                uint32_t off = SWZ((uint32_t)((warp_m * 32 + mi * 16 + a_row) * 128 + kbyte + a_kb));
                ldmatrix_x4(a_hi[mi], sb + SM_A_HI + off);
                ldmatrix_x4(a_lo[mi], sb + SM_A_LO + off);
            }
            #pragma unroll
            for (int pi = 0; pi < 4; pi++) {
                uint32_t off = SWZ((uint32_t)((warp_n * 64 + pi * 16 + b_row) * 128 + kbyte + b_kb));
                ldmatrix_x4(b_hi[pi], sb + SM_B_HI + off);
                ldmatrix_x4(b_lo[pi], sb + SM_B_LO + off);
            }
            #pragma unroll
            for (int mi = 0; mi < 2; mi++)
                #pragma unroll
                for (int ni = 0; ni < 8; ni++) {
                    const uint32_t* bh = &b_hi[ni >> 1][(ni & 1) * 2];
                    const uint32_t* bl = &b_lo[ni >> 1][(ni & 1) * 2];
                    mma16816(acc[mi][ni], a_hi[mi], bh);
                    mma16816(acc[mi][ni], a_hi[mi], bl);
                    mma16816(acc[mi][ni], a_lo[mi], bh);
                }
        }
        slot++; if (slot >= NSTAGE) slot = 0;
    }

    // Epilogue: direct stores with bias
    const int gm0 = m0 + warp_m * 32;
    const int gn0 = n0 + warp_n * 64;
    #pragma unroll
    for (int mi = 0; mi < 2; mi++) {
        int row = gm0 + mi * 16 + (lane >> 2);
        #pragma unroll
        for (int ni = 0; ni < 8; ni++) {
            int col = gn0 + ni * 8 + 2 * (lane & 3);
            float2 b2 = *(const float2*)&bias[col];
            float2 v0 = {acc[mi][ni][0] + b2.x, acc[mi][ni][1] + b2.y};
            float2 v1 = {acc[mi][ni][2] + b2.x, acc[mi][ni][3] + b2.y};
            *(float2*)&Y[(size_t)row * DIM + col]       = v0;
            *(float2*)&Y[(size_t)(row + 8) * DIM + col] = v1;
        }
    }
}

// ---------------------------------------------------------------------------
// Causal flash attention (fp32) — unchanged from R0
// ---------------------------------------------------------------------------
#define AQS 129
#define APS 65
#define ATTN_SMEM_BYTES ((3 * 64 * AQS + 64 * APS) * 4)

__global__ __launch_bounds__(256) void attn_kernel(
    const float* __restrict__ Q, const float* __restrict__ K,
    const float* __restrict__ V, float* __restrict__ O)
{
    extern __shared__ float sm[];
    float* Qs = sm;
    float* Ks = Qs + 64 * AQS;
    float* Vs = Ks + 64 * AQS;
    float* Ps = Vs + 64 * AQS;

    const int tid = threadIdx.x;
    const int tx  = tid & 15;
    const int ty  = tid >> 4;
    const int qt  = blockIdx.x;
    const int h   = blockIdx.y;
    const int b   = blockIdx.z;

    const int q0 = qt * 64;
    const size_t baseBH = (size_t)b * SEQ * DIM + (size_t)h * DHEAD;
    const float* Qb = Q + baseBH;
    const float* Kb = K + baseBH;
    const float* Vb = V + baseBH;
    float*       Ob = O + baseBH;

    const float SCALE = 0.08838834764831843f;

    for (int t = tid; t < 64 * 32; t += 256) {
        int r = t >> 5;
        int c = (t & 31) << 2;
        float4 v = *(const float4*)(Qb + (size_t)(q0 + r) * DIM + c);
        float* d = &Qs[r * AQS + c];
        d[0] = v.x * SCALE; d[1] = v.y * SCALE; d[2] = v.z * SCALE; d[3] = v.w * SCALE;
    }

    float m_i[4], l_i[4], o[4][8];
    #pragma unroll
    for (int ii = 0; ii < 4; ii++) {
        m_i[ii] = -INFINITY; l_i[ii] = 0.f;
        #pragma unroll
        for (int c = 0; c < 8; c++) o[ii][c] = 0.f;
    }

    for (int kt = 0; kt <= qt; kt++) {
        const int k0 = kt * 64;
        __syncthreads();
        for (int t = tid; t < 64 * 32; t += 256) {
            int r = t >> 5;
            int c = (t & 31) << 2;
            size_t g = (size_t)(k0 + r) * DIM + c;
            float4 kv = *(const float4*)(Kb + g);
            float4 vv = *(const float4*)(Vb + g);
            float* dk = &Ks[r * AQS + c];
            float* dv = &Vs[r * AQS + c];
            dk[0] = kv.x; dk[1] = kv.y; dk[2] = kv.z; dk[3] = kv.w;
            dv[0] = vv.x; dv[1] = vv.y; dv[2] = vv.z; dv[3] = vv.w;
        }
        __syncthreads();

        float s[4][4];
        #pragma unroll
        for (int ii = 0; ii < 4; ii++)
            #pragma unroll
            for (int jj = 0; jj < 4; jj++) s[ii][jj] = 0.f;

        #pragma unroll 8
        for (int d = 0; d < DHEAD; d++) {
            float a[4], bb[4];
            #pragma unroll
            for (int ii = 0; ii < 4; ii++) a[ii]  = Qs[(ty + 16 * ii) * AQS + d];
            #pragma unroll
            for (int jj = 0; jj < 4; jj++) bb[jj] = Ks[(tx + 16 * jj) * AQS + d];
            #pragma unroll
            for (int ii = 0; ii < 4; ii++)
                #pragma unroll
                for (int jj = 0; jj < 4; jj++)
                    s[ii][jj] = fmaf(a[ii], bb[jj], s[ii][jj]);
        }

        if (kt == qt) {
            #pragma unroll
            for (int ii = 0; ii < 4; ii++) {
                int rg = ty + 16 * ii;
                #pragma unroll
                for (int jj = 0; jj < 4; jj++) {
                    int cg = tx + 16 * jj;
                    if (cg > rg) s[ii][jj] = -1e30f;
                }
            }
        }

        #pragma unroll
        for (int ii = 0; ii < 4; ii++) {
            float mx = fmaxf(fmaxf(s[ii][0], s[ii][1]), fmaxf(s[ii][2], s[ii][3]));
            #pragma unroll
            for (int off = 1; off < 16; off <<= 1)
                mx = fmaxf(mx, __shfl_xor_sync(0xffffffffu, mx, off));
            float mnew = fmaxf(m_i[ii], mx);
            float corr = __expf(m_i[ii] - mnew);
            m_i[ii] = mnew;

            float rs = 0.f;
            #pragma unroll
            for (int jj = 0; jj < 4; jj++) {
                float p = __expf(s[ii][jj] - mnew);
                Ps[(ty + 16 * ii) * APS + (tx + 16 * jj)] = p;
                rs += p;
            }
            #pragma unroll
            for (int off = 1; off < 16; off <<= 1)
                rs += __shfl_xor_sync(0xffffffffu, rs, off);
            l_i[ii] = l_i[ii] * corr + rs;

            #pragma unroll
            for (int c = 0; c < 8; c++) o[ii][c] *= corr;
        }
        __syncthreads();

        #pragma unroll 4
        for (int j = 0; j < 64; j++) {
            float p[4], v[8];
            #pragma unroll
            for (int ii = 0; ii < 4; ii++) p[ii] = Ps[(ty + 16 * ii) * APS + j];
            #pragma unroll
            for (int c = 0; c < 8; c++)   v[c]  = Vs[j * AQS + tx + 16 * c];
            #pragma unroll
            for (int ii = 0; ii < 4; ii++)
                #pragma unroll
                for (int c = 0; c < 8; c++)
                    o[ii][c] = fmaf(p[ii], v[c], o[ii][c]);
        }
    }

    #pragma unroll
    for (int ii = 0; ii < 4; ii++) {
        float inv = 1.f / l_i[ii];
        int row = q0 + ty + 16 * ii;
        float* op = Ob + (size_t)row * DIM;
        #pragma unroll
        for (int c = 0; c < 8; c++)
            op[tx + 16 * c] = o[ii][c] * inv;
    }
}

// ---------------------------------------------------------------------------
extern "C" void kernel_launch(void* const* d_in, const int* in_sizes, int n_in,
                              void* d_out, int out_size)
{
    const float* x  = (const float*)d_in[0];
    const float* Wq = (const float*)d_in[1];
    const float* bq = (const float*)d_in[2];
    const float* Wk = (const float*)d_in[3];
    const float* bk = (const float*)d_in[4];
    const float* Wv = (const float*)d_in[5];
    const float* bv = (const float*)d_in[6];
    const float* Wo = (const float*)d_in[7];
    const float* bo = (const float*)d_in[8];
    float* out = (float*)d_out;

    float *Qs, *Ks, *Vs, *As;
    cudaGetSymbolAddress((void**)&Qs, g_Q);
    cudaGetSymbolAddress((void**)&Ks, g_K);
    cudaGetSymbolAddress((void**)&Vs, g_V);
    cudaGetSymbolAddress((void**)&As, g_A);
    __half *Xhi, *Xlo, *Whi, *Wlo, *Ahi, *Alo;
    cudaGetSymbolAddress((void**)&Xhi, g_Xhi);
    cudaGetSymbolAddress((void**)&Xlo, g_Xlo);
    cudaGetSymbolAddress((void**)&Whi, g_Whi);
    cudaGetSymbolAddress((void**)&Wlo, g_Wlo);
    cudaGetSymbolAddress((void**)&Ahi, g_Ahi);
    cudaGetSymbolAddress((void**)&Alo, g_Alo);

    cudaFuncSetAttribute(gemm_tc_kernel,
                         cudaFuncAttributeMaxDynamicSharedMemorySize, GEMM_SMEM);
    cudaFuncSetAttribute(attn_kernel,
                         cudaFuncAttributeMaxDynamicSharedMemorySize, ATTN_SMEM_BYTES);

    const int nX4 = MTOT * DIM / 4;
    const int nW4 = DIM * DIM / 4;
    const size_t WSZ = (size_t)DIM * DIM;

    // Split inputs to (hi, lo) fp16
    split_kernel<<<nX4 / 256, 256>>>(x,  Xhi, Xlo, nX4);
    split_kernel<<<nW4 / 256, 256>>>(Wq, Whi + 0 * WSZ, Wlo + 0 * WSZ, nW4);
    split_kernel<<<nW4 / 256, 256>>>(Wk, Whi + 1 * WSZ, Wlo + 1 * WSZ, nW4);
    split_kernel<<<nW4 / 256, 256>>>(Wv, Whi + 2 * WSZ, Wlo + 2 * WSZ, nW4);
    split_kernel<<<nW4 / 256, 256>>>(Wo, Whi + 3 * WSZ, Wlo + 3 * WSZ, nW4);

    // QKV projections on tensor cores (HMMA)
    dim3 ggrid(MTOT / TM, DIM / TN);   // (32, 16)
    gemm_tc_kernel<<<ggrid, 256, GEMM_SMEM>>>(Xhi, Xlo, Whi + 0 * WSZ, Wlo + 0 * WSZ, bq, Qs);
    gemm_tc_kernel<<<ggrid, 256, GEMM_SMEM>>>(Xhi, Xlo, Whi + 1 * WSZ, Wlo + 1 * WSZ, bk, Ks);
    gemm_tc_kernel<<<ggrid, 256, GEMM_SMEM>>>(Xhi, Xlo, Whi + 2 * WSZ, Wlo + 2 * WSZ, bv, Vs);

    // Attention (fp32)
    dim3 agrid(SEQ / 64, HEADS, BATCH);
    attn_kernel<<<agrid, 256, ATTN_SMEM_BYTES>>>(Qs, Ks, Vs, As);

    // Split attention output, then output projection
    split_kernel<<<nX4 / 256, 256>>>(As, Ahi, Alo, nX4);
    gemm_tc_kernel<<<ggrid, 256, GEMM_SMEM>>>(Ahi, Alo, Whi + 3 * WSZ, Wlo + 3 * WSZ, bo, out);
}

// round 4
// speedup vs baseline: 3.5189x; 1.7730x over previous
#include <cuda_runtime.h>
#include <cuda_fp16.h>
#include <math.h>
#include <stdint.h>

// Problem constants
#define BATCH 2
#define SEQ   2048
#define DIM   2048
#define HEADS 16
#define DHEAD 128
#define MTOT  (BATCH * SEQ)   // 4096

// ---------------------------------------------------------------------------
// Scratch (allocation-free rule: __device__ globals)
// ---------------------------------------------------------------------------
__device__ __half g_Xhi[MTOT * DIM];
__device__ __half g_Xlo[MTOT * DIM];
__device__ __half g_Whi[4][DIM * DIM];
__device__ __half g_Wlo[4][DIM * DIM];
__device__ __half g_Qhi[MTOT * DIM];
__device__ __half g_Qlo[MTOT * DIM];
__device__ __half g_Khi[MTOT * DIM];
__device__ __half g_Klo[MTOT * DIM];
__device__ __half g_Vhi[MTOT * DIM];
__device__ __half g_Vlo[MTOT * DIM];
__device__ __half g_Ahi[MTOT * DIM];
__device__ __half g_Alo[MTOT * DIM];

// ---------------------------------------------------------------------------
// PTX helpers (portable sm_80+ : cp.async, ldmatrix, mma.sync)
// ---------------------------------------------------------------------------
__device__ __forceinline__ uint32_t smem_u32(const void* p) {
    uint32_t a;
    asm("{ .reg .u64 t; cvta.to.shared.u64 t, %1; cvt.u32.u64 %0, t; }" : "=r"(a) : "l"(p));
    return a;
}

#define CP_ASYNC_16(dst_u32, src_ptr) \
    asm volatile("cp.async.cg.shared.global [%0], [%1], 16;" \
                 :: "r"(dst_u32), "l"(src_ptr) : "memory")
#define CP_ASYNC_COMMIT() asm volatile("cp.async.commit_group;" ::: "memory")
#define CP_ASYNC_WAIT_1() asm volatile("cp.async.wait_group 1;" ::: "memory")

__device__ __forceinline__ void ldmatrix_x4(uint32_t* r, uint32_t addr) {
    asm volatile("ldmatrix.sync.aligned.m8n8.x4.shared.b16 {%0,%1,%2,%3}, [%4];"
        : "=r"(r[0]), "=r"(r[1]), "=r"(r[2]), "=r"(r[3]) : "r"(addr));
}
__device__ __forceinline__ void ldmatrix_x4_trans(uint32_t* r, uint32_t addr) {
    asm volatile("ldmatrix.sync.aligned.m8n8.x4.trans.shared.b16 {%0,%1,%2,%3}, [%4];"
        : "=r"(r[0]), "=r"(r[1]), "=r"(r[2]), "=r"(r[3]) : "r"(addr));
}

__device__ __forceinline__ void mma16816(float* d, const uint32_t* a, const uint32_t* b) {
    asm volatile(
        "mma.sync.aligned.m16n8k16.row.col.f32.f16.f16.f32 "
        "{%0,%1,%2,%3}, {%4,%5,%6,%7}, {%8,%9}, {%0,%1,%2,%3};"
        : "+f"(d[0]), "+f"(d[1]), "+f"(d[2]), "+f"(d[3])
        : "r"(a[0]), "r"(a[1]), "r"(a[2]), "r"(a[3]), "r"(b[0]), "r"(b[1]));
}

// 128B-row XOR swizzle: conflict-free ldmatrix over 8 rows of 128B-stride tiles
#define SWZ(x) ((x) ^ (((x) >> 3) & 0x70))

// ---------------------------------------------------------------------------
// Split fp32 -> (hi, lo) fp16 pair
// ---------------------------------------------------------------------------
__global__ __launch_bounds__(256) void split_kernel(
    const float* __restrict__ in, __half* __restrict__ hi,
    __half* __restrict__ lo, int n4)
{
    int i = blockIdx.x * 256 + threadIdx.x;
    if (i >= n4) return;
    float4 v = ((const float4*)in)[i];
    __half hx = __float2half_rn(v.x), hy = __float2half_rn(v.y);
    __half hz = __float2half_rn(v.z), hw = __float2half_rn(v.w);
    __half lx = __float2half_rn(v.x - __half2float(hx));
    __half ly = __float2half_rn(v.y - __half2float(hy));
    __half lz = __float2half_rn(v.z - __half2float(hz));
    __half lw = __float2half_rn(v.w - __half2float(hw));
    ((__half2*)hi)[2 * i]     = __halves2half2(hx, hy);
    ((__half2*)hi)[2 * i + 1] = __halves2half2(hz, hw);
    ((__half2*)lo)[2 * i]     = __halves2half2(lx, ly);
    ((__half2*)lo)[2 * i + 1] = __halves2half2(lz, lw);
}

// ---------------------------------------------------------------------------
// HMMA split-fp16 GEMM:  Y[m][n] = sum_k X[m][k]*W[n][k] + bias[n]
// CTA 128x128, 8 warps (4m x 2n), warp tile 32x64, K chunk 64, 3-stage ring.
// HILO=true: write (hi,lo) fp16 pair; else fp32.
// ---------------------------------------------------------------------------
#define TM 128
#define TN 128
#define TKC 64
#define NCHUNK (DIM / TKC)
#define SM_A_HI 0
#define SM_A_LO 16384
#define SM_B_HI 32768
#define SM_B_LO 49152
#define STAGE_BYTES 65536
#define NSTAGE 3
#define GEMM_SMEM (NSTAGE * STAGE_BYTES)

__device__ __forceinline__ void load_stage(
    uint32_t sb, const __half* __restrict__ Ahi, const __half* __restrict__ Alo,
    const __half* __restrict__ Bhi, const __half* __restrict__ Blo,
    int m0, int n0, int k0, int tid)
{
    #pragma unroll
    for (int it = 0; it < 4; it++) {
        int t = tid + it * 256;
        int row = t >> 3;
        int kk = (t & 7) * 8;
        uint32_t soff = SWZ((uint32_t)(row * 128 + kk * 2));
        CP_ASYNC_16(sb + SM_A_HI + soff, Ahi + (size_t)(m0 + row) * DIM + k0 + kk);
        CP_ASYNC_16(sb + SM_A_LO + soff, Alo + (size_t)(m0 + row) * DIM + k0 + kk);
        CP_ASYNC_16(sb + SM_B_HI + soff, Bhi + (size_t)(n0 + row) * DIM + k0 + kk);
        CP_ASYNC_16(sb + SM_B_LO + soff, Blo + (size_t)(n0 + row) * DIM + k0 + kk);
    }
}

template <bool HILO>
__global__ __launch_bounds__(256, 1) void gemm_tc_kernel(
    const __half* __restrict__ Ahi, const __half* __restrict__ Alo,
    const __half* __restrict__ Bhi, const __half* __restrict__ Blo,
    const float* __restrict__ bias, float* __restrict__ Yf,
    __half* __restrict__ Yhi, __half* __restrict__ Ylo)
{
    extern __shared__ char smem[];
    const uint32_t smem_base = smem_u32(smem);
    const int tid = threadIdx.x;
    const int wid = tid >> 5;
    const int lane = tid & 31;
    const int warp_m = wid & 3;
    const int warp_n = wid >> 2;
    const int m0 = blockIdx.x * TM;
    const int n0 = blockIdx.y * TN;

    float acc[2][8][4];
    #pragma unroll
    for (int mi = 0; mi < 2; mi++)
        #pragma unroll
        for (int ni = 0; ni < 8; ni++)
            #pragma unroll
            for (int r = 0; r < 4; r++) acc[mi][ni][r] = 0.f;

    load_stage(smem_base, Ahi, Alo, Bhi, Blo, m0, n0, 0, tid);
    CP_ASYNC_COMMIT();
    load_stage(smem_base + STAGE_BYTES, Ahi, Alo, Bhi, Blo, m0, n0, TKC, tid);
    CP_ASYNC_COMMIT();

    const int a_row = (lane & 15);
    const int a_kb  = (lane >> 4) << 4;
    const int b_row = ((lane >> 4) << 3) + (lane & 7);
    const int b_kb  = ((lane >> 3) & 1) << 4;

    int slot = 0;
    for (int c = 0; c < NCHUNK; c++) {
        CP_ASYNC_WAIT_1();
        __syncthreads();

        if (c + 2 < NCHUNK) {
            int s2 = slot + 2; if (s2 >= NSTAGE) s2 -= NSTAGE;
            load_stage(smem_base + s2 * STAGE_BYTES, Ahi, Alo, Bhi, Blo,
                       m0, n0, (c + 2) * TKC, tid);
        }
        CP_ASYNC_COMMIT();

        const uint32_t sb = smem_base + slot * STAGE_BYTES;
        #pragma unroll
        for (int ks = 0; ks < 4; ks++) {
            const int kbyte = ks * 32;
            uint32_t a_hi[2][4], a_lo[2][4], b_hi[4][4], b_lo[4][4];
            #pragma unroll
            for (int mi = 0; mi < 2; mi++) {
                uint32_t off = SWZ((uint32_t)((warp_m * 32 + mi * 16 + a_row) * 128 + kbyte + a_kb));
                ldmatrix_x4(a_hi[mi], sb + SM_A_HI + off);
                ldmatrix_x4(a_lo[mi], sb + SM_A_LO + off);
            }
            #pragma unroll
            for (int pi = 0; pi < 4; pi++) {
                uint32_t off = SWZ((uint32_t)((warp_n * 64 + pi * 16 + b_row) * 128 + kbyte + b_kb));
                ldmatrix_x4(b_hi[pi], sb + SM_B_HI + off);
                ldmatrix_x4(b_lo[pi], sb + SM_B_LO + off);
            }
            #pragma unroll
            for (int mi = 0; mi < 2; mi++)
                #pragma unroll
                for (int ni = 0; ni < 8; ni++) {
                    const uint32_t* bh = &b_hi[ni >> 1][(ni & 1) * 2];
                    const uint32_t* bl = &b_lo[ni >> 1][(ni & 1) * 2];
                    mma16816(acc[mi][ni], a_hi[mi], bh);
                    mma16816(acc[mi][ni], a_hi[mi], bl);
                    mma16816(acc[mi][ni], a_lo[mi], bh);
                }
        }
        slot++; if (slot >= NSTAGE) slot = 0;
    }

    const int gm0 = m0 + warp_m * 32;
    const int gn0 = n0 + warp_n * 64;
    #pragma unroll
    for (int mi = 0; mi < 2; mi++) {
        int row = gm0 + mi * 16 + (lane >> 2);
        #pragma unroll
        for (int ni = 0; ni < 8; ni++) {
            int col = gn0 + ni * 8 + 2 * (lane & 3);
            float2 b2 = *(const float2*)&bias[col];
            float y0 = acc[mi][ni][0] + b2.x, y1 = acc[mi][ni][1] + b2.y;
            float y2 = acc[mi][ni][2] + b2.x, y3 = acc[mi][ni][3] + b2.y;
            if (HILO) {
                __half h0 = __float2half_rn(y0), h1 = __float2half_rn(y1);
                __half h2 = __float2half_rn(y2), h3 = __float2half_rn(y3);
                __half l0 = __float2half_rn(y0 - __half2float(h0));
                __half l1 = __float2half_rn(y1 - __half2float(h1));
                __half l2 = __float2half_rn(y2 - __half2float(h2));
                __half l3 = __float2half_rn(y3 - __half2float(h3));
                *(__half2*)&Yhi[(size_t)row * DIM + col]       = __halves2half2(h0, h1);
                *(__half2*)&Yhi[(size_t)(row + 8) * DIM + col] = __halves2half2(h2, h3);
                *(__half2*)&Ylo[(size_t)row * DIM + col]       = __halves2half2(l0, l1);
                *(__half2*)&Ylo[(size_t)(row + 8) * DIM + col] = __halves2half2(l2, l3);
            } else {
                *(float2*)&Yf[(size_t)row * DIM + col]       = make_float2(y0, y1);
                *(float2*)&Yf[(size_t)(row + 8) * DIM + col] = make_float2(y2, y3);
            }
        }
    }
}

// ---------------------------------------------------------------------------
// Tensor-core causal flash attention (split fp16, fp32 softmax).
// CTA: 128 queries, 8 warps (16 q each). Key tiles of 64, double-buffered.
// Smem: Q[hilo][plane][128][128B] 64KB | K[st][hilo][plane][64][128B] 64KB |
//       V same 64KB. Planes split dh into [0:64) and [64:128).
// ---------------------------------------------------------------------------
#define SM_Qb 0
#define SM_Kb 65536
#define SM_Vb 131072
#define ATTN_SMEM 196608
#define KSC 0.12751741219860918f   /* (1/sqrt(128)) * log2(e) */

__device__ __forceinline__ void attn_load_kv(
    uint32_t sb, const __half* __restrict__ Khi, const __half* __restrict__ Klo,
    const __half* __restrict__ Vhi, const __half* __restrict__ Vlo,
    size_t gbase, int k0, int stage, int tid)
{
    // 4096 16B chunks: [KV][hilo][row64][chunk16]
    #pragma unroll
    for (int i = 0; i < 16; i++) {
        int t = tid + i * 256;
        int kv  = t >> 11;
        int hil = (t >> 10) & 1;
        int row = (t >> 4) & 63;
        int ch  = t & 15;
        int pl  = ch >> 3;
        const __half* src;
        if (kv == 0) src = (hil ? Klo : Khi);
        else         src = (hil ? Vlo : Vhi);
        src += gbase + (size_t)(k0 + row) * DIM + ch * 8;
        uint32_t dst = sb + (kv == 0 ? SM_Kb : SM_Vb) + stage * 32768 + hil * 16384
                     + pl * 8192 + SWZ((uint32_t)(row * 128 + (ch & 7) * 16));
        CP_ASYNC_16(dst, src);
    }
}

__global__ __launch_bounds__(256, 1) void attn_tc_kernel(
    const __half* __restrict__ Qhi, const __half* __restrict__ Qlo,
    const __half* __restrict__ Khi, const __half* __restrict__ Klo,
    const __half* __restrict__ Vhi, const __half* __restrict__ Vlo,
    __half* __restrict__ Ahi, __half* __restrict__ Alo)
{
    extern __shared__ char smem[];
    const uint32_t sb = smem_u32(smem);
    const int tid = threadIdx.x;
    const int w = tid >> 5;
    const int lane = tid & 31;
    const int qt = gridDim.x - 1 - blockIdx.x;   // big tiles first
    const int h = blockIdx.y;
    const int b = blockIdx.z;
    const int q0 = qt * 128;
    const size_t gbase = (size_t)b * SEQ * DIM + (size_t)h * DHEAD;

    // Load Q tile (hi+lo)
    #pragma unroll
    for (int i = 0; i < 16; i++) {
        int t = tid + i * 256;
        int hil = t >> 11;
        int row = (t >> 4) & 127;
        int ch  = t & 15;
        int pl  = ch >> 3;
        const __half* src = (hil ? Qlo : Qhi) + gbase + (size_t)(q0 + row) * DIM + ch * 8;
        uint32_t dst = sb + SM_Qb + hil * 32768 + pl * 16384
                     + SWZ((uint32_t)(row * 128 + (ch & 7) * 16));
        CP_ASYNC_16(dst, src);
    }
    attn_load_kv(sb, Khi, Klo, Vhi, Vlo, gbase, 0, 0, tid);
    CP_ASYNC_COMMIT();

    float m0v = -1e30f, m1v = -1e30f, l0v = 0.f, l1v = 0.f;
    float acc_o[16][4];
    #pragma unroll
    for (int n = 0; n < 16; n++)
        #pragma unroll
        for (int r = 0; r < 4; r++) acc_o[n][r] = 0.f;

    const int a_row = lane & 15;
    const int a_kb  = (lane >> 4) << 4;
    const int b_row = ((lane >> 4) << 3) + (lane & 7);
    const int b_kb  = ((lane >> 3) & 1) << 4;
    const int v_row = (lane & 7) + ((lane >> 3) & 1) * 8;
    const int v_cb  = ((lane >> 4) & 1) << 4;

    const int qwmin = q0 + w * 16;
    const int nt = 2 * qt + 2;

    for (int kt = 0; kt < nt; kt++) {
        __syncthreads();
        if (kt + 1 < nt)
            attn_load_kv(sb, Khi, Klo, Vhi, Vlo, gbase, (kt + 1) * 64, (kt + 1) & 1, tid);
        CP_ASYNC_COMMIT();
        CP_ASYNC_WAIT_1();
        __syncthreads();

        const int k0 = kt * 64;
        const int st = kt & 1;
        if (k0 > qwmin + 15) continue;   // fully masked for this warp

        // ---- S = Q K^T (hi*hi + hi*lo + lo*hi) ----
        float s[8][4];
        #pragma unroll
        for (int ni = 0; ni < 8; ni++)
            #pragma unroll
            for (int r = 0; r < 4; r++) s[ni][r] = 0.f;

        #pragma unroll
        for (int ks = 0; ks < 8; ks++) {
            const int kbyte = (ks & 3) * 32;
            const int pl = ks >> 2;
            uint32_t aH[4], aL[4];
            uint32_t aoff = SM_Qb + pl * 16384
                          + SWZ((uint32_t)((w * 16 + a_row) * 128 + kbyte + a_kb));
            ldmatrix_x4(aH, sb + aoff);
            ldmatrix_x4(aL, sb + aoff + 32768);
            #pragma unroll
            for (int pi = 0; pi < 4; pi++) {
                uint32_t bH[4], bL[4];
                uint32_t boff = SM_Kb + st * 32768 + pl * 8192
                              + SWZ((uint32_t)((pi * 16 + b_row) * 128 + kbyte + b_kb));
                ldmatrix_x4(bH, sb + boff);
                ldmatrix_x4(bL, sb + boff + 16384);
                mma16816(s[2 * pi],     aH, &bH[0]);
                mma16816(s[2 * pi],     aH, &bL[0]);
                mma16816(s[2 * pi],     aL, &bH[0]);
                mma16816(s[2 * pi + 1], aH, &bH[2]);
                mma16816(s[2 * pi + 1], aH, &bL[2]);
                mma16816(s[2 * pi + 1], aL, &bH[2]);
            }
        }

        // ---- causal mask ----
        const int qr0 = qwmin + (lane >> 2);
        const int qr1 = qr0 + 8;
        if (k0 + 63 > qwmin) {
            const int kc = k0 + 2 * (lane & 3);
            #pragma unroll
            for (int ni = 0; ni < 8; ni++) {
                int kb2 = kc + ni * 8;
                if (kb2     > qr0) s[ni][0] = -1e30f;
                if (kb2 + 1 > qr0) s[ni][1] = -1e30f;
                if (kb2     > qr1) s[ni][2] = -1e30f;
                if (kb2 + 1 > qr1) s[ni][3] = -1e30f;
            }
        }

        // ---- online softmax (fp32, quad shfl reductions) ----
        float mx0 = -1e30f, mx1 = -1e30f;
        #pragma unroll
        for (int ni = 0; ni < 8; ni++) {
            mx0 = fmaxf(mx0, fmaxf(s[ni][0], s[ni][1]));
            mx1 = fmaxf(mx1, fmaxf(s[ni][2], s[ni][3]));
        }
        mx0 = fmaxf(mx0, __shfl_xor_sync(0xffffffffu, mx0, 1));
        mx0 = fmaxf(mx0, __shfl_xor_sync(0xffffffffu, mx0, 2));
        mx1 = fmaxf(mx1, __shfl_xor_sync(0xffffffffu, mx1, 1));
        mx1 = fmaxf(mx1, __shfl_xor_sync(0xffffffffu, mx1, 2));
        float mn0 = fmaxf(m0v, mx0), mn1 = fmaxf(m1v, mx1);
        float corr0 = exp2f((m0v - mn0) * KSC);
        float corr1 = exp2f((m1v - mn1) * KSC);
        m0v = mn0; m1v = mn1;

        float rs0 = 0.f, rs1 = 0.f;
        #pragma unroll
        for (int ni = 0; ni < 8; ni++) {
            s[ni][0] = exp2f((s[ni][0] - mn0) * KSC);
            s[ni][1] = exp2f((s[ni][1] - mn0) * KSC);
            s[ni][2] = exp2f((s[ni][2] - mn1) * KSC);
            s[ni][3] = exp2f((s[ni][3] - mn1) * KSC);
            rs0 += s[ni][0] + s[ni][1];
            rs1 += s[ni][2] + s[ni][3];
        }
        rs0 += __shfl_xor_sync(0xffffffffu, rs0, 1);
        rs0 += __shfl_xor_sync(0xffffffffu, rs0, 2);
        rs1 += __shfl_xor_sync(0xffffffffu, rs1, 1);
        rs1 += __shfl_xor_sync(0xffffffffu, rs1, 2);
        l0v = l0v * corr0 + rs0;
        l1v = l1v * corr1 + rs1;

        #pragma unroll
        for (int n = 0; n < 16; n++) {
            acc_o[n][0] *= corr0; acc_o[n][1] *= corr0;
            acc_o[n][2] *= corr1; acc_o[n][3] *= corr1;
        }

        // ---- O += P V (Phi*Vhi + Phi*Vlo + Plo*Vhi) ----
        #pragma unroll
        for (int vks = 0; vks < 4; vks++) {
            uint32_t pH[4], pL[4];
            #pragma unroll
            for (int half16 = 0; half16 < 2; half16++) {
                const float* sp = s[2 * vks + half16];
                __half2 h01 = __floats2half2_rn(sp[0], sp[1]);
                __half2 h23 = __floats2half2_rn(sp[2], sp[3]);
                float2 f01 = __half22float2(h01);
                float2 f23 = __half22float2(h23);
                __half2 l01 = __floats2half2_rn(sp[0] - f01.x, sp[1] - f01.y);
                __half2 l23 = __floats2half2_rn(sp[2] - f23.x, sp[3] - f23.y);
                pH[2 * half16]     = *(uint32_t*)&h01;
                pH[2 * half16 + 1] = *(uint32_t*)&h23;
                pL[2 * half16]     = *(uint32_t*)&l01;
                pL[2 * half16 + 1] = *(uint32_t*)&l23;
            }
            const int vr = vks * 16 + v_row;
            #pragma unroll
            for (int nb = 0; nb < 8; nb++) {
                uint32_t vH[4], vL[4];
                uint32_t voff = SM_Vb + st * 32768 + (nb >> 2) * 8192
                              + SWZ((uint32_t)(vr * 128 + (nb & 3) * 32 + v_cb));
                ldmatrix_x4_trans(vH, sb + voff);
                ldmatrix_x4_trans(vL, sb + voff + 16384);
                mma16816(acc_o[2 * nb],     pH, &vH[0]);
                mma16816(acc_o[2 * nb],     pH, &vL[0]);
                mma16816(acc_o[2 * nb],     pL, &vH[0]);
                mma16816(acc_o[2 * nb + 1], pH, &vH[2]);
                mma16816(acc_o[2 * nb + 1], pH, &vL[2]);
                mma16816(acc_o[2 * nb + 1], pL, &vH[2]);
            }
        }
    }

    // ---- normalize, split hi/lo, store ----
    const float inv0 = 1.f / l0v;
    const float inv1 = 1.f / l1v;
    const size_t r0o = gbase + (size_t)(q0 + w * 16 + (lane >> 2)) * DIM;
    const size_t r1o = r0o + 8 * DIM;
    #pragma unroll
    for (int n = 0; n < 16; n++) {
        int col = n * 8 + 2 * (lane & 3);
        float y0 = acc_o[n][0] * inv0, y1 = acc_o[n][1] * inv0;
        float y2 = acc_o[n][2] * inv1, y3 = acc_o[n][3] * inv1;
        __half h0 = __float2half_rn(y0), h1 = __float2half_rn(y1);
        __half h2 = __float2half_rn(y2), h3 = __float2half_rn(y3);
        __half l0h = __float2half_rn(y0 - __half2float(h0));
        __half l1h = __float2half_rn(y1 - __half2float(h1));
        __half l2h = __float2half_rn(y2 - __half2float(h2));
        __half l3h = __float2half_rn(y3 - __half2float(h3));
        *(__half2*)&Ahi[r0o + col] = __halves2half2(h0, h1);
        *(__half2*)&Ahi[r1o + col] = __halves2half2(h2, h3);
        *(__half2*)&Alo[r0o + col] = __halves2half2(l0h, l1h);
        *(__half2*)&Alo[r1o + col] = __halves2half2(l2h, l3h);
    }
}

// ---------------------------------------------------------------------------
extern "C" void kernel_launch(void* const* d_in, const int* in_sizes, int n_in,
                              void* d_out, int out_size)
{
    const float* x  = (const float*)d_in[0];
    const float* Wq = (const float*)d_in[1];
    const float* bq = (const float*)d_in[2];
    const float* Wk = (const float*)d_in[3];
    const float* bk = (const float*)d_in[4];
    const float* Wv = (const float*)d_in[5];
    const float* bv = (const float*)d_in[6];
    const float* Wo = (const float*)d_in[7];
    const float* bo = (const float*)d_in[8];
    float* out = (float*)d_out;

    __half *Xhi, *Xlo, *Whi, *Wlo;
    __half *Qhi, *Qlo, *Khi, *Klo, *Vhi, *Vlo, *Ahi, *Alo;
    cudaGetSymbolAddress((void**)&Xhi, g_Xhi);
    cudaGetSymbolAddress((void**)&Xlo, g_Xlo);
    cudaGetSymbolAddress((void**)&Whi, g_Whi);
    cudaGetSymbolAddress((void**)&Wlo, g_Wlo);
    cudaGetSymbolAddress((void**)&Qhi, g_Qhi);
    cudaGetSymbolAddress((void**)&Qlo, g_Qlo);
    cudaGetSymbolAddress((void**)&Khi, g_Khi);
    cudaGetSymbolAddress((void**)&Klo, g_Klo);
    cudaGetSymbolAddress((void**)&Vhi, g_Vhi);
    cudaGetSymbolAddress((void**)&Vlo, g_Vlo);
    cudaGetSymbolAddress((void**)&Ahi, g_Ahi);
    cudaGetSymbolAddress((void**)&Alo, g_Alo);

    cudaFuncSetAttribute(gemm_tc_kernel<true>,
                         cudaFuncAttributeMaxDynamicSharedMemorySize, GEMM_SMEM);
    cudaFuncSetAttribute(gemm_tc_kernel<false>,
                         cudaFuncAttributeMaxDynamicSharedMemorySize, GEMM_SMEM);
    cudaFuncSetAttribute(attn_tc_kernel,
                         cudaFuncAttributeMaxDynamicSharedMemorySize, ATTN_SMEM);

    const int nX4 = MTOT * DIM / 4;
    const int nW4 = DIM * DIM / 4;
    const size_t WSZ = (size_t)DIM * DIM;

    split_kernel<<<nX4 / 256, 256>>>(x,  Xhi, Xlo, nX4);
    split_kernel<<<nW4 / 256, 256>>>(Wq, Whi + 0 * WSZ, Wlo + 0 * WSZ, nW4);
    split_kernel<<<nW4 / 256, 256>>>(Wk, Whi + 1 * WSZ, Wlo + 1 * WSZ, nW4);
    split_kernel<<<nW4 / 256, 256>>>(Wv, Whi + 2 * WSZ, Wlo + 2 * WSZ, nW4);
    split_kernel<<<nW4 / 256, 256>>>(Wo, Whi + 3 * WSZ, Wlo + 3 * WSZ, nW4);

    dim3 ggrid(MTOT / TM, DIM / TN);
    gemm_tc_kernel<true><<<ggrid, 256, GEMM_SMEM>>>(Xhi, Xlo, Whi + 0 * WSZ, Wlo + 0 * WSZ, bq, nullptr, Qhi, Qlo);
    gemm_tc_kernel<true><<<ggrid, 256, GEMM_SMEM>>>(Xhi, Xlo, Whi + 1 * WSZ, Wlo + 1 * WSZ, bk, nullptr, Khi, Klo);
    gemm_tc_kernel<true><<<ggrid, 256, GEMM_SMEM>>>(Xhi, Xlo, Whi + 2 * WSZ, Wlo + 2 * WSZ, bv, nullptr, Vhi, Vlo);

    dim3 agrid(SEQ / 128, HEADS, BATCH);
    attn_tc_kernel<<<agrid, 256, ATTN_SMEM>>>(Qhi, Qlo, Khi, Klo, Vhi, Vlo, Ahi, Alo);

    gemm_tc_kernel<false><<<ggrid, 256, GEMM_SMEM>>>(Ahi, Alo, Whi + 3 * WSZ, Wlo + 3 * WSZ, bo, out, nullptr, nullptr);
}

// round 5
// speedup vs baseline: 4.5407x; 1.2904x over previous
#include <cuda_runtime.h>
#include <cuda_fp16.h>
#include <math.h>
#include <stdint.h>

// Problem constants
#define BATCH 2
#define SEQ   2048
#define DIM   2048
#define HEADS 16
#define DHEAD 128
#define MTOT  (BATCH * SEQ)   // 4096

// ---------------------------------------------------------------------------
// Scratch (allocation-free rule: __device__ globals)
// ---------------------------------------------------------------------------
__device__ __half g_Xhi[MTOT * DIM];
__device__ __half g_Whi[4][DIM * DIM];
__device__ __half g_Wlo[4][DIM * DIM];
__device__ __half g_Qh [MTOT * DIM];
__device__ __half g_Khi[MTOT * DIM];
__device__ __half g_Klo[MTOT * DIM];
__device__ __half g_Vhi[MTOT * DIM];
__device__ __half g_Vlo[MTOT * DIM];
__device__ __half g_Ahi[MTOT * DIM];
__device__ __half g_Alo[MTOT * DIM];

// ---------------------------------------------------------------------------
// PTX helpers (portable sm_80+ : cp.async, ldmatrix, mma.sync)
// ---------------------------------------------------------------------------
__device__ __forceinline__ uint32_t smem_u32(const void* p) {
    uint32_t a;
    asm("{ .reg .u64 t; cvta.to.shared.u64 t, %1; cvt.u32.u64 %0, t; }" : "=r"(a) : "l"(p));
    return a;
}

#define CP_ASYNC_16(dst_u32, src_ptr) \
    asm volatile("cp.async.cg.shared.global [%0], [%1], 16;" \
                 :: "r"(dst_u32), "l"(src_ptr) : "memory")
#define CP_ASYNC_COMMIT() asm volatile("cp.async.commit_group;" ::: "memory")
#define CP_ASYNC_WAIT_1() asm volatile("cp.async.wait_group 1;" ::: "memory")
#define CP_ASYNC_WAIT_2() asm volatile("cp.async.wait_group 2;" ::: "memory")

__device__ __forceinline__ void ldmatrix_x4(uint32_t* r, uint32_t addr) {
    asm volatile("ldmatrix.sync.aligned.m8n8.x4.shared.b16 {%0,%1,%2,%3}, [%4];"
        : "=r"(r[0]), "=r"(r[1]), "=r"(r[2]), "=r"(r[3]) : "r"(addr));
}
__device__ __forceinline__ void ldmatrix_x4_trans(uint32_t* r, uint32_t addr) {
    asm volatile("ldmatrix.sync.aligned.m8n8.x4.trans.shared.b16 {%0,%1,%2,%3}, [%4];"
        : "=r"(r[0]), "=r"(r[1]), "=r"(r[2]), "=r"(r[3]) : "r"(addr));
}

__device__ __forceinline__ void mma16816(float* d, const uint32_t* a, const uint32_t* b) {
    asm volatile(
        "mma.sync.aligned.m16n8k16.row.col.f32.f16.f16.f32 "
        "{%0,%1,%2,%3}, {%4,%5,%6,%7}, {%8,%9}, {%0,%1,%2,%3};"
        : "+f"(d[0]), "+f"(d[1]), "+f"(d[2]), "+f"(d[3])
        : "r"(a[0]), "r"(a[1]), "r"(a[2]), "r"(a[3]), "r"(b[0]), "r"(b[1]));
}

#define SWZ(x) ((x) ^ (((x) >> 3) & 0x70))

// ---------------------------------------------------------------------------
// Splits
// ---------------------------------------------------------------------------
__global__ __launch_bounds__(256) void splitX_hi_kernel(
    const float* __restrict__ in, __half* __restrict__ hi, int n4)
{
    int i = blockIdx.x * 256 + threadIdx.x;
    if (i >= n4) return;
    float4 v = ((const float4*)in)[i];
    ((__half2*)hi)[2 * i]     = __floats2half2_rn(v.x, v.y);
    ((__half2*)hi)[2 * i + 1] = __floats2half2_rn(v.z, v.w);
}

__global__ __launch_bounds__(256) void splitW_kernel(
    const float* __restrict__ w0, const float* __restrict__ w1,
    const float* __restrict__ w2, const float* __restrict__ w3,
    __half* __restrict__ WhiAll, __half* __restrict__ WloAll, int n4)
{
    int i = blockIdx.x * 256 + threadIdx.x;
    if (i >= n4) return;
    int wsel = blockIdx.y;
    const float* in = (wsel == 0) ? w0 : (wsel == 1) ? w1 : (wsel == 2) ? w2 : w3;
    __half* hi = WhiAll + (size_t)wsel * DIM * DIM;
    __half* lo = WloAll + (size_t)wsel * DIM * DIM;
    float4 v = ((const float4*)in)[i];
    __half hx = __float2half_rn(v.x), hy = __float2half_rn(v.y);
    __half hz = __float2half_rn(v.z), hw = __float2half_rn(v.w);
    __half lx = __float2half_rn(v.x - __half2float(hx));
    __half ly = __float2half_rn(v.y - __half2float(hy));
    __half lz = __float2half_rn(v.z - __half2float(hz));
    __half lw = __float2half_rn(v.w - __half2float(hw));
    ((__half2*)hi)[2 * i]     = __halves2half2(hx, hy);
    ((__half2*)hi)[2 * i + 1] = __halves2half2(hz, hw);
    ((__half2*)lo)[2 * i]     = __halves2half2(lx, ly);
    ((__half2*)lo)[2 * i + 1] = __halves2half2(lz, lw);
}

// ---------------------------------------------------------------------------
// Fused QKV GEMM (2-product): Y = Xhi @ (Whi + Wlo)^T + bias
// Grid (32, 48): y/16 selects Q/K/V, y%16 selects n-block.
// Q output: plain fp16. K/V output: hi/lo pair.
// CTA 128x128, 8 warps, K chunk 64, 4-stage cp.async ring (48KB/stage).
// ---------------------------------------------------------------------------
#define TM 128
#define TN 128
#define TKC 64
#define NCHUNK (DIM / TKC)
#define QS_A  0
#define QS_BH 16384
#define QS_BL 32768
#define QSTAGE 49152
#define QNSTAGE 4
#define QKV_SMEM (QNSTAGE * QSTAGE)   // 196608

__device__ __forceinline__ void load_stage_qkv(
    uint32_t sb, const __half* __restrict__ Xh,
    const __half* __restrict__ Bhi, const __half* __restrict__ Blo,
    int m0, int n0, int k0, int tid)
{
    #pragma unroll
    for (int it = 0; it < 4; it++) {
        int t = tid + it * 256;
        int row = t >> 3;
        int kk = (t & 7) * 8;
        uint32_t soff = SWZ((uint32_t)(row * 128 + kk * 2));
        CP_ASYNC_16(sb + QS_A  + soff, Xh  + (size_t)(m0 + row) * DIM + k0 + kk);
        CP_ASYNC_16(sb + QS_BH + soff, Bhi + (size_t)(n0 + row) * DIM + k0 + kk);
        CP_ASYNC_16(sb + QS_BL + soff, Blo + (size_t)(n0 + row) * DIM + k0 + kk);
    }
}

__global__ __launch_bounds__(256, 1) void gemm_qkv_kernel(
    const __half* __restrict__ Xh,
    const __half* __restrict__ WhiAll, const __half* __restrict__ WloAll,
    const float* __restrict__ bq, const float* __restrict__ bk,
    const float* __restrict__ bv,
    __half* __restrict__ Qh,
    __half* __restrict__ Khi, __half* __restrict__ Klo,
    __half* __restrict__ Vhi, __half* __restrict__ Vlo)
{
    extern __shared__ char smem[];
    const uint32_t smem_base = smem_u32(smem);
    const int tid = threadIdx.x;
    const int wid = tid >> 5;
    const int lane = tid & 31;
    const int warp_m = wid & 3;
    const int warp_n = wid >> 2;
    const int m0 = blockIdx.x * TM;
    const int out = blockIdx.y >> 4;            // 0=Q 1=K 2=V
    const int n0 = (blockIdx.y & 15) * TN;

    const __half* Bhi = WhiAll + (size_t)out * DIM * DIM;
    const __half* Blo = WloAll + (size_t)out * DIM * DIM;
    const float* bias = (out == 0) ? bq : (out == 1) ? bk : bv;

    float acc[2][8][4];
    #pragma unroll
    for (int mi = 0; mi < 2; mi++)
        #pragma unroll
        for (int ni = 0; ni < 8; ni++)
            #pragma unroll
            for (int r = 0; r < 4; r++) acc[mi][ni][r] = 0.f;

    load_stage_qkv(smem_base,              Xh, Bhi, Blo, m0, n0, 0 * TKC, tid);
    CP_ASYNC_COMMIT();
    load_stage_qkv(smem_base + QSTAGE,     Xh, Bhi, Blo, m0, n0, 1 * TKC, tid);
    CP_ASYNC_COMMIT();
    load_stage_qkv(smem_base + 2 * QSTAGE, Xh, Bhi, Blo, m0, n0, 2 * TKC, tid);
    CP_ASYNC_COMMIT();

    const int a_row = (lane & 15);
    const int a_kb  = (lane >> 4) << 4;
    const int b_row = ((lane >> 4) << 3) + (lane & 7);
    const int b_kb  = ((lane >> 3) & 1) << 4;

    int slot = 0;
    for (int c = 0; c < NCHUNK; c++) {
        CP_ASYNC_WAIT_2();
        __syncthreads();

        if (c + 3 < NCHUNK) {
            int s2 = (slot + 3) & 3;
            load_stage_qkv(smem_base + s2 * QSTAGE, Xh, Bhi, Blo,
                           m0, n0, (c + 3) * TKC, tid);
        }
        CP_ASYNC_COMMIT();

        const uint32_t sb = smem_base + slot * QSTAGE;
        #pragma unroll
        for (int ks = 0; ks < 4; ks++) {
            const int kbyte = ks * 32;
            uint32_t a_h[2][4], b_h[4][4], b_l[4][4];
            #pragma unroll
            for (int mi = 0; mi < 2; mi++) {
                uint32_t off = SWZ((uint32_t)((warp_m * 32 + mi * 16 + a_row) * 128 + kbyte + a_kb));
                ldmatrix_x4(a_h[mi], sb + QS_A + off);
            }
            #pragma unroll
            for (int pi = 0; pi < 4; pi++) {
                uint32_t off = SWZ((uint32_t)((warp_n * 64 + pi * 16 + b_row) * 128 + kbyte + b_kb));
                ldmatrix_x4(b_h[pi], sb + QS_BH + off);
                ldmatrix_x4(b_l[pi], sb + QS_BL + off);
            }
            #pragma unroll
            for (int mi = 0; mi < 2; mi++)
                #pragma unroll
                for (int ni = 0; ni < 8; ni++) {
                    mma16816(acc[mi][ni], a_h[mi], &b_h[ni >> 1][(ni & 1) * 2]);
                    mma16816(acc[mi][ni], a_h[mi], &b_l[ni >> 1][(ni & 1) * 2]);
                }
        }
        slot = (slot + 1) & 3;
    }

    const int gm0 = m0 + warp_m * 32;
    const int gn0 = n0 + warp_n * 64;
    #pragma unroll
    for (int mi = 0; mi < 2; mi++) {
        int row = gm0 + mi * 16 + (lane >> 2);
        #pragma unroll
        for (int ni = 0; ni < 8; ni++) {
            int col = gn0 + ni * 8 + 2 * (lane & 3);
            float2 b2 = *(const float2*)&bias[col];
            float y0 = acc[mi][ni][0] + b2.x, y1 = acc[mi][ni][1] + b2.y;
            float y2 = acc[mi][ni][2] + b2.x, y3 = acc[mi][ni][3] + b2.y;
            if (out == 0) {
                *(__half2*)&Qh[(size_t)row * DIM + col]       = __floats2half2_rn(y0, y1);
                *(__half2*)&Qh[(size_t)(row + 8) * DIM + col] = __floats2half2_rn(y2, y3);
            } else {
                __half* Yhi = (out == 1) ? Khi : Vhi;
                __half* Ylo = (out == 1) ? Klo : Vlo;
                __half h0 = __float2half_rn(y0), h1 = __float2half_rn(y1);
                __half h2 = __float2half_rn(y2), h3 = __float2half_rn(y3);
                __half l0 = __float2half_rn(y0 - __half2float(h0));
                __half l1 = __float2half_rn(y1 - __half2float(h1));
                __half l2 = __float2half_rn(y2 - __half2float(h2));
                __half l3 = __float2half_rn(y3 - __half2float(h3));
                *(__half2*)&Yhi[(size_t)row * DIM + col]       = __halves2half2(h0, h1);
                *(__half2*)&Yhi[(size_t)(row + 8) * DIM + col] = __halves2half2(h2, h3);
                *(__half2*)&Ylo[(size_t)row * DIM + col]       = __halves2half2(l0, l1);
                *(__half2*)&Ylo[(size_t)(row + 8) * DIM + col] = __halves2half2(l2, l3);
            }
        }
    }
}

// ---------------------------------------------------------------------------
// O-projection GEMM (3-product): out = (Ahi+Alo) @ (Whi+Wlo)^T + bias, fp32
// ---------------------------------------------------------------------------
#define SM_A_HI 0
#define SM_A_LO 16384
#define SM_B_HI 32768
#define SM_B_LO 49152
#define STAGE_BYTES 65536
#define NSTAGE 3
#define GEMM_SMEM (NSTAGE * STAGE_BYTES)

__device__ __forceinline__ void load_stage_o(
    uint32_t sb, const __half* __restrict__ Ahi, const __half* __restrict__ Alo,
    const __half* __restrict__ Bhi, const __half* __restrict__ Blo,
    int m0, int n0, int k0, int tid)
{
    #pragma unroll
    for (int it = 0; it < 4; it++) {
        int t = tid + it * 256;
        int row = t >> 3;
        int kk = (t & 7) * 8;
        uint32_t soff = SWZ((uint32_t)(row * 128 + kk * 2));
        CP_ASYNC_16(sb + SM_A_HI + soff, Ahi + (size_t)(m0 + row) * DIM + k0 + kk);
        CP_ASYNC_16(sb + SM_A_LO + soff, Alo + (size_t)(m0 + row) * DIM + k0 + kk);
        CP_ASYNC_16(sb + SM_B_HI + soff, Bhi + (size_t)(n0 + row) * DIM + k0 + kk);
        CP_ASYNC_16(sb + SM_B_LO + soff, Blo + (size_t)(n0 + row) * DIM + k0 + kk);
    }
}

__global__ __launch_bounds__(256, 1) void gemm_o_kernel(
    const __half* __restrict__ Ahi, const __half* __restrict__ Alo,
    const __half* __restrict__ Bhi, const __half* __restrict__ Blo,
    const float* __restrict__ bias, float* __restrict__ Yf)
{
    extern __shared__ char smem[];
    const uint32_t smem_base = smem_u32(smem);
    const int tid = threadIdx.x;
    const int wid = tid >> 5;
    const int lane = tid & 31;
    const int warp_m = wid & 3;
    const int warp_n = wid >> 2;
    const int m0 = blockIdx.x * TM;
    const int n0 = blockIdx.y * TN;

    float acc[2][8][4];
    #pragma unroll
    for (int mi = 0; mi < 2; mi++)
        #pragma unroll
        for (int ni = 0; ni < 8; ni++)
            #pragma unroll
            for (int r = 0; r < 4; r++) acc[mi][ni][r] = 0.f;

    load_stage_o(smem_base, Ahi, Alo, Bhi, Blo, m0, n0, 0, tid);
    CP_ASYNC_COMMIT();
    load_stage_o(smem_base + STAGE_BYTES, Ahi, Alo, Bhi, Blo, m0, n0, TKC, tid);
    CP_ASYNC_COMMIT();

    const int a_row = (lane & 15);
    const int a_kb  = (lane >> 4) << 4;
    const int b_row = ((lane >> 4) << 3) + (lane & 7);
    const int b_kb  = ((lane >> 3) & 1) << 4;

    int slot = 0;
    for (int c = 0; c < NCHUNK; c++) {
        CP_ASYNC_WAIT_1();
        __syncthreads();

        if (c + 2 < NCHUNK) {
            int s2 = slot + 2; if (s2 >= NSTAGE) s2 -= NSTAGE;
            load_stage_o(smem_base + s2 * STAGE_BYTES, Ahi, Alo, Bhi, Blo,
                         m0, n0, (c + 2) * TKC, tid);
        }
        CP_ASYNC_COMMIT();

        const uint32_t sb = smem_base + slot * STAGE_BYTES;
        #pragma unroll
        for (int ks = 0; ks < 4; ks++) {
            const int kbyte = ks * 32;
            uint32_t a_hi[2][4], a_lo[2][4], b_hi[4][4], b_lo[4][4];
            #pragma unroll
            for (int mi = 0; mi < 2; mi++) {
                uint32_t off = SWZ((uint32_t)((warp_m * 32 + mi * 16 + a_row) * 128 + kbyte + a_kb));
                ldmatrix_x4(a_hi[mi], sb + SM_A_HI + off);
                ldmatrix_x4(a_lo[mi], sb + SM_A_LO + off);
            }
            #pragma unroll
            for (int pi = 0; pi < 4; pi++) {
                uint32_t off = SWZ((uint32_t)((warp_n * 64 + pi * 16 + b_row) * 128 + kbyte + b_kb));
                ldmatrix_x4(b_hi[pi], sb + SM_B_HI + off);
                ldmatrix_x4(b_lo[pi], sb + SM_B_LO + off);
            }
            #pragma unroll
            for (int mi = 0; mi < 2; mi++)
                #pragma unroll
                for (int ni = 0; ni < 8; ni++) {
                    const uint32_t* bh = &b_hi[ni >> 1][(ni & 1) * 2];
                    const uint32_t* bl = &b_lo[ni >> 1][(ni & 1) * 2];
                    mma16816(acc[mi][ni], a_hi[mi], bh);
                    mma16816(acc[mi][ni], a_hi[mi], bl);
                    mma16816(acc[mi][ni], a_lo[mi], bh);
                }
        }
        slot++; if (slot >= NSTAGE) slot = 0;
    }

    const int gm0 = m0 + warp_m * 32;
    const int gn0 = n0 + warp_n * 64;
    #pragma unroll
    for (int mi = 0; mi < 2; mi++) {
        int row = gm0 + mi * 16 + (lane >> 2);
        #pragma unroll
        for (int ni = 0; ni < 8; ni++) {
            int col = gn0 + ni * 8 + 2 * (lane & 3);
            float2 b2 = *(const float2*)&bias[col];
            *(float2*)&Yf[(size_t)row * DIM + col] =
                make_float2(acc[mi][ni][0] + b2.x, acc[mi][ni][1] + b2.y);
            *(float2*)&Yf[(size_t)(row + 8) * DIM + col] =
                make_float2(acc[mi][ni][2] + b2.x, acc[mi][ni][3] + b2.y);
        }
    }
}

// ---------------------------------------------------------------------------
// Tensor-core causal flash attention.
// Q: plain fp16 (2 products for QK^T). K,V: hi/lo (3 products for PV).
// Smem: Q 32KB | K 2st x 32KB | V 2st x 32KB = 160KB.
// ---------------------------------------------------------------------------
#define SM_Qb 0
#define SM_Kb 32768
#define SM_Vb 98304
#define ATTN_SMEM 163840
#define KSC 0.12751741219860918f   /* (1/sqrt(128)) * log2(e) */

__device__ __forceinline__ void attn_load_kv(
    uint32_t sb, const __half* __restrict__ Khi, const __half* __restrict__ Klo,
    const __half* __restrict__ Vhi, const __half* __restrict__ Vlo,
    size_t gbase, int k0, int stage, int tid)
{
    #pragma unroll
    for (int i = 0; i < 16; i++) {
        int t = tid + i * 256;
        int kv  = t >> 11;
        int hil = (t >> 10) & 1;
        int row = (t >> 4) & 63;
        int ch  = t & 15;
        int pl  = ch >> 3;
        const __half* src;
        if (kv == 0) src = (hil ? Klo : Khi);
        else         src = (hil ? Vlo : Vhi);
        src += gbase + (size_t)(k0 + row) * DIM + ch * 8;
        uint32_t dst = sb + (kv == 0 ? SM_Kb : SM_Vb) + stage * 32768 + hil * 16384
                     + pl * 8192 + SWZ((uint32_t)(row * 128 + (ch & 7) * 16));
        CP_ASYNC_16(dst, src);
    }
}

__global__ __launch_bounds__(256, 1) void attn_tc_kernel(
    const __half* __restrict__ Qh,
    const __half* __restrict__ Khi, const __half* __restrict__ Klo,
    const __half* __restrict__ Vhi, const __half* __restrict__ Vlo,
    __half* __restrict__ Ahi, __half* __restrict__ Alo)
{
    extern __shared__ char smem[];
    const uint32_t sb = smem_u32(smem);
    const int tid = threadIdx.x;
    const int w = tid >> 5;
    const int lane = tid & 31;
    const int qt = gridDim.x - 1 - blockIdx.x;   // big tiles first
    const int h = blockIdx.y;
    const int b = blockIdx.z;
    const int q0 = qt * 128;
    const size_t gbase = (size_t)b * SEQ * DIM + (size_t)h * DHEAD;

    // Load Q tile (hi only, 32KB)
    #pragma unroll
    for (int i = 0; i < 8; i++) {
        int t = tid + i * 256;
        int row = (t >> 4) & 127;
        int ch  = t & 15;
        int pl  = ch >> 3;
        const __half* src = Qh + gbase + (size_t)(q0 + row) * DIM + ch * 8;
        uint32_t dst = sb + SM_Qb + pl * 16384
                     + SWZ((uint32_t)(row * 128 + (ch & 7) * 16));
        CP_ASYNC_16(dst, src);
    }
    attn_load_kv(sb, Khi, Klo, Vhi, Vlo, gbase, 0, 0, tid);
    CP_ASYNC_COMMIT();

    float m0v = -1e30f, m1v = -1e30f, l0v = 0.f, l1v = 0.f;
    float acc_o[16][4];
    #pragma unroll
    for (int n = 0; n < 16; n++)
        #pragma unroll
        for (int r = 0; r < 4; r++) acc_o[n][r] = 0.f;

    const int a_row = lane & 15;
    const int a_kb  = (lane >> 4) << 4;
    const int b_row = ((lane >> 4) << 3) + (lane & 7);
    const int b_kb  = ((lane >> 3) & 1) << 4;
    const int v_row = (lane & 7) + ((lane >> 3) & 1) * 8;
    const int v_cb  = ((lane >> 4) & 1) << 4;

    const int qwmin = q0 + w * 16;
    const int nt = 2 * qt + 2;

    for (int kt = 0; kt < nt; kt++) {
        __syncthreads();
        if (kt + 1 < nt)
            attn_load_kv(sb, Khi, Klo, Vhi, Vlo, gbase, (kt + 1) * 64, (kt + 1) & 1, tid);
        CP_ASYNC_COMMIT();
        CP_ASYNC_WAIT_1();
        __syncthreads();

        const int k0 = kt * 64;
        const int st = kt & 1;
        if (k0 > qwmin + 15) continue;

        // ---- S = Q K^T (Qh*Khi + Qh*Klo) ----
        float s[8][4];
        #pragma unroll
        for (int ni = 0; ni < 8; ni++)
            #pragma unroll
            for (int r = 0; r < 4; r++) s[ni][r] = 0.f;

        #pragma unroll
        for (int ks = 0; ks < 8; ks++) {
            const int kbyte = (ks & 3) * 32;
            const int pl = ks >> 2;
            uint32_t aH[4];
            uint32_t aoff = SM_Qb + pl * 16384
                          + SWZ((uint32_t)((w * 16 + a_row) * 128 + kbyte + a_kb));
            ldmatrix_x4(aH, sb + aoff);
            #pragma unroll
            for (int pi = 0; pi < 4; pi++) {
                uint32_t bH[4], bL[4];
                uint32_t boff = SM_Kb + st * 32768 + pl * 8192
                              + SWZ((uint32_t)((pi * 16 + b_row) * 128 + kbyte + b_kb));
                ldmatrix_x4(bH, sb + boff);
                ldmatrix_x4(bL, sb + boff + 16384);
                mma16816(s[2 * pi],     aH, &bH[0]);
                mma16816(s[2 * pi],     aH, &bL[0]);
                mma16816(s[2 * pi + 1], aH, &bH[2]);
                mma16816(s[2 * pi + 1], aH, &bL[2]);
            }
        }

        // ---- causal mask ----
        const int qr0 = qwmin + (lane >> 2);
        const int qr1 = qr0 + 8;
        if (k0 + 63 > qwmin) {
            const int kc = k0 + 2 * (lane & 3);
            #pragma unroll
            for (int ni = 0; ni < 8; ni++) {
                int kb2 = kc + ni * 8;
                if (kb2     > qr0) s[ni][0] = -1e30f;
                if (kb2 + 1 > qr0) s[ni][1] = -1e30f;
                if (kb2     > qr1) s[ni][2] = -1e30f;
                if (kb2 + 1 > qr1) s[ni][3] = -1e30f;
            }
        }

        // ---- online softmax ----
        float mx0 = -1e30f, mx1 = -1e30f;
        #pragma unroll
        for (int ni = 0; ni < 8; ni++) {
            mx0 = fmaxf(mx0, fmaxf(s[ni][0], s[ni][1]));
            mx1 = fmaxf(mx1, fmaxf(s[ni][2], s[ni][3]));
        }
        mx0 = fmaxf(mx0, __shfl_xor_sync(0xffffffffu, mx0, 1));
        mx0 = fmaxf(mx0, __shfl_xor_sync(0xffffffffu, mx0, 2));
        mx1 = fmaxf(mx1, __shfl_xor_sync(0xffffffffu, mx1, 1));
        mx1 = fmaxf(mx1, __shfl_xor_sync(0xffffffffu, mx1, 2));
        float mn0 = fmaxf(m0v, mx0), mn1 = fmaxf(m1v, mx1);
        float corr0 = exp2f((m0v - mn0) * KSC);
        float corr1 = exp2f((m1v - mn1) * KSC);
        m0v = mn0; m1v = mn1;

        float rs0 = 0.f, rs1 = 0.f;
        #pragma unroll
        for (int ni = 0; ni < 8; ni++) {
            s[ni][0] = exp2f((s[ni][0] - mn0) * KSC);
            s[ni][1] = exp2f((s[ni][1] - mn0) * KSC);
            s[ni][2] = exp2f((s[ni][2] - mn1) * KSC);
            s[ni][3] = exp2f((s[ni][3] - mn1) * KSC);
            rs0 += s[ni][0] + s[ni][1];
            rs1 += s[ni][2] + s[ni][3];
        }
        rs0 += __shfl_xor_sync(0xffffffffu, rs0, 1);
        rs0 += __shfl_xor_sync(0xffffffffu, rs0, 2);
        rs1 += __shfl_xor_sync(0xffffffffu, rs1, 1);
        rs1 += __shfl_xor_sync(0xffffffffu, rs1, 2);
        l0v = l0v * corr0 + rs0;
        l1v = l1v * corr1 + rs1;

        #pragma unroll
        for (int n = 0; n < 16; n++) {
            acc_o[n][0] *= corr0; acc_o[n][1] *= corr0;
            acc_o[n][2] *= corr1; acc_o[n][3] *= corr1;
        }

        // ---- O += P V (Phi*Vhi + Phi*Vlo + Plo*Vhi) ----
        #pragma unroll
        for (int vks = 0; vks < 4; vks++) {
            uint32_t pH[4], pL[4];
            #pragma unroll
            for (int half16 = 0; half16 < 2; half16++) {
                const float* sp = s[2 * vks + half16];
                __half2 h01 = __floats2half2_rn(sp[0], sp[1]);
                __half2 h23 = __floats2half2_rn(sp[2], sp[3]);
                float2 f01 = __half22float2(h01);
                float2 f23 = __half22float2(h23);
                __half2 l01 = __floats2half2_rn(sp[0] - f01.x, sp[1] - f01.y);
                __half2 l23 = __floats2half2_rn(sp[2] - f23.x, sp[3] - f23.y);
                pH[2 * half16]     = *(uint32_t*)&h01;
                pH[2 * half16 + 1] = *(uint32_t*)&h23;
                pL[2 * half16]     = *(uint32_t*)&l01;
                pL[2 * half16 + 1] = *(uint32_t*)&l23;
            }
            const int vr = vks * 16 + v_row;
            #pragma unroll
            for (int nb = 0; nb < 8; nb++) {
                uint32_t vH[4], vL[4];
                uint32_t voff = SM_Vb + st * 32768 + (nb >> 2) * 8192
                              + SWZ((uint32_t)(vr * 128 + (nb & 3) * 32 + v_cb));
                ldmatrix_x4_trans(vH, sb + voff);
                ldmatrix_x4_trans(vL, sb + voff + 16384);
                mma16816(acc_o[2 * nb],     pH, &vH[0]);
                mma16816(acc_o[2 * nb],     pH, &vL[0]);
                mma16816(acc_o[2 * nb],     pL, &vH[0]);
                mma16816(acc_o[2 * nb + 1], pH, &vH[2]);
                mma16816(acc_o[2 * nb + 1], pH, &vL[2]);
                mma16816(acc_o[2 * nb + 1], pL, &vH[2]);
            }
        }
    }

    // ---- normalize, split hi/lo, store ----
    const float inv0 = 1.f / l0v;
    const float inv1 = 1.f / l1v;
    const size_t r0o = gbase + (size_t)(q0 + w * 16 + (lane >> 2)) * DIM;
    const size_t r1o = r0o + 8 * DIM;
    #pragma unroll
    for (int n = 0; n < 16; n++) {
        int col = n * 8 + 2 * (lane & 3);
        float y0 = acc_o[n][0] * inv0, y1 = acc_o[n][1] * inv0;
        float y2 = acc_o[n][2] * inv1, y3 = acc_o[n][3] * inv1;
        __half h0 = __float2half_rn(y0), h1 = __float2half_rn(y1);
        __half h2 = __float2half_rn(y2), h3 = __float2half_rn(y3);
        __half l0h = __float2half_rn(y0 - __half2float(h0));
        __half l1h = __float2half_rn(y1 - __half2float(h1));
        __half l2h = __float2half_rn(y2 - __half2float(h2));
        __half l3h = __float2half_rn(y3 - __half2float(h3));
        *(__half2*)&Ahi[r0o + col] = __halves2half2(h0, h1);
        *(__half2*)&Ahi[r1o + col] = __halves2half2(h2, h3);
        *(__half2*)&Alo[r0o + col] = __halves2half2(l0h, l1h);
        *(__half2*)&Alo[r1o + col] = __halves2half2(l2h, l3h);
    }
}

// ---------------------------------------------------------------------------
extern "C" void kernel_launch(void* const* d_in, const int* in_sizes, int n_in,
                              void* d_out, int out_size)
{
    const float* x  = (const float*)d_in[0];
    const float* Wq = (const float*)d_in[1];
    const float* bq = (const float*)d_in[2];
    const float* Wk = (const float*)d_in[3];
    const float* bk = (const float*)d_in[4];
    const float* Wv = (const float*)d_in[5];
    const float* bv = (const float*)d_in[6];
    const float* Wo = (const float*)d_in[7];
    const float* bo = (const float*)d_in[8];
    float* out = (float*)d_out;

    __half *Xhi, *Whi, *Wlo, *Qh, *Khi, *Klo, *Vhi, *Vlo, *Ahi, *Alo;
    cudaGetSymbolAddress((void**)&Xhi, g_Xhi);
    cudaGetSymbolAddress((void**)&Whi, g_Whi);
    cudaGetSymbolAddress((void**)&Wlo, g_Wlo);
    cudaGetSymbolAddress((void**)&Qh,  g_Qh);
    cudaGetSymbolAddress((void**)&Khi, g_Khi);
    cudaGetSymbolAddress((void**)&Klo, g_Klo);
    cudaGetSymbolAddress((void**)&Vhi, g_Vhi);
    cudaGetSymbolAddress((void**)&Vlo, g_Vlo);
    cudaGetSymbolAddress((void**)&Ahi, g_Ahi);
    cudaGetSymbolAddress((void**)&Alo, g_Alo);

    cudaFuncSetAttribute(gemm_qkv_kernel,
                         cudaFuncAttributeMaxDynamicSharedMemorySize, QKV_SMEM);
    cudaFuncSetAttribute(gemm_o_kernel,
                         cudaFuncAttributeMaxDynamicSharedMemorySize, GEMM_SMEM);
    cudaFuncSetAttribute(attn_tc_kernel,
                         cudaFuncAttributeMaxDynamicSharedMemorySize, ATTN_SMEM);

    const int nX4 = MTOT * DIM / 4;
    const int nW4 = DIM * DIM / 4;
    const size_t WSZ = (size_t)DIM * DIM;

    splitX_hi_kernel<<<nX4 / 256, 256>>>(x, Xhi, nX4);
    splitW_kernel<<<dim3(nW4 / 256, 4), 256>>>(Wq, Wk, Wv, Wo, Whi, Wlo, nW4);

    // Fused QKV projection
    gemm_qkv_kernel<<<dim3(MTOT / TM, 48), 256, QKV_SMEM>>>(
        Xhi, Whi, Wlo, bq, bk, bv, Qh, Khi, Klo, Vhi, Vlo);

    // Attention
    dim3 agrid(SEQ / 128, HEADS, BATCH);
    attn_tc_kernel<<<agrid, 256, ATTN_SMEM>>>(Qh, Khi, Klo, Vhi, Vlo, Ahi, Alo);

    // Output projection (full 3-product accuracy)
    gemm_o_kernel<<<dim3(MTOT / TM, DIM / TN), 256, GEMM_SMEM>>>(
        Ahi, Alo, Whi + 3 * WSZ, Wlo + 3 * WSZ, bo, out);
}

// round 6
// speedup vs baseline: 4.7024x; 1.0356x over previous
#include <cuda_runtime.h>
#include <cuda_fp16.h>
#include <math.h>
#include <stdint.h>

// Problem constants
#define BATCH 2
#define SEQ   2048
#define DIM   2048
#define HEADS 16
#define DHEAD 128
#define MTOT  (BATCH * SEQ)   // 4096

// ---------------------------------------------------------------------------
// Scratch (allocation-free rule: __device__ globals)
// ---------------------------------------------------------------------------
__device__ __half g_Xhi[MTOT * DIM];
__device__ __half g_Whi[4][DIM * DIM];
__device__ __half g_Wlo[4][DIM * DIM];
__device__ __half g_Qh [MTOT * DIM];
__device__ __half g_Khi[MTOT * DIM];
__device__ __half g_Klo[MTOT * DIM];
__device__ __half g_Vhi[MTOT * DIM];
__device__ __half g_Vlo[MTOT * DIM];
__device__ __half g_Ahi[MTOT * DIM];
__device__ __half g_Alo[MTOT * DIM];

// ---------------------------------------------------------------------------
// PTX helpers
// ---------------------------------------------------------------------------
__device__ __forceinline__ uint32_t smem_u32(const void* p) {
    uint32_t a;
    asm("{ .reg .u64 t; cvta.to.shared.u64 t, %1; cvt.u32.u64 %0, t; }" : "=r"(a) : "l"(p));
    return a;
}

#define CP_ASYNC_16(dst_u32, src_ptr) \
    asm volatile("cp.async.cg.shared.global [%0], [%1], 16;" \
                 :: "r"(dst_u32), "l"(src_ptr) : "memory")
#define CP_ASYNC_COMMIT() asm volatile("cp.async.commit_group;" ::: "memory")
#define CP_ASYNC_WAIT_1() asm volatile("cp.async.wait_group 1;" ::: "memory")

__device__ __forceinline__ void ldmatrix_x4(uint32_t* r, uint32_t addr) {
    asm volatile("ldmatrix.sync.aligned.m8n8.x4.shared.b16 {%0,%1,%2,%3}, [%4];"
        : "=r"(r[0]), "=r"(r[1]), "=r"(r[2]), "=r"(r[3]) : "r"(addr));
}
__device__ __forceinline__ void ldmatrix_x4_trans(uint32_t* r, uint32_t addr) {
    asm volatile("ldmatrix.sync.aligned.m8n8.x4.trans.shared.b16 {%0,%1,%2,%3}, [%4];"
        : "=r"(r[0]), "=r"(r[1]), "=r"(r[2]), "=r"(r[3]) : "r"(addr));
}

__device__ __forceinline__ void mma16816(float* d, const uint32_t* a, const uint32_t* b) {
    asm volatile(
        "mma.sync.aligned.m16n8k16.row.col.f32.f16.f16.f32 "
        "{%0,%1,%2,%3}, {%4,%5,%6,%7}, {%8,%9}, {%0,%1,%2,%3};"
        : "+f"(d[0]), "+f"(d[1]), "+f"(d[2]), "+f"(d[3])
        : "r"(a[0]), "r"(a[1]), "r"(a[2]), "r"(a[3]), "r"(b[0]), "r"(b[1]));
}

#define SWZ(x) ((x) ^ (((x) >> 3) & 0x70))

// ---------------------------------------------------------------------------
// Splits
// ---------------------------------------------------------------------------
__global__ __launch_bounds__(256) void splitX_hi_kernel(
    const float* __restrict__ in, __half* __restrict__ hi, int n4)
{
    int i = blockIdx.x * 256 + threadIdx.x;
    if (i >= n4) return;
    float4 v = ((const float4*)in)[i];
    ((__half2*)hi)[2 * i]     = __floats2half2_rn(v.x, v.y);
    ((__half2*)hi)[2 * i + 1] = __floats2half2_rn(v.z, v.w);
}

__global__ __launch_bounds__(256) void splitW_kernel(
    const float* __restrict__ w0, const float* __restrict__ w1,
    const float* __restrict__ w2, const float* __restrict__ w3,
    __half* __restrict__ WhiAll, __half* __restrict__ WloAll, int n4)
{
    int i = blockIdx.x * 256 + threadIdx.x;
    if (i >= n4) return;
    int wsel = blockIdx.y;
    const float* in = (wsel == 0) ? w0 : (wsel == 1) ? w1 : (wsel == 2) ? w2 : w3;
    __half* hi = WhiAll + (size_t)wsel * DIM * DIM;
    __half* lo = WloAll + (size_t)wsel * DIM * DIM;
    float4 v = ((const float4*)in)[i];
    __half hx = __float2half_rn(v.x), hy = __float2half_rn(v.y);
    __half hz = __float2half_rn(v.z), hw = __float2half_rn(v.w);
    __half lx = __float2half_rn(v.x - __half2float(hx));
    __half ly = __float2half_rn(v.y - __half2float(hy));
    __half lz = __float2half_rn(v.z - __half2float(hz));
    __half lw = __float2half_rn(v.w - __half2float(hw));
    ((__half2*)hi)[2 * i]     = __halves2half2(hx, hy);
    ((__half2*)hi)[2 * i + 1] = __halves2half2(hz, hw);
    ((__half2*)lo)[2 * i]     = __halves2half2(lx, ly);
    ((__half2*)lo)[2 * i + 1] = __halves2half2(lz, lw);
}

// ---------------------------------------------------------------------------
// Fused QKV GEMM (2-product): Y = Xhi @ (Whi + Wlo)^T + bias
// CTA tile 256x128, 8 warps (4m x 2n), warp tile 64x64, K chunk 64, 3 stages.
// Grid (16, 48): y/16 selects Q/K/V output, y%16 selects n-block.
// ---------------------------------------------------------------------------
#define TKC 64
#define NCHUNK (DIM / TKC)
#define QTM 256
#define QS_A  0
#define QS_BH 32768
#define QS_BL 49152
#define QSTAGE 65536
#define QKV_SMEM (3 * QSTAGE)   // 196608

__device__ __forceinline__ void load_stage_qkv(
    uint32_t sb, const __half* __restrict__ Xh,
    const __half* __restrict__ Bhi, const __half* __restrict__ Blo,
    int m0, int n0, int k0, int tid)
{
    #pragma unroll
    for (int it = 0; it < 8; it++) {
        int t = tid + it * 256;            // 0..2047
        int row = t >> 3;                  // 0..255
        int kk = (t & 7) * 8;
        uint32_t soff = SWZ((uint32_t)(row * 128 + kk * 2));
        CP_ASYNC_16(sb + QS_A + soff, Xh + (size_t)(m0 + row) * DIM + k0 + kk);
    }
    #pragma unroll
    for (int it = 0; it < 8; it++) {
        int t = tid + it * 256;            // 0..2047
        int hil = t >> 10;                 // 0: hi, 1: lo
        int row = (t >> 3) & 127;
        int kk = (t & 7) * 8;
        uint32_t soff = SWZ((uint32_t)(row * 128 + kk * 2));
        const __half* src = (hil ? Blo : Bhi) + (size_t)(n0 + row) * DIM + k0 + kk;
        CP_ASYNC_16(sb + (hil ? QS_BL : QS_BH) + soff, src);
    }
}

__global__ __launch_bounds__(256, 1) void gemm_qkv_kernel(
    const __half* __restrict__ Xh,
    const __half* __restrict__ WhiAll, const __half* __restrict__ WloAll,
    const float* __restrict__ bq, const float* __restrict__ bk,
    const float* __restrict__ bv,
    __half* __restrict__ Qh,
    __half* __restrict__ Khi, __half* __restrict__ Klo,
    __half* __restrict__ Vhi, __half* __restrict__ Vlo)
{
    extern __shared__ char smem[];
    const uint32_t smem_base = smem_u32(smem);
    const int tid = threadIdx.x;
    const int wid = tid >> 5;
    const int lane = tid & 31;
    const int warp_m = wid & 3;        // 4 -> 64 rows each
    const int warp_n = wid >> 2;       // 2 -> 64 cols each
    const int m0 = blockIdx.x * QTM;
    const int out = blockIdx.y >> 4;   // 0=Q 1=K 2=V
    const int n0 = (blockIdx.y & 15) * 128;

    const __half* Bhi = WhiAll + (size_t)out * DIM * DIM;
    const __half* Blo = WloAll + (size_t)out * DIM * DIM;
    const float* bias = (out == 0) ? bq : (out == 1) ? bk : bv;

    float acc[4][8][4];
    #pragma unroll
    for (int mi = 0; mi < 4; mi++)
        #pragma unroll
        for (int ni = 0; ni < 8; ni++)
            #pragma unroll
            for (int r = 0; r < 4; r++) acc[mi][ni][r] = 0.f;

    load_stage_qkv(smem_base,          Xh, Bhi, Blo, m0, n0, 0 * TKC, tid);
    CP_ASYNC_COMMIT();
    load_stage_qkv(smem_base + QSTAGE, Xh, Bhi, Blo, m0, n0, 1 * TKC, tid);
    CP_ASYNC_COMMIT();

    const int a_row = (lane & 15);
    const int a_kb  = (lane >> 4) << 4;
    const int b_row = ((lane >> 4) << 3) + (lane & 7);
    const int b_kb  = ((lane >> 3) & 1) << 4;

    int slot = 0;
    for (int c = 0; c < NCHUNK; c++) {
        CP_ASYNC_WAIT_1();
        __syncthreads();

        if (c + 2 < NCHUNK) {
            int s2 = slot + 2; if (s2 >= 3) s2 -= 3;
            load_stage_qkv(smem_base + s2 * QSTAGE, Xh, Bhi, Blo,
                           m0, n0, (c + 2) * TKC, tid);
        }
        CP_ASYNC_COMMIT();

        const uint32_t sb = smem_base + slot * QSTAGE;
        #pragma unroll
        for (int ks = 0; ks < 4; ks++) {
            const int kbyte = ks * 32;
            uint32_t b_h[4][4], b_l[4][4];
            #pragma unroll
            for (int pi = 0; pi < 4; pi++) {
                uint32_t off = SWZ((uint32_t)((warp_n * 64 + pi * 16 + b_row) * 128 + kbyte + b_kb));
                ldmatrix_x4(b_h[pi], sb + QS_BH + off);
                ldmatrix_x4(b_l[pi], sb + QS_BL + off);
            }
            #pragma unroll
            for (int mi = 0; mi < 4; mi++) {
                uint32_t a_h[4];
                uint32_t aoff = SWZ((uint32_t)((warp_m * 64 + mi * 16 + a_row) * 128 + kbyte + a_kb));
                ldmatrix_x4(a_h, sb + QS_A + aoff);
                #pragma unroll
                for (int ni = 0; ni < 8; ni++) {
                    mma16816(acc[mi][ni], a_h, &b_h[ni >> 1][(ni & 1) * 2]);
                    mma16816(acc[mi][ni], a_h, &b_l[ni >> 1][(ni & 1) * 2]);
                }
            }
        }
        slot++; if (slot >= 3) slot = 0;
    }

    const int gm0 = m0 + warp_m * 64;
    const int gn0 = n0 + warp_n * 64;
    #pragma unroll
    for (int mi = 0; mi < 4; mi++) {
        int row = gm0 + mi * 16 + (lane >> 2);
        #pragma unroll
        for (int ni = 0; ni < 8; ni++) {
            int col = gn0 + ni * 8 + 2 * (lane & 3);
            float2 b2 = *(const float2*)&bias[col];
            float y0 = acc[mi][ni][0] + b2.x, y1 = acc[mi][ni][1] + b2.y;
            float y2 = acc[mi][ni][2] + b2.x, y3 = acc[mi][ni][3] + b2.y;
            if (out == 0) {
                *(__half2*)&Qh[(size_t)row * DIM + col]       = __floats2half2_rn(y0, y1);
                *(__half2*)&Qh[(size_t)(row + 8) * DIM + col] = __floats2half2_rn(y2, y3);
            } else {
                __half* Yhi = (out == 1) ? Khi : Vhi;
                __half* Ylo = (out == 1) ? Klo : Vlo;
                __half h0 = __float2half_rn(y0), h1 = __float2half_rn(y1);
                __half h2 = __float2half_rn(y2), h3 = __float2half_rn(y3);
                __half l0 = __float2half_rn(y0 - __half2float(h0));
                __half l1 = __float2half_rn(y1 - __half2float(h1));
                __half l2 = __float2half_rn(y2 - __half2float(h2));
                __half l3 = __float2half_rn(y3 - __half2float(h3));
                *(__half2*)&Yhi[(size_t)row * DIM + col]       = __halves2half2(h0, h1);
                *(__half2*)&Yhi[(size_t)(row + 8) * DIM + col] = __halves2half2(h2, h3);
                *(__half2*)&Ylo[(size_t)row * DIM + col]       = __halves2half2(l0, l1);
                *(__half2*)&Ylo[(size_t)(row + 8) * DIM + col] = __halves2half2(l2, l3);
            }
        }
    }
}

// ---------------------------------------------------------------------------
// O-projection GEMM (3-product): out = (Ahi+Alo) @ (Whi+Wlo)^T + bias, fp32
// CTA 128x128, 3-stage ring.
// ---------------------------------------------------------------------------
#define TM 128
#define SM_A_HI 0
#define SM_A_LO 16384
#define SM_B_HI 32768
#define SM_B_LO 49152
#define STAGE_BYTES 65536
#define NSTAGE 3
#define GEMM_SMEM (NSTAGE * STAGE_BYTES)

__device__ __forceinline__ void load_stage_o(
    uint32_t sb, const __half* __restrict__ Ahi, const __half* __restrict__ Alo,
    const __half* __restrict__ Bhi, const __half* __restrict__ Blo,
    int m0, int n0, int k0, int tid)
{
    #pragma unroll
    for (int it = 0; it < 4; it++) {
        int t = tid + it * 256;
        int row = t >> 3;
        int kk = (t & 7) * 8;
        uint32_t soff = SWZ((uint32_t)(row * 128 + kk * 2));
        CP_ASYNC_16(sb + SM_A_HI + soff, Ahi + (size_t)(m0 + row) * DIM + k0 + kk);
        CP_ASYNC_16(sb + SM_A_LO + soff, Alo + (size_t)(m0 + row) * DIM + k0 + kk);
        CP_ASYNC_16(sb + SM_B_HI + soff, Bhi + (size_t)(n0 + row) * DIM + k0 + kk);
        CP_ASYNC_16(sb + SM_B_LO + soff, Blo + (size_t)(n0 + row) * DIM + k0 + kk);
    }
}

__global__ __launch_bounds__(256, 1) void gemm_o_kernel(
    const __half* __restrict__ Ahi, const __half* __restrict__ Alo,
    const __half* __restrict__ Bhi, const __half* __restrict__ Blo,
    const float* __restrict__ bias, float* __restrict__ Yf)
{
    extern __shared__ char smem[];
    const uint32_t smem_base = smem_u32(smem);
    const int tid = threadIdx.x;
    const int wid = tid >> 5;
    const int lane = tid & 31;
    const int warp_m = wid & 3;
    const int warp_n = wid >> 2;
    const int m0 = blockIdx.x * TM;
    const int n0 = blockIdx.y * 128;

    float acc[2][8][4];
    #pragma unroll
    for (int mi = 0; mi < 2; mi++)
        #pragma unroll
        for (int ni = 0; ni < 8; ni++)
            #pragma unroll
            for (int r = 0; r < 4; r++) acc[mi][ni][r] = 0.f;

    load_stage_o(smem_base, Ahi, Alo, Bhi, Blo, m0, n0, 0, tid);
    CP_ASYNC_COMMIT();
    load_stage_o(smem_base + STAGE_BYTES, Ahi, Alo, Bhi, Blo, m0, n0, TKC, tid);
    CP_ASYNC_COMMIT();

    const int a_row = (lane & 15);
    const int a_kb  = (lane >> 4) << 4;
    const int b_row = ((lane >> 4) << 3) + (lane & 7);
    const int b_kb  = ((lane >> 3) & 1) << 4;

    int slot = 0;
    for (int c = 0; c < NCHUNK; c++) {
        CP_ASYNC_WAIT_1();
        __syncthreads();

        if (c + 2 < NCHUNK) {
            int s2 = slot + 2; if (s2 >= NSTAGE) s2 -= NSTAGE;
            load_stage_o(smem_base + s2 * STAGE_BYTES, Ahi, Alo, Bhi, Blo,
                         m0, n0, (c + 2) * TKC, tid);
        }
        CP_ASYNC_COMMIT();

        const uint32_t sb = smem_base + slot * STAGE_BYTES;
        #pragma unroll
        for (int ks = 0; ks < 4; ks++) {
            const int kbyte = ks * 32;
            uint32_t a_hi[2][4], a_lo[2][4], b_hi[4][4], b_lo[4][4];
            #pragma unroll
            for (int mi = 0; mi < 2; mi++) {
                uint32_t off = SWZ((uint32_t)((warp_m * 32 + mi * 16 + a_row) * 128 + kbyte + a_kb));
                ldmatrix_x4(a_hi[mi], sb + SM_A_HI + off);
                ldmatrix_x4(a_lo[mi], sb + SM_A_LO + off);
            }
            #pragma unroll
            for (int pi = 0; pi < 4; pi++) {
                uint32_t off = SWZ((uint32_t)((warp_n * 64 + pi * 16 + b_row) * 128 + kbyte + b_kb));
                ldmatrix_x4(b_hi[pi], sb + SM_B_HI + off);
                ldmatrix_x4(b_lo[pi], sb + SM_B_LO + off);
            }
            #pragma unroll
            for (int mi = 0; mi < 2; mi++)
                #pragma unroll
                for (int ni = 0; ni < 8; ni++) {
                    const uint32_t* bh = &b_hi[ni >> 1][(ni & 1) * 2];
                    const uint32_t* bl = &b_lo[ni >> 1][(ni & 1) * 2];
                    mma16816(acc[mi][ni], a_hi[mi], bh);
                    mma16816(acc[mi][ni], a_hi[mi], bl);
                    mma16816(acc[mi][ni], a_lo[mi], bh);
                }
        }
        slot++; if (slot >= NSTAGE) slot = 0;
    }

    const int gm0 = m0 + warp_m * 32;
    const int gn0 = n0 + warp_n * 64;
    #pragma unroll
    for (int mi = 0; mi < 2; mi++) {
        int row = gm0 + mi * 16 + (lane >> 2);
        #pragma unroll
        for (int ni = 0; ni < 8; ni++) {
            int col = gn0 + ni * 8 + 2 * (lane & 3);
            float2 b2 = *(const float2*)&bias[col];
            *(float2*)&Yf[(size_t)row * DIM + col] =
                make_float2(acc[mi][ni][0] + b2.x, acc[mi][ni][1] + b2.y);
            *(float2*)&Yf[(size_t)(row + 8) * DIM + col] =
                make_float2(acc[mi][ni][2] + b2.x, acc[mi][ni][3] + b2.y);
        }
    }
}

// ---------------------------------------------------------------------------
// Tensor-core causal flash attention.
// Q: plain fp16 (2 products QK^T). K,V: hi/lo. PV: 2 products (Phi*Vhi+Phi*Vlo).
// ---------------------------------------------------------------------------
#define SM_Qb 0
#define SM_Kb 32768
#define SM_Vb 98304
#define ATTN_SMEM 163840
#define KSC 0.12751741219860918f   /* (1/sqrt(128)) * log2(e) */

__device__ __forceinline__ void attn_load_kv(
    uint32_t sb, const __half* __restrict__ Khi, const __half* __restrict__ Klo,
    const __half* __restrict__ Vhi, const __half* __restrict__ Vlo,
    size_t gbase, int k0, int stage, int tid)
{
    #pragma unroll
    for (int i = 0; i < 16; i++) {
        int t = tid + i * 256;
        int kv  = t >> 11;
        int hil = (t >> 10) & 1;
        int row = (t >> 4) & 63;
        int ch  = t & 15;
        int pl  = ch >> 3;
        const __half* src;
        if (kv == 0) src = (hil ? Klo : Khi);
        else         src = (hil ? Vlo : Vhi);
        src += gbase + (size_t)(k0 + row) * DIM + ch * 8;
        uint32_t dst = sb + (kv == 0 ? SM_Kb : SM_Vb) + stage * 32768 + hil * 16384
                     + pl * 8192 + SWZ((uint32_t)(row * 128 + (ch & 7) * 16));
        CP_ASYNC_16(dst, src);
    }
}

__global__ __launch_bounds__(256, 1) void attn_tc_kernel(
    const __half* __restrict__ Qh,
    const __half* __restrict__ Khi, const __half* __restrict__ Klo,
    const __half* __restrict__ Vhi, const __half* __restrict__ Vlo,
    __half* __restrict__ Ahi, __half* __restrict__ Alo)
{
    extern __shared__ char smem[];
    const uint32_t sb = smem_u32(smem);
    const int tid = threadIdx.x;
    const int w = tid >> 5;
    const int lane = tid & 31;
    const int qt = gridDim.x - 1 - blockIdx.x;   // big tiles first
    const int h = blockIdx.y;
    const int b = blockIdx.z;
    const int q0 = qt * 128;
    const size_t gbase = (size_t)b * SEQ * DIM + (size_t)h * DHEAD;

    // Load Q tile (hi only)
    #pragma unroll
    for (int i = 0; i < 8; i++) {
        int t = tid + i * 256;
        int row = (t >> 4) & 127;
        int ch  = t & 15;
        int pl  = ch >> 3;
        const __half* src = Qh + gbase + (size_t)(q0 + row) * DIM + ch * 8;
        uint32_t dst = sb + SM_Qb + pl * 16384
                     + SWZ((uint32_t)(row * 128 + (ch & 7) * 16));
        CP_ASYNC_16(dst, src);
    }
    attn_load_kv(sb, Khi, Klo, Vhi, Vlo, gbase, 0, 0, tid);
    CP_ASYNC_COMMIT();

    float m0v = -1e30f, m1v = -1e30f, l0v = 0.f, l1v = 0.f;
    float acc_o[16][4];
    #pragma unroll
    for (int n = 0; n < 16; n++)
        #pragma unroll
        for (int r = 0; r < 4; r++) acc_o[n][r] = 0.f;

    const int a_row = lane & 15;
    const int a_kb  = (lane >> 4) << 4;
    const int b_row = ((lane >> 4) << 3) + (lane & 7);
    const int b_kb  = ((lane >> 3) & 1) << 4;
    const int v_row = (lane & 7) + ((lane >> 3) & 1) * 8;
    const int v_cb  = ((lane >> 4) & 1) << 4;

    const int qwmin = q0 + w * 16;
    const int nt = 2 * qt + 2;

    for (int kt = 0; kt < nt; kt++) {
        __syncthreads();
        if (kt + 1 < nt)
            attn_load_kv(sb, Khi, Klo, Vhi, Vlo, gbase, (kt + 1) * 64, (kt + 1) & 1, tid);
        CP_ASYNC_COMMIT();
        CP_ASYNC_WAIT_1();
        __syncthreads();

        const int k0 = kt * 64;
        const int st = kt & 1;
        if (k0 > qwmin + 15) continue;

        // ---- S = Q K^T (Qh*Khi + Qh*Klo) ----
        float s[8][4];
        #pragma unroll
        for (int ni = 0; ni < 8; ni++)
            #pragma unroll
            for (int r = 0; r < 4; r++) s[ni][r] = 0.f;

        #pragma unroll
        for (int ks = 0; ks < 8; ks++) {
            const int kbyte = (ks & 3) * 32;
            const int pl = ks >> 2;
            uint32_t aH[4];
            uint32_t aoff = SM_Qb + pl * 16384
                          + SWZ((uint32_t)((w * 16 + a_row) * 128 + kbyte + a_kb));
            ldmatrix_x4(aH, sb + aoff);
            #pragma unroll
            for (int pi = 0; pi < 4; pi++) {
                uint32_t bH[4], bL[4];
                uint32_t boff = SM_Kb + st * 32768 + pl * 8192
                              + SWZ((uint32_t)((pi * 16 + b_row) * 128 + kbyte + b_kb));
                ldmatrix_x4(bH, sb + boff);
                ldmatrix_x4(bL, sb + boff + 16384);
                mma16816(s[2 * pi],     aH, &bH[0]);
                mma16816(s[2 * pi],     aH, &bL[0]);
                mma16816(s[2 * pi + 1], aH, &bH[2]);
                mma16816(s[2 * pi + 1], aH, &bL[2]);
            }
        }

        // ---- causal mask ----
        const int qr0 = qwmin + (lane >> 2);
        const int qr1 = qr0 + 8;
        if (k0 + 63 > qwmin) {
            const int kc = k0 + 2 * (lane & 3);
            #pragma unroll
            for (int ni = 0; ni < 8; ni++) {
                int kb2 = kc + ni * 8;
                if (kb2     > qr0) s[ni][0] = -1e30f;
                if (kb2 + 1 > qr0) s[ni][1] = -1e30f;
                if (kb2     > qr1) s[ni][2] = -1e30f;
                if (kb2 + 1 > qr1) s[ni][3] = -1e30f;
            }
        }

        // ---- online softmax ----
        float mx0 = -1e30f, mx1 = -1e30f;
        #pragma unroll
        for (int ni = 0; ni < 8; ni++) {
            mx0 = fmaxf(mx0, fmaxf(s[ni][0], s[ni][1]));
            mx1 = fmaxf(mx1, fmaxf(s[ni][2], s[ni][3]));
        }
        mx0 = fmaxf(mx0, __shfl_xor_sync(0xffffffffu, mx0, 1));
        mx0 = fmaxf(mx0, __shfl_xor_sync(0xffffffffu, mx0, 2));
        mx1 = fmaxf(mx1, __shfl_xor_sync(0xffffffffu, mx1, 1));
        mx1 = fmaxf(mx1, __shfl_xor_sync(0xffffffffu, mx1, 2));
        float mn0 = fmaxf(m0v, mx0), mn1 = fmaxf(m1v, mx1);
        float corr0 = exp2f((m0v - mn0) * KSC);
        float corr1 = exp2f((m1v - mn1) * KSC);
        m0v = mn0; m1v = mn1;

        float rs0 = 0.f, rs1 = 0.f;
        #pragma unroll
        for (int ni = 0; ni < 8; ni++) {
            s[ni][0] = exp2f((s[ni][0] - mn0) * KSC);
            s[ni][1] = exp2f((s[ni][1] - mn0) * KSC);
            s[ni][2] = exp2f((s[ni][2] - mn1) * KSC);
            s[ni][3] = exp2f((s[ni][3] - mn1) * KSC);
            rs0 += s[ni][0] + s[ni][1];
            rs1 += s[ni][2] + s[ni][3];
        }
        rs0 += __shfl_xor_sync(0xffffffffu, rs0, 1);
        rs0 += __shfl_xor_sync(0xffffffffu, rs0, 2);
        rs1 += __shfl_xor_sync(0xffffffffu, rs1, 1);
        rs1 += __shfl_xor_sync(0xffffffffu, rs1, 2);
        l0v = l0v * corr0 + rs0;
        l1v = l1v * corr1 + rs1;

        #pragma unroll
        for (int n = 0; n < 16; n++) {
            acc_o[n][0] *= corr0; acc_o[n][1] *= corr0;
            acc_o[n][2] *= corr1; acc_o[n][3] *= corr1;
        }

        // ---- O += P V (Phi*Vhi + Phi*Vlo) ----
        #pragma unroll
        for (int vks = 0; vks < 4; vks++) {
            uint32_t pH[4];
            #pragma unroll
            for (int half16 = 0; half16 < 2; half16++) {
                const float* sp = s[2 * vks + half16];
                __half2 h01 = __floats2half2_rn(sp[0], sp[1]);
                __half2 h23 = __floats2half2_rn(sp[2], sp[3]);
                pH[2 * half16]     = *(uint32_t*)&h01;
                pH[2 * half16 + 1] = *(uint32_t*)&h23;
            }
            const int vr = vks * 16 + v_row;
            #pragma unroll
            for (int nb = 0; nb < 8; nb++) {
                uint32_t vH[4], vL[4];
                uint32_t voff = SM_Vb + st * 32768 + (nb >> 2) * 8192
                              + SWZ((uint32_t)(vr * 128 + (nb & 3) * 32 + v_cb));
                ldmatrix_x4_trans(vH, sb + voff);
                ldmatrix_x4_trans(vL, sb + voff + 16384);
                mma16816(acc_o[2 * nb],     pH, &vH[0]);
                mma16816(acc_o[2 * nb],     pH, &vL[0]);
                mma16816(acc_o[2 * nb + 1], pH, &vH[2]);
                mma16816(acc_o[2 * nb + 1], pH, &vL[2]);
            }
        }
    }

    // ---- normalize, split hi/lo, store ----
    const float inv0 = 1.f / l0v;
    const float inv1 = 1.f / l1v;
    const size_t r0o = gbase + (size_t)(q0 + w * 16 + (lane >> 2)) * DIM;
    const size_t r1o = r0o + 8 * DIM;
    #pragma unroll
    for (int n = 0; n < 16; n++) {
        int col = n * 8 + 2 * (lane & 3);
        float y0 = acc_o[n][0] * inv0, y1 = acc_o[n][1] * inv0;
        float y2 = acc_o[n][2] * inv1, y3 = acc_o[n][3] * inv1;
        __half h0 = __float2half_rn(y0), h1 = __float2half_rn(y1);
        __half h2 = __float2half_rn(y2), h3 = __float2half_rn(y3);
        __half l0h = __float2half_rn(y0 - __half2float(h0));
        __half l1h = __float2half_rn(y1 - __half2float(h1));
        __half l2h = __float2half_rn(y2 - __half2float(h2));
        __half l3h = __float2half_rn(y3 - __half2float(h3));
        *(__half2*)&Ahi[r0o + col] = __halves2half2(h0, h1);
        *(__half2*)&Ahi[r1o + col] = __halves2half2(h2, h3);
        *(__half2*)&Alo[r0o + col] = __halves2half2(l0h, l1h);
        *(__half2*)&Alo[r1o + col] = __halves2half2(l2h, l3h);
    }
}

// ---------------------------------------------------------------------------
extern "C" void kernel_launch(void* const* d_in, const int* in_sizes, int n_in,
                              void* d_out, int out_size)
{
    const float* x  = (const float*)d_in[0];
    const float* Wq = (const float*)d_in[1];
    const float* bq = (const float*)d_in[2];
    const float* Wk = (const float*)d_in[3];
    const float* bk = (const float*)d_in[4];
    const float* Wv = (const float*)d_in[5];
    const float* bv = (const float*)d_in[6];
    const float* Wo = (const float*)d_in[7];
    const float* bo = (const float*)d_in[8];
    float* out = (float*)d_out;

    __half *Xhi, *Whi, *Wlo, *Qh, *Khi, *Klo, *Vhi, *Vlo, *Ahi, *Alo;
    cudaGetSymbolAddress((void**)&Xhi, g_Xhi);
    cudaGetSymbolAddress((void**)&Whi, g_Whi);
    cudaGetSymbolAddress((void**)&Wlo, g_Wlo);
    cudaGetSymbolAddress((void**)&Qh,  g_Qh);
    cudaGetSymbolAddress((void**)&Khi, g_Khi);
    cudaGetSymbolAddress((void**)&Klo, g_Klo);
    cudaGetSymbolAddress((void**)&Vhi, g_Vhi);
    cudaGetSymbolAddress((void**)&Vlo, g_Vlo);
    cudaGetSymbolAddress((void**)&Ahi, g_Ahi);
    cudaGetSymbolAddress((void**)&Alo, g_Alo);

    cudaFuncSetAttribute(gemm_qkv_kernel,
                         cudaFuncAttributeMaxDynamicSharedMemorySize, QKV_SMEM);
    cudaFuncSetAttribute(gemm_o_kernel,
                         cudaFuncAttributeMaxDynamicSharedMemorySize, GEMM_SMEM);
    cudaFuncSetAttribute(attn_tc_kernel,
                         cudaFuncAttributeMaxDynamicSharedMemorySize, ATTN_SMEM);

    const int nX4 = MTOT * DIM / 4;
    const int nW4 = DIM * DIM / 4;
    const size_t WSZ = (size_t)DIM * DIM;

    splitX_hi_kernel<<<nX4 / 256, 256>>>(x, Xhi, nX4);
    splitW_kernel<<<dim3(nW4 / 256, 4), 256>>>(Wq, Wk, Wv, Wo, Whi, Wlo, nW4);

    // Fused QKV projection (256x128 tiles)
    gemm_qkv_kernel<<<dim3(MTOT / QTM, 48), 256, QKV_SMEM>>>(
        Xhi, Whi, Wlo, bq, bk, bv, Qh, Khi, Klo, Vhi, Vlo);

    // Attention
    dim3 agrid(SEQ / 128, HEADS, BATCH);
    attn_tc_kernel<<<agrid, 256, ATTN_SMEM>>>(Qh, Khi, Klo, Vhi, Vlo, Ahi, Alo);

    // Output projection (full 3-product accuracy)
    gemm_o_kernel<<<dim3(MTOT / TM, DIM / 128), 256, GEMM_SMEM>>>(
        Ahi, Alo, Whi + 3 * WSZ, Wlo + 3 * WSZ, bo, out);
}

// round 7
// speedup vs baseline: 6.8263x; 1.4517x over previous
#include <cuda_runtime.h>
#include <cuda_fp16.h>
#include <math.h>
#include <stdint.h>

// Problem constants
#define BATCH 2
#define SEQ   2048
#define DIM   2048
#define HEADS 16
#define DHEAD 128
#define MTOT  (BATCH * SEQ)   // 4096

// ---------------------------------------------------------------------------
// Scratch (allocation-free rule: __device__ globals)
// ---------------------------------------------------------------------------
__device__ __half g_Xhi[MTOT * DIM];
__device__ __half g_Whi[4][DIM * DIM];
__device__ __half g_Wlo[4][DIM * DIM];   // only [3] (Wo) populated
__device__ __half g_Qh [MTOT * DIM];
__device__ __half g_Kh [MTOT * DIM];
__device__ __half g_Vh [MTOT * DIM];
__device__ __half g_Ahi[MTOT * DIM];
__device__ __half g_Alo[MTOT * DIM];

// ---------------------------------------------------------------------------
// PTX helpers
// ---------------------------------------------------------------------------
__device__ __forceinline__ uint32_t smem_u32(const void* p) {
    uint32_t a;
    asm("{ .reg .u64 t; cvta.to.shared.u64 t, %1; cvt.u32.u64 %0, t; }" : "=r"(a) : "l"(p));
    return a;
}

#define CP_ASYNC_16(dst_u32, src_ptr) \
    asm volatile("cp.async.cg.shared.global [%0], [%1], 16;" \
                 :: "r"(dst_u32), "l"(src_ptr) : "memory")
#define CP_ASYNC_COMMIT() asm volatile("cp.async.commit_group;" ::: "memory")
#define CP_ASYNC_WAIT_1() asm volatile("cp.async.wait_group 1;" ::: "memory")
#define CP_ASYNC_WAIT_2() asm volatile("cp.async.wait_group 2;" ::: "memory")

__device__ __forceinline__ void ldmatrix_x4(uint32_t* r, uint32_t addr) {
    asm volatile("ldmatrix.sync.aligned.m8n8.x4.shared.b16 {%0,%1,%2,%3}, [%4];"
        : "=r"(r[0]), "=r"(r[1]), "=r"(r[2]), "=r"(r[3]) : "r"(addr));
}
__device__ __forceinline__ void ldmatrix_x4_trans(uint32_t* r, uint32_t addr) {
    asm volatile("ldmatrix.sync.aligned.m8n8.x4.trans.shared.b16 {%0,%1,%2,%3}, [%4];"
        : "=r"(r[0]), "=r"(r[1]), "=r"(r[2]), "=r"(r[3]) : "r"(addr));
}

__device__ __forceinline__ void mma16816(float* d, const uint32_t* a, const uint32_t* b) {
    asm volatile(
        "mma.sync.aligned.m16n8k16.row.col.f32.f16.f16.f32 "
        "{%0,%1,%2,%3}, {%4,%5,%6,%7}, {%8,%9}, {%0,%1,%2,%3};"
        : "+f"(d[0]), "+f"(d[1]), "+f"(d[2]), "+f"(d[3])
        : "r"(a[0]), "r"(a[1]), "r"(a[2]), "r"(a[3]), "r"(b[0]), "r"(b[1]));
}

#define SWZ(x) ((x) ^ (((x) >> 3) & 0x70))

// ---------------------------------------------------------------------------
// Splits
// ---------------------------------------------------------------------------
__global__ __launch_bounds__(256) void splitX_hi_kernel(
    const float* __restrict__ in, __half* __restrict__ hi, int n4)
{
    int i = blockIdx.x * 256 + threadIdx.x;
    if (i >= n4) return;
    float4 v = ((const float4*)in)[i];
    ((__half2*)hi)[2 * i]     = __floats2half2_rn(v.x, v.y);
    ((__half2*)hi)[2 * i + 1] = __floats2half2_rn(v.z, v.w);
}

__global__ __launch_bounds__(256) void splitW_kernel(
    const float* __restrict__ w0, const float* __restrict__ w1,
    const float* __restrict__ w2, const float* __restrict__ w3,
    __half* __restrict__ WhiAll, __half* __restrict__ WloAll, int n4)
{
    int i = blockIdx.x * 256 + threadIdx.x;
    if (i >= n4) return;
    int wsel = blockIdx.y;
    const float* in = (wsel == 0) ? w0 : (wsel == 1) ? w1 : (wsel == 2) ? w2 : w3;
    __half* hi = WhiAll + (size_t)wsel * DIM * DIM;
    float4 v = ((const float4*)in)[i];
    __half hx = __float2half_rn(v.x), hy = __float2half_rn(v.y);
    __half hz = __float2half_rn(v.z), hw = __float2half_rn(v.w);
    ((__half2*)hi)[2 * i]     = __halves2half2(hx, hy);
    ((__half2*)hi)[2 * i + 1] = __halves2half2(hz, hw);
    if (wsel == 3) {   // only Wo needs the lo plane (O-proj is 3-product)
        __half* lo = WloAll + (size_t)wsel * DIM * DIM;
        __half lx = __float2half_rn(v.x - __half2float(hx));
        __half ly = __float2half_rn(v.y - __half2float(hy));
        __half lz = __float2half_rn(v.z - __half2float(hz));
        __half lw = __float2half_rn(v.w - __half2float(hw));
        ((__half2*)lo)[2 * i]     = __halves2half2(lx, ly);
        ((__half2*)lo)[2 * i + 1] = __halves2half2(lz, lw);
    }
}

// ---------------------------------------------------------------------------
// Fused QKV GEMM (single product): Y = Xhi @ Whi^T + bias   -> plain fp16
// CTA tile 256x128, 8 warps (4m x 2n), warp tile 64x64, K chunk 64, 4 stages.
// Grid (16, 48): y/16 selects Q/K/V output, y%16 selects n-block.
// ---------------------------------------------------------------------------
#define TKC 64
#define NCHUNK (DIM / TKC)
#define QTM 256
#define QS_A  0
#define QS_B  32768
#define QSTAGE 49152
#define QKV_SMEM (4 * QSTAGE)   // 196608

__device__ __forceinline__ void load_stage_qkv(
    uint32_t sb, const __half* __restrict__ Xh, const __half* __restrict__ Bh,
    int m0, int n0, int k0, int tid)
{
    #pragma unroll
    for (int it = 0; it < 8; it++) {
        int t = tid + it * 256;            // 0..2047
        int row = t >> 3;                  // 0..255
        int kk = (t & 7) * 8;
        uint32_t soff = SWZ((uint32_t)(row * 128 + kk * 2));
        CP_ASYNC_16(sb + QS_A + soff, Xh + (size_t)(m0 + row) * DIM + k0 + kk);
    }
    #pragma unroll
    for (int it = 0; it < 4; it++) {
        int t = tid + it * 256;            // 0..1023
        int row = t >> 3;                  // 0..127
        int kk = (t & 7) * 8;
        uint32_t soff = SWZ((uint32_t)(row * 128 + kk * 2));
        CP_ASYNC_16(sb + QS_B + soff, Bh + (size_t)(n0 + row) * DIM + k0 + kk);
    }
}

__global__ __launch_bounds__(256, 1) void gemm_qkv_kernel(
    const __half* __restrict__ Xh, const __half* __restrict__ WhiAll,
    const float* __restrict__ bq, const float* __restrict__ bk,
    const float* __restrict__ bv,
    __half* __restrict__ Qh, __half* __restrict__ Kh, __half* __restrict__ Vh)
{
    extern __shared__ char smem[];
    const uint32_t smem_base = smem_u32(smem);
    const int tid = threadIdx.x;
    const int wid = tid >> 5;
    const int lane = tid & 31;
    const int warp_m = wid & 3;
    const int warp_n = wid >> 2;
    const int m0 = blockIdx.x * QTM;
    const int out = blockIdx.y >> 4;   // 0=Q 1=K 2=V
    const int n0 = (blockIdx.y & 15) * 128;

    const __half* Bh = WhiAll + (size_t)out * DIM * DIM;
    const float* bias = (out == 0) ? bq : (out == 1) ? bk : bv;
    __half* Yp = (out == 0) ? Qh : (out == 1) ? Kh : Vh;

    float acc[4][8][4];
    #pragma unroll
    for (int mi = 0; mi < 4; mi++)
        #pragma unroll
        for (int ni = 0; ni < 8; ni++)
            #pragma unroll
            for (int r = 0; r < 4; r++) acc[mi][ni][r] = 0.f;

    load_stage_qkv(smem_base,              Xh, Bh, m0, n0, 0 * TKC, tid);
    CP_ASYNC_COMMIT();
    load_stage_qkv(smem_base + QSTAGE,     Xh, Bh, m0, n0, 1 * TKC, tid);
    CP_ASYNC_COMMIT();
    load_stage_qkv(smem_base + 2 * QSTAGE, Xh, Bh, m0, n0, 2 * TKC, tid);
    CP_ASYNC_COMMIT();

    const int a_row = (lane & 15);
    const int a_kb  = (lane >> 4) << 4;
    const int b_row = ((lane >> 4) << 3) + (lane & 7);
    const int b_kb  = ((lane >> 3) & 1) << 4;

    int slot = 0;
    for (int c = 0; c < NCHUNK; c++) {
        CP_ASYNC_WAIT_2();
        __syncthreads();

        if (c + 3 < NCHUNK) {
            int s2 = (slot + 3) & 3;
            load_stage_qkv(smem_base + s2 * QSTAGE, Xh, Bh, m0, n0, (c + 3) * TKC, tid);
        }
        CP_ASYNC_COMMIT();

        const uint32_t sb = smem_base + slot * QSTAGE;
        #pragma unroll
        for (int ks = 0; ks < 4; ks++) {
            const int kbyte = ks * 32;
            uint32_t b_h[4][4];
            #pragma unroll
            for (int pi = 0; pi < 4; pi++) {
                uint32_t off = SWZ((uint32_t)((warp_n * 64 + pi * 16 + b_row) * 128 + kbyte + b_kb));
                ldmatrix_x4(b_h[pi], sb + QS_B + off);
            }
            #pragma unroll
            for (int mi = 0; mi < 4; mi++) {
                uint32_t a_h[4];
                uint32_t aoff = SWZ((uint32_t)((warp_m * 64 + mi * 16 + a_row) * 128 + kbyte + a_kb));
                ldmatrix_x4(a_h, sb + QS_A + aoff);
                #pragma unroll
                for (int ni = 0; ni < 8; ni++)
                    mma16816(acc[mi][ni], a_h, &b_h[ni >> 1][(ni & 1) * 2]);
            }
        }
        slot = (slot + 1) & 3;
    }

    const int gm0 = m0 + warp_m * 64;
    const int gn0 = n0 + warp_n * 64;
    #pragma unroll
    for (int mi = 0; mi < 4; mi++) {
        int row = gm0 + mi * 16 + (lane >> 2);
        #pragma unroll
        for (int ni = 0; ni < 8; ni++) {
            int col = gn0 + ni * 8 + 2 * (lane & 3);
            float2 b2 = *(const float2*)&bias[col];
            *(__half2*)&Yp[(size_t)row * DIM + col] =
                __floats2half2_rn(acc[mi][ni][0] + b2.x, acc[mi][ni][1] + b2.y);
            *(__half2*)&Yp[(size_t)(row + 8) * DIM + col] =
                __floats2half2_rn(acc[mi][ni][2] + b2.x, acc[mi][ni][3] + b2.y);
        }
    }
}

// ---------------------------------------------------------------------------
// O-projection GEMM (3-product): out = (Ahi+Alo) @ (Whi+Wlo)^T + bias, fp32
// ---------------------------------------------------------------------------
#define TM 128
#define SM_A_HI 0
#define SM_A_LO 16384
#define SM_B_HI 32768
#define SM_B_LO 49152
#define STAGE_BYTES 65536
#define NSTAGE 3
#define GEMM_SMEM (NSTAGE * STAGE_BYTES)

__device__ __forceinline__ void load_stage_o(
    uint32_t sb, const __half* __restrict__ Ahi, const __half* __restrict__ Alo,
    const __half* __restrict__ Bhi, const __half* __restrict__ Blo,
    int m0, int n0, int k0, int tid)
{
    #pragma unroll
    for (int it = 0; it < 4; it++) {
        int t = tid + it * 256;
        int row = t >> 3;
        int kk = (t & 7) * 8;
        uint32_t soff = SWZ((uint32_t)(row * 128 + kk * 2));
        CP_ASYNC_16(sb + SM_A_HI + soff, Ahi + (size_t)(m0 + row) * DIM + k0 + kk);
        CP_ASYNC_16(sb + SM_A_LO + soff, Alo + (size_t)(m0 + row) * DIM + k0 + kk);
        CP_ASYNC_16(sb + SM_B_HI + soff, Bhi + (size_t)(n0 + row) * DIM + k0 + kk);
        CP_ASYNC_16(sb + SM_B_LO + soff, Blo + (size_t)(n0 + row) * DIM + k0 + kk);
    }
}

__global__ __launch_bounds__(256, 1) void gemm_o_kernel(
    const __half* __restrict__ Ahi, const __half* __restrict__ Alo,
    const __half* __restrict__ Bhi, const __half* __restrict__ Blo,
    const float* __restrict__ bias, float* __restrict__ Yf)
{
    extern __shared__ char smem[];
    const uint32_t smem_base = smem_u32(smem);
    const int tid = threadIdx.x;
    const int wid = tid >> 5;
    const int lane = tid & 31;
    const int warp_m = wid & 3;
    const int warp_n = wid >> 2;
    const int m0 = blockIdx.x * TM;
    const int n0 = blockIdx.y * 128;

    float acc[2][8][4];
    #pragma unroll
    for (int mi = 0; mi < 2; mi++)
        #pragma unroll
        for (int ni = 0; ni < 8; ni++)
            #pragma unroll
            for (int r = 0; r < 4; r++) acc[mi][ni][r] = 0.f;

    load_stage_o(smem_base, Ahi, Alo, Bhi, Blo, m0, n0, 0, tid);
    CP_ASYNC_COMMIT();
    load_stage_o(smem_base + STAGE_BYTES, Ahi, Alo, Bhi, Blo, m0, n0, TKC, tid);
    CP_ASYNC_COMMIT();

    const int a_row = (lane & 15);
    const int a_kb  = (lane >> 4) << 4;
    const int b_row = ((lane >> 4) << 3) + (lane & 7);
    const int b_kb  = ((lane >> 3) & 1) << 4;

    int slot = 0;
    for (int c = 0; c < NCHUNK; c++) {
        CP_ASYNC_WAIT_1();
        __syncthreads();

        if (c + 2 < NCHUNK) {
            int s2 = slot + 2; if (s2 >= NSTAGE) s2 -= NSTAGE;
            load_stage_o(smem_base + s2 * STAGE_BYTES, Ahi, Alo, Bhi, Blo,
                         m0, n0, (c + 2) * TKC, tid);
        }
        CP_ASYNC_COMMIT();

        const uint32_t sb = smem_base + slot * STAGE_BYTES;
        #pragma unroll
        for (int ks = 0; ks < 4; ks++) {
            const int kbyte = ks * 32;
            uint32_t a_hi[2][4], a_lo[2][4], b_hi[4][4], b_lo[4][4];
            #pragma unroll
            for (int mi = 0; mi < 2; mi++) {
                uint32_t off = SWZ((uint32_t)((warp_m * 32 + mi * 16 + a_row) * 128 + kbyte + a_kb));
                ldmatrix_x4(a_hi[mi], sb + SM_A_HI + off);
                ldmatrix_x4(a_lo[mi], sb + SM_A_LO + off);
            }
            #pragma unroll
            for (int pi = 0; pi < 4; pi++) {
                uint32_t off = SWZ((uint32_t)((warp_n * 64 + pi * 16 + b_row) * 128 + kbyte + b_kb));
                ldmatrix_x4(b_hi[pi], sb + SM_B_HI + off);
                ldmatrix_x4(b_lo[pi], sb + SM_B_LO + off);
            }
            #pragma unroll
            for (int mi = 0; mi < 2; mi++)
                #pragma unroll
                for (int ni = 0; ni < 8; ni++) {
                    const uint32_t* bh = &b_hi[ni >> 1][(ni & 1) * 2];
                    const uint32_t* bl = &b_lo[ni >> 1][(ni & 1) * 2];
                    mma16816(acc[mi][ni], a_hi[mi], bh);
                    mma16816(acc[mi][ni], a_hi[mi], bl);
                    mma16816(acc[mi][ni], a_lo[mi], bh);
                }
        }
        slot++; if (slot >= NSTAGE) slot = 0;
    }

    const int gm0 = m0 + warp_m * 32;
    const int gn0 = n0 + warp_n * 64;
    #pragma unroll
    for (int mi = 0; mi < 2; mi++) {
        int row = gm0 + mi * 16 + (lane >> 2);
        #pragma unroll
        for (int ni = 0; ni < 8; ni++) {
            int col = gn0 + ni * 8 + 2 * (lane & 3);
            float2 b2 = *(const float2*)&bias[col];
            *(float2*)&Yf[(size_t)row * DIM + col] =
                make_float2(acc[mi][ni][0] + b2.x, acc[mi][ni][1] + b2.y);
            *(float2*)&Yf[(size_t)(row + 8) * DIM + col] =
                make_float2(acc[mi][ni][2] + b2.x, acc[mi][ni][3] + b2.y);
        }
    }
}

// ---------------------------------------------------------------------------
// Tensor-core causal flash attention. Q, K, V plain fp16; 1 product per GEMM.
// Smem: Q 32KB | K 2st x 16KB | V 2st x 16KB = 96KB.
// ---------------------------------------------------------------------------
#define SM_Qb 0
#define SM_Kb 32768
#define SM_Vb 65536
#define ATTN_SMEM 98304
#define KSC 0.12751741219860918f   /* (1/sqrt(128)) * log2(e) */

__device__ __forceinline__ void attn_load_kv(
    uint32_t sb, const __half* __restrict__ Kh, const __half* __restrict__ Vh,
    size_t gbase, int k0, int stage, int tid)
{
    #pragma unroll
    for (int i = 0; i < 8; i++) {
        int t = tid + i * 256;            // 0..2047
        int kv  = t >> 10;                // 0: K, 1: V
        int row = (t >> 4) & 63;
        int ch  = t & 15;
        int pl  = ch >> 3;
        const __half* src = (kv ? Vh : Kh) + gbase + (size_t)(k0 + row) * DIM + ch * 8;
        uint32_t dst = sb + (kv ? SM_Vb : SM_Kb) + stage * 16384
                     + pl * 8192 + SWZ((uint32_t)(row * 128 + (ch & 7) * 16));
        CP_ASYNC_16(dst, src);
    }
}

__global__ __launch_bounds__(256, 1) void attn_tc_kernel(
    const __half* __restrict__ Qh, const __half* __restrict__ Kh,
    const __half* __restrict__ Vh,
    __half* __restrict__ Ahi, __half* __restrict__ Alo)
{
    extern __shared__ char smem[];
    const uint32_t sb = smem_u32(smem);
    const int tid = threadIdx.x;
    const int w = tid >> 5;
    const int lane = tid & 31;
    const int qt = gridDim.x - 1 - blockIdx.x;   // big tiles first
    const int h = blockIdx.y;
    const int b = blockIdx.z;
    const int q0 = qt * 128;
    const size_t gbase = (size_t)b * SEQ * DIM + (size_t)h * DHEAD;

    // Load Q tile
    #pragma unroll
    for (int i = 0; i < 8; i++) {
        int t = tid + i * 256;
        int row = (t >> 4) & 127;
        int ch  = t & 15;
        int pl  = ch >> 3;
        const __half* src = Qh + gbase + (size_t)(q0 + row) * DIM + ch * 8;
        uint32_t dst = sb + SM_Qb + pl * 16384
                     + SWZ((uint32_t)(row * 128 + (ch & 7) * 16));
        CP_ASYNC_16(dst, src);
    }
    attn_load_kv(sb, Kh, Vh, gbase, 0, 0, tid);
    CP_ASYNC_COMMIT();

    float m0v = -1e30f, m1v = -1e30f, l0v = 0.f, l1v = 0.f;
    float acc_o[16][4];
    #pragma unroll
    for (int n = 0; n < 16; n++)
        #pragma unroll
        for (int r = 0; r < 4; r++) acc_o[n][r] = 0.f;

    const int a_row = lane & 15;
    const int a_kb  = (lane >> 4) << 4;
    const int b_row = ((lane >> 4) << 3) + (lane & 7);
    const int b_kb  = ((lane >> 3) & 1) << 4;
    const int v_row = (lane & 7) + ((lane >> 3) & 1) * 8;
    const int v_cb  = ((lane >> 4) & 1) << 4;

    const int qwmin = q0 + w * 16;
    const int nt = 2 * qt + 2;

    for (int kt = 0; kt < nt; kt++) {
        __syncthreads();
        if (kt + 1 < nt)
            attn_load_kv(sb, Kh, Vh, gbase, (kt + 1) * 64, (kt + 1) & 1, tid);
        CP_ASYNC_COMMIT();
        CP_ASYNC_WAIT_1();
        __syncthreads();

        const int k0 = kt * 64;
        const int st = kt & 1;
        if (k0 > qwmin + 15) continue;

        // ---- S = Q K^T (single product) ----
        float s[8][4];
        #pragma unroll
        for (int ni = 0; ni < 8; ni++)
            #pragma unroll
            for (int r = 0; r < 4; r++) s[ni][r] = 0.f;

        #pragma unroll
        for (int ks = 0; ks < 8; ks++) {
            const int kbyte = (ks & 3) * 32;
            const int pl = ks >> 2;
            uint32_t aH[4];
            uint32_t aoff = SM_Qb + pl * 16384
                          + SWZ((uint32_t)((w * 16 + a_row) * 128 + kbyte + a_kb));
            ldmatrix_x4(aH, sb + aoff);
            #pragma unroll
            for (int pi = 0; pi < 4; pi++) {
                uint32_t bH[4];
                uint32_t boff = SM_Kb + st * 16384 + pl * 8192
                              + SWZ((uint32_t)((pi * 16 + b_row) * 128 + kbyte + b_kb));
                ldmatrix_x4(bH, sb + boff);
                mma16816(s[2 * pi],     aH, &bH[0]);
                mma16816(s[2 * pi + 1], aH, &bH[2]);
            }
        }

        // ---- causal mask ----
        const int qr0 = qwmin + (lane >> 2);
        const int qr1 = qr0 + 8;
        if (k0 + 63 > qwmin) {
            const int kc = k0 + 2 * (lane & 3);
            #pragma unroll
            for (int ni = 0; ni < 8; ni++) {
                int kb2 = kc + ni * 8;
                if (kb2     > qr0) s[ni][0] = -1e30f;
                if (kb2 + 1 > qr0) s[ni][1] = -1e30f;
                if (kb2     > qr1) s[ni][2] = -1e30f;
                if (kb2 + 1 > qr1) s[ni][3] = -1e30f;
            }
        }

        // ---- online softmax ----
        float mx0 = -1e30f, mx1 = -1e30f;
        #pragma unroll
        for (int ni = 0; ni < 8; ni++) {
            mx0 = fmaxf(mx0, fmaxf(s[ni][0], s[ni][1]));
            mx1 = fmaxf(mx1, fmaxf(s[ni][2], s[ni][3]));
        }
        mx0 = fmaxf(mx0, __shfl_xor_sync(0xffffffffu, mx0, 1));
        mx0 = fmaxf(mx0, __shfl_xor_sync(0xffffffffu, mx0, 2));
        mx1 = fmaxf(mx1, __shfl_xor_sync(0xffffffffu, mx1, 1));
        mx1 = fmaxf(mx1, __shfl_xor_sync(0xffffffffu, mx1, 2));
        float mn0 = fmaxf(m0v, mx0), mn1 = fmaxf(m1v, mx1);
        float corr0 = exp2f((m0v - mn0) * KSC);
        float corr1 = exp2f((m1v - mn1) * KSC);
        m0v = mn0; m1v = mn1;

        float rs0 = 0.f, rs1 = 0.f;
        #pragma unroll
        for (int ni = 0; ni < 8; ni++) {
            s[ni][0] = exp2f((s[ni][0] - mn0) * KSC);
            s[ni][1] = exp2f((s[ni][1] - mn0) * KSC);
            s[ni][2] = exp2f((s[ni][2] - mn1) * KSC);
            s[ni][3] = exp2f((s[ni][3] - mn1) * KSC);
            rs0 += s[ni][0] + s[ni][1];
            rs1 += s[ni][2] + s[ni][3];
        }
        rs0 += __shfl_xor_sync(0xffffffffu, rs0, 1);
        rs0 += __shfl_xor_sync(0xffffffffu, rs0, 2);
        rs1 += __shfl_xor_sync(0xffffffffu, rs1, 1);
        rs1 += __shfl_xor_sync(0xffffffffu, rs1, 2);
        l0v = l0v * corr0 + rs0;
        l1v = l1v * corr1 + rs1;

        #pragma unroll
        for (int n = 0; n < 16; n++) {
            acc_o[n][0] *= corr0; acc_o[n][1] *= corr0;
            acc_o[n][2] *= corr1; acc_o[n][3] *= corr1;
        }

        // ---- O += P V (single product) ----
        #pragma unroll
        for (int vks = 0; vks < 4; vks++) {
            uint32_t pH[4];
            #pragma unroll
            for (int half16 = 0; half16 < 2; half16++) {
                const float* sp = s[2 * vks + half16];
                __half2 h01 = __floats2half2_rn(sp[0], sp[1]);
                __half2 h23 = __floats2half2_rn(sp[2], sp[3]);
                pH[2 * half16]     = *(uint32_t*)&h01;
                pH[2 * half16 + 1] = *(uint32_t*)&h23;
            }
            const int vr = vks * 16 + v_row;
            #pragma unroll
            for (int nb = 0; nb < 8; nb++) {
                uint32_t vH[4];
                uint32_t voff = SM_Vb + st * 16384 + (nb >> 2) * 8192
                              + SWZ((uint32_t)(vr * 128 + (nb & 3) * 32 + v_cb));
                ldmatrix_x4_trans(vH, sb + voff);
                mma16816(acc_o[2 * nb],     pH, &vH[0]);
                mma16816(acc_o[2 * nb + 1], pH, &vH[2]);
            }
        }
    }

    // ---- normalize, split hi/lo, store ----
    const float inv0 = 1.f / l0v;
    const float inv1 = 1.f / l1v;
    const size_t r0o = gbase + (size_t)(q0 + w * 16 + (lane >> 2)) * DIM;
    const size_t r1o = r0o + 8 * DIM;
    #pragma unroll
    for (int n = 0; n < 16; n++) {
        int col = n * 8 + 2 * (lane & 3);
        float y0 = acc_o[n][0] * inv0, y1 = acc_o[n][1] * inv0;
        float y2 = acc_o[n][2] * inv1, y3 = acc_o[n][3] * inv1;
        __half h0 = __float2half_rn(y0), h1 = __float2half_rn(y1);
        __half h2 = __float2half_rn(y2), h3 = __float2half_rn(y3);
        __half l0h = __float2half_rn(y0 - __half2float(h0));
        __half l1h = __float2half_rn(y1 - __half2float(h1));
        __half l2h = __float2half_rn(y2 - __half2float(h2));
        __half l3h = __float2half_rn(y3 - __half2float(h3));
        *(__half2*)&Ahi[r0o + col] = __halves2half2(h0, h1);
        *(__half2*)&Ahi[r1o + col] = __halves2half2(h2, h3);
        *(__half2*)&Alo[r0o + col] = __halves2half2(l0h, l1h);
        *(__half2*)&Alo[r1o + col] = __halves2half2(l2h, l3h);
    }
}

// ---------------------------------------------------------------------------
extern "C" void kernel_launch(void* const* d_in, const int* in_sizes, int n_in,
                              void* d_out, int out_size)
{
    const float* x  = (const float*)d_in[0];
    const float* Wq = (const float*)d_in[1];
    const float* bq = (const float*)d_in[2];
    const float* Wk = (const float*)d_in[3];
    const float* bk = (const float*)d_in[4];
    const float* Wv = (const float*)d_in[5];
    const float* bv = (const float*)d_in[6];
    const float* Wo = (const float*)d_in[7];
    const float* bo = (const float*)d_in[8];
    float* out = (float*)d_out;

    __half *Xhi, *Whi, *Wlo, *Qh, *Kh, *Vh, *Ahi, *Alo;
    cudaGetSymbolAddress((void**)&Xhi, g_Xhi);
    cudaGetSymbolAddress((void**)&Whi, g_Whi);
    cudaGetSymbolAddress((void**)&Wlo, g_Wlo);
    cudaGetSymbolAddress((void**)&Qh,  g_Qh);
    cudaGetSymbolAddress((void**)&Kh,  g_Kh);
    cudaGetSymbolAddress((void**)&Vh,  g_Vh);
    cudaGetSymbolAddress((void**)&Ahi, g_Ahi);
    cudaGetSymbolAddress((void**)&Alo, g_Alo);

    cudaFuncSetAttribute(gemm_qkv_kernel,
                         cudaFuncAttributeMaxDynamicSharedMemorySize, QKV_SMEM);
    cudaFuncSetAttribute(gemm_o_kernel,
                         cudaFuncAttributeMaxDynamicSharedMemorySize, GEMM_SMEM);
    cudaFuncSetAttribute(attn_tc_kernel,
                         cudaFuncAttributeMaxDynamicSharedMemorySize, ATTN_SMEM);

    const int nX4 = MTOT * DIM / 4;
    const int nW4 = DIM * DIM / 4;
    const size_t WSZ = (size_t)DIM * DIM;

    splitX_hi_kernel<<<nX4 / 256, 256>>>(x, Xhi, nX4);
    splitW_kernel<<<dim3(nW4 / 256, 4), 256>>>(Wq, Wk, Wv, Wo, Whi, Wlo, nW4);

    // Fused QKV projection (single product, plain fp16 outputs)
    gemm_qkv_kernel<<<dim3(MTOT / QTM, 48), 256, QKV_SMEM>>>(
        Xhi, Whi, bq, bk, bv, Qh, Kh, Vh);

    // Attention (plain fp16 Q/K/V)
    dim3 agrid(SEQ / 128, HEADS, BATCH);
    attn_tc_kernel<<<agrid, 256, ATTN_SMEM>>>(Qh, Kh, Vh, Ahi, Alo);

    // Output projection (full 3-product accuracy)
    gemm_o_kernel<<<dim3(MTOT / TM, DIM / 128), 256, GEMM_SMEM>>>(
        Ahi, Alo, Whi + 3 * WSZ, Wlo + 3 * WSZ, bo, out);
}

// round 8
// speedup vs baseline: 7.8389x; 1.1483x over previous
#include <cuda_runtime.h>
#include <cuda_fp16.h>
#include <math.h>
#include <stdint.h>

// Problem constants
#define BATCH 2
#define SEQ   2048
#define DIM   2048
#define HEADS 16
#define DHEAD 128
#define MTOT  (BATCH * SEQ)   // 4096

// ---------------------------------------------------------------------------
// Scratch (allocation-free rule: __device__ globals)
// ---------------------------------------------------------------------------
__device__ __half g_Xhi[MTOT * DIM];
__device__ __half g_Whi[4][DIM * DIM];
__device__ __half g_Wlo[4][DIM * DIM];   // only [3] (Wo) populated
__device__ __half g_Qh [MTOT * DIM];
__device__ __half g_Kh [MTOT * DIM];
__device__ __half g_Vh [MTOT * DIM];
__device__ __half g_Ah [MTOT * DIM];

// ---------------------------------------------------------------------------
// PTX helpers
// ---------------------------------------------------------------------------
__device__ __forceinline__ uint32_t smem_u32(const void* p) {
    uint32_t a;
    asm("{ .reg .u64 t; cvta.to.shared.u64 t, %1; cvt.u32.u64 %0, t; }" : "=r"(a) : "l"(p));
    return a;
}

#define CP_ASYNC_16(dst_u32, src_ptr) \
    asm volatile("cp.async.cg.shared.global [%0], [%1], 16;" \
                 :: "r"(dst_u32), "l"(src_ptr) : "memory")
#define CP_ASYNC_COMMIT() asm volatile("cp.async.commit_group;" ::: "memory")
#define CP_ASYNC_WAIT_1() asm volatile("cp.async.wait_group 1;" ::: "memory")
#define CP_ASYNC_WAIT_2() asm volatile("cp.async.wait_group 2;" ::: "memory")

__device__ __forceinline__ void ldmatrix_x4(uint32_t* r, uint32_t addr) {
    asm volatile("ldmatrix.sync.aligned.m8n8.x4.shared.b16 {%0,%1,%2,%3}, [%4];"
        : "=r"(r[0]), "=r"(r[1]), "=r"(r[2]), "=r"(r[3]) : "r"(addr));
}
__device__ __forceinline__ void ldmatrix_x4_trans(uint32_t* r, uint32_t addr) {
    asm volatile("ldmatrix.sync.aligned.m8n8.x4.trans.shared.b16 {%0,%1,%2,%3}, [%4];"
        : "=r"(r[0]), "=r"(r[1]), "=r"(r[2]), "=r"(r[3]) : "r"(addr));
}

__device__ __forceinline__ void mma16816(float* d, const uint32_t* a, const uint32_t* b) {
    asm volatile(
        "mma.sync.aligned.m16n8k16.row.col.f32.f16.f16.f32 "
        "{%0,%1,%2,%3}, {%4,%5,%6,%7}, {%8,%9}, {%0,%1,%2,%3};"
        : "+f"(d[0]), "+f"(d[1]), "+f"(d[2]), "+f"(d[3])
        : "r"(a[0]), "r"(a[1]), "r"(a[2]), "r"(a[3]), "r"(b[0]), "r"(b[1]));
}

#define SWZ(x) ((x) ^ (((x) >> 3) & 0x70))

// ---------------------------------------------------------------------------
// Splits
// ---------------------------------------------------------------------------
__global__ __launch_bounds__(256) void splitX_hi_kernel(
    const float* __restrict__ in, __half* __restrict__ hi, int n4)
{
    int i = blockIdx.x * 256 + threadIdx.x;
    if (i >= n4) return;
    float4 v = ((const float4*)in)[i];
    ((__half2*)hi)[2 * i]     = __floats2half2_rn(v.x, v.y);
    ((__half2*)hi)[2 * i + 1] = __floats2half2_rn(v.z, v.w);
}

__global__ __launch_bounds__(256) void splitW_kernel(
    const float* __restrict__ w0, const float* __restrict__ w1,
    const float* __restrict__ w2, const float* __restrict__ w3,
    __half* __restrict__ WhiAll, __half* __restrict__ WloAll, int n4)
{
    int i = blockIdx.x * 256 + threadIdx.x;
    if (i >= n4) return;
    int wsel = blockIdx.y;
    const float* in = (wsel == 0) ? w0 : (wsel == 1) ? w1 : (wsel == 2) ? w2 : w3;
    __half* hi = WhiAll + (size_t)wsel * DIM * DIM;
    float4 v = ((const float4*)in)[i];
    __half hx = __float2half_rn(v.x), hy = __float2half_rn(v.y);
    __half hz = __float2half_rn(v.z), hw = __float2half_rn(v.w);
    ((__half2*)hi)[2 * i]     = __halves2half2(hx, hy);
    ((__half2*)hi)[2 * i + 1] = __halves2half2(hz, hw);
    if (wsel == 3) {   // only Wo needs the lo plane (O-proj 2-product uses it)
        __half* lo = WloAll + (size_t)wsel * DIM * DIM;
        __half lx = __float2half_rn(v.x - __half2float(hx));
        __half ly = __float2half_rn(v.y - __half2float(hy));
        __half lz = __float2half_rn(v.z - __half2float(hz));
        __half lw = __float2half_rn(v.w - __half2float(hw));
        ((__half2*)lo)[2 * i]     = __halves2half2(lx, ly);
        ((__half2*)lo)[2 * i + 1] = __halves2half2(lz, lw);
    }
}

// ---------------------------------------------------------------------------
// Shared GEMM geometry: CTA 256x128, 8 warps (4m x 2n), warp 64x64, 4 stages.
// Stage layout: A 32KB | Bh 16KB | Bl 16KB (Bl unused by QKV... QKV uses
// single B; O-proj uses hi+lo).  Two kernels below share loader shapes.
// ---------------------------------------------------------------------------
#define TKC 64
#define NCHUNK (DIM / TKC)
#define QTM 256
#define QS_A  0
#define QS_B  32768
#define QSTAGE 49152
#define QKV_SMEM (4 * QSTAGE)   // 196608

__device__ __forceinline__ void load_stage_qkv(
    uint32_t sb, const __half* __restrict__ Xh, const __half* __restrict__ Bh,
    int m0, int n0, int k0, int tid)
{
    #pragma unroll
    for (int it = 0; it < 8; it++) {
        int t = tid + it * 256;            // 0..2047
        int row = t >> 3;                  // 0..255
        int kk = (t & 7) * 8;
        uint32_t soff = SWZ((uint32_t)(row * 128 + kk * 2));
        CP_ASYNC_16(sb + QS_A + soff, Xh + (size_t)(m0 + row) * DIM + k0 + kk);
    }
    #pragma unroll
    for (int it = 0; it < 4; it++) {
        int t = tid + it * 256;            // 0..1023
        int row = t >> 3;                  // 0..127
        int kk = (t & 7) * 8;
        uint32_t soff = SWZ((uint32_t)(row * 128 + kk * 2));
        CP_ASYNC_16(sb + QS_B + soff, Bh + (size_t)(n0 + row) * DIM + k0 + kk);
    }
}

// ---------------------------------------------------------------------------
// Fused QKV GEMM (single product): Y = Xhi @ Whi^T + bias -> plain fp16
// Grid (16, 48): y/16 selects Q/K/V output, y%16 selects n-block.
// ---------------------------------------------------------------------------
__global__ __launch_bounds__(256, 1) void gemm_qkv_kernel(
    const __half* __restrict__ Xh, const __half* __restrict__ WhiAll,
    const float* __restrict__ bq, const float* __restrict__ bk,
    const float* __restrict__ bv,
    __half* __restrict__ Qh, __half* __restrict__ Kh, __half* __restrict__ Vh)
{
    extern __shared__ char smem[];
    const uint32_t smem_base = smem_u32(smem);
    const int tid = threadIdx.x;
    const int wid = tid >> 5;
    const int lane = tid & 31;
    const int warp_m = wid & 3;
    const int warp_n = wid >> 2;
    const int m0 = blockIdx.x * QTM;
    const int out = blockIdx.y >> 4;   // 0=Q 1=K 2=V
    const int n0 = (blockIdx.y & 15) * 128;

    const __half* Bh = WhiAll + (size_t)out * DIM * DIM;
    const float* bias = (out == 0) ? bq : (out == 1) ? bk : bv;
    __half* Yp = (out == 0) ? Qh : (out == 1) ? Kh : Vh;

    float acc[4][8][4];
    #pragma unroll
    for (int mi = 0; mi < 4; mi++)
        #pragma unroll
        for (int ni = 0; ni < 8; ni++)
            #pragma unroll
            for (int r = 0; r < 4; r++) acc[mi][ni][r] = 0.f;

    load_stage_qkv(smem_base,              Xh, Bh, m0, n0, 0 * TKC, tid);
    CP_ASYNC_COMMIT();
    load_stage_qkv(smem_base + QSTAGE,     Xh, Bh, m0, n0, 1 * TKC, tid);
    CP_ASYNC_COMMIT();
    load_stage_qkv(smem_base + 2 * QSTAGE, Xh, Bh, m0, n0, 2 * TKC, tid);
    CP_ASYNC_COMMIT();

    const int a_row = (lane & 15);
    const int a_kb  = (lane >> 4) << 4;
    const int b_row = ((lane >> 4) << 3) + (lane & 7);
    const int b_kb  = ((lane >> 3) & 1) << 4;

    int slot = 0;
    for (int c = 0; c < NCHUNK; c++) {
        CP_ASYNC_WAIT_2();
        __syncthreads();

        if (c + 3 < NCHUNK) {
            int s2 = (slot + 3) & 3;
            load_stage_qkv(smem_base + s2 * QSTAGE, Xh, Bh, m0, n0, (c + 3) * TKC, tid);
        }
        CP_ASYNC_COMMIT();

        const uint32_t sb = smem_base + slot * QSTAGE;
        #pragma unroll
        for (int ks = 0; ks < 4; ks++) {
            const int kbyte = ks * 32;
            uint32_t b_h[4][4];
            #pragma unroll
            for (int pi = 0; pi < 4; pi++) {
                uint32_t off = SWZ((uint32_t)((warp_n * 64 + pi * 16 + b_row) * 128 + kbyte + b_kb));
                ldmatrix_x4(b_h[pi], sb + QS_B + off);
            }
            #pragma unroll
            for (int mi = 0; mi < 4; mi++) {
                uint32_t a_h[4];
                uint32_t aoff = SWZ((uint32_t)((warp_m * 64 + mi * 16 + a_row) * 128 + kbyte + a_kb));
                ldmatrix_x4(a_h, sb + QS_A + aoff);
                #pragma unroll
                for (int ni = 0; ni < 8; ni++)
                    mma16816(acc[mi][ni], a_h, &b_h[ni >> 1][(ni & 1) * 2]);
            }
        }
        slot = (slot + 1) & 3;
    }

    const int gm0 = m0 + warp_m * 64;
    const int gn0 = n0 + warp_n * 64;
    #pragma unroll
    for (int mi = 0; mi < 4; mi++) {
        int row = gm0 + mi * 16 + (lane >> 2);
        #pragma unroll
        for (int ni = 0; ni < 8; ni++) {
            int col = gn0 + ni * 8 + 2 * (lane & 3);
            float2 b2 = *(const float2*)&bias[col];
            *(__half2*)&Yp[(size_t)row * DIM + col] =
                __floats2half2_rn(acc[mi][ni][0] + b2.x, acc[mi][ni][1] + b2.y);
            *(__half2*)&Yp[(size_t)(row + 8) * DIM + col] =
                __floats2half2_rn(acc[mi][ni][2] + b2.x, acc[mi][ni][3] + b2.y);
        }
    }
}

// ---------------------------------------------------------------------------
// O-projection GEMM (2-product): out = Ah @ (Whi + Wlo)^T + bias, fp32
// CTA 256x128, 8 warps, 3-stage ring of 64KB (A 32K | Bh 16K | Bl 16K).
// ---------------------------------------------------------------------------
#define OS_A  0
#define OS_BH 32768
#define OS_BL 49152
#define OSTAGE 65536
#define O_SMEM (3 * OSTAGE)   // 196608

__device__ __forceinline__ void load_stage_o(
    uint32_t sb, const __half* __restrict__ Ah,
    const __half* __restrict__ Bhi, const __half* __restrict__ Blo,
    int m0, int n0, int k0, int tid)
{
    #pragma unroll
    for (int it = 0; it < 8; it++) {
        int t = tid + it * 256;            // 0..2047
        int row = t >> 3;                  // 0..255
        int kk = (t & 7) * 8;
        uint32_t soff = SWZ((uint32_t)(row * 128 + kk * 2));
        CP_ASYNC_16(sb + OS_A + soff, Ah + (size_t)(m0 + row) * DIM + k0 + kk);
    }
    #pragma unroll
    for (int it = 0; it < 8; it++) {
        int t = tid + it * 256;            // 0..2047
        int hil = t >> 10;                 // 0: hi, 1: lo
        int row = (t >> 3) & 127;
        int kk = (t & 7) * 8;
        uint32_t soff = SWZ((uint32_t)(row * 128 + kk * 2));
        const __half* src = (hil ? Blo : Bhi) + (size_t)(n0 + row) * DIM + k0 + kk;
        CP_ASYNC_16(sb + (hil ? OS_BL : OS_BH) + soff, src);
    }
}

__global__ __launch_bounds__(256, 1) void gemm_o_kernel(
    const __half* __restrict__ Ah,
    const __half* __restrict__ Bhi, const __half* __restrict__ Blo,
    const float* __restrict__ bias, float* __restrict__ Yf)
{
    extern __shared__ char smem[];
    const uint32_t smem_base = smem_u32(smem);
    const int tid = threadIdx.x;
    const int wid = tid >> 5;
    const int lane = tid & 31;
    const int warp_m = wid & 3;
    const int warp_n = wid >> 2;
    const int m0 = blockIdx.x * QTM;
    const int n0 = blockIdx.y * 128;

    float acc[4][8][4];
    #pragma unroll
    for (int mi = 0; mi < 4; mi++)
        #pragma unroll
        for (int ni = 0; ni < 8; ni++)
            #pragma unroll
            for (int r = 0; r < 4; r++) acc[mi][ni][r] = 0.f;

    load_stage_o(smem_base,          Ah, Bhi, Blo, m0, n0, 0 * TKC, tid);
    CP_ASYNC_COMMIT();
    load_stage_o(smem_base + OSTAGE, Ah, Bhi, Blo, m0, n0, 1 * TKC, tid);
    CP_ASYNC_COMMIT();

    const int a_row = (lane & 15);
    const int a_kb  = (lane >> 4) << 4;
    const int b_row = ((lane >> 4) << 3) + (lane & 7);
    const int b_kb  = ((lane >> 3) & 1) << 4;

    int slot = 0;
    for (int c = 0; c < NCHUNK; c++) {
        CP_ASYNC_WAIT_1();
        __syncthreads();

        if (c + 2 < NCHUNK) {
            int s2 = slot + 2; if (s2 >= 3) s2 -= 3;
            load_stage_o(smem_base + s2 * OSTAGE, Ah, Bhi, Blo,
                         m0, n0, (c + 2) * TKC, tid);
        }
        CP_ASYNC_COMMIT();

        const uint32_t sb = smem_base + slot * OSTAGE;
        #pragma unroll
        for (int ks = 0; ks < 4; ks++) {
            const int kbyte = ks * 32;
            uint32_t b_h[4][4], b_l[4][4];
            #pragma unroll
            for (int pi = 0; pi < 4; pi++) {
                uint32_t off = SWZ((uint32_t)((warp_n * 64 + pi * 16 + b_row) * 128 + kbyte + b_kb));
                ldmatrix_x4(b_h[pi], sb + OS_BH + off);
                ldmatrix_x4(b_l[pi], sb + OS_BL + off);
            }
            #pragma unroll
            for (int mi = 0; mi < 4; mi++) {
                uint32_t a_h[4];
                uint32_t aoff = SWZ((uint32_t)((warp_m * 64 + mi * 16 + a_row) * 128 + kbyte + a_kb));
                ldmatrix_x4(a_h, sb + OS_A + aoff);
                #pragma unroll
                for (int ni = 0; ni < 8; ni++) {
                    mma16816(acc[mi][ni], a_h, &b_h[ni >> 1][(ni & 1) * 2]);
                    mma16816(acc[mi][ni], a_h, &b_l[ni >> 1][(ni & 1) * 2]);
                }
            }
        }
        slot++; if (slot >= 3) slot = 0;
    }

    const int gm0 = m0 + warp_m * 64;
    const int gn0 = n0 + warp_n * 64;
    #pragma unroll
    for (int mi = 0; mi < 4; mi++) {
        int row = gm0 + mi * 16 + (lane >> 2);
        #pragma unroll
        for (int ni = 0; ni < 8; ni++) {
            int col = gn0 + ni * 8 + 2 * (lane & 3);
            float2 b2 = *(const float2*)&bias[col];
            *(float2*)&Yf[(size_t)row * DIM + col] =
                make_float2(acc[mi][ni][0] + b2.x, acc[mi][ni][1] + b2.y);
            *(float2*)&Yf[(size_t)(row + 8) * DIM + col] =
                make_float2(acc[mi][ni][2] + b2.x, acc[mi][ni][3] + b2.y);
        }
    }
}

// ---------------------------------------------------------------------------
// Tensor-core causal flash attention. Q, K, V plain fp16; 1 product per GEMM.
// Output: plain fp16 A. Smem: Q 32KB | K 2st x 16KB | V 2st x 16KB = 96KB.
// ---------------------------------------------------------------------------
#define SM_Qb 0
#define SM_Kb 32768
#define SM_Vb 65536
#define ATTN_SMEM 98304
#define KSC 0.12751741219860918f   /* (1/sqrt(128)) * log2(e) */

__device__ __forceinline__ void attn_load_kv(
    uint32_t sb, const __half* __restrict__ Kh, const __half* __restrict__ Vh,
    size_t gbase, int k0, int stage, int tid)
{
    #pragma unroll
    for (int i = 0; i < 8; i++) {
        int t = tid + i * 256;            // 0..2047
        int kv  = t >> 10;                // 0: K, 1: V
        int row = (t >> 4) & 63;
        int ch  = t & 15;
        int pl  = ch >> 3;
        const __half* src = (kv ? Vh : Kh) + gbase + (size_t)(k0 + row) * DIM + ch * 8;
        uint32_t dst = sb + (kv ? SM_Vb : SM_Kb) + stage * 16384
                     + pl * 8192 + SWZ((uint32_t)(row * 128 + (ch & 7) * 16));
        CP_ASYNC_16(dst, src);
    }
}

__global__ __launch_bounds__(256, 1) void attn_tc_kernel(
    const __half* __restrict__ Qh, const __half* __restrict__ Kh,
    const __half* __restrict__ Vh, __half* __restrict__ Ah)
{
    extern __shared__ char smem[];
    const uint32_t sb = smem_u32(smem);
    const int tid = threadIdx.x;
    const int w = tid >> 5;
    const int lane = tid & 31;
    const int qt = gridDim.x - 1 - blockIdx.x;   // big tiles first
    const int h = blockIdx.y;
    const int b = blockIdx.z;
    const int q0 = qt * 128;
    const size_t gbase = (size_t)b * SEQ * DIM + (size_t)h * DHEAD;

    // Load Q tile
    #pragma unroll
    for (int i = 0; i < 8; i++) {
        int t = tid + i * 256;
        int row = (t >> 4) & 127;
        int ch  = t & 15;
        int pl  = ch >> 3;
        const __half* src = Qh + gbase + (size_t)(q0 + row) * DIM + ch * 8;
        uint32_t dst = sb + SM_Qb + pl * 16384
                     + SWZ((uint32_t)(row * 128 + (ch & 7) * 16));
        CP_ASYNC_16(dst, src);
    }
    attn_load_kv(sb, Kh, Vh, gbase, 0, 0, tid);
    CP_ASYNC_COMMIT();

    float m0v = -1e30f, m1v = -1e30f, l0v = 0.f, l1v = 0.f;
    float acc_o[16][4];
    #pragma unroll
    for (int n = 0; n < 16; n++)
        #pragma unroll
        for (int r = 0; r < 4; r++) acc_o[n][r] = 0.f;

    const int a_row = lane & 15;
    const int a_kb  = (lane >> 4) << 4;
    const int b_row = ((lane >> 4) << 3) + (lane & 7);
    const int b_kb  = ((lane >> 3) & 1) << 4;
    const int v_row = (lane & 7) + ((lane >> 3) & 1) * 8;
    const int v_cb  = ((lane >> 4) & 1) << 4;

    const int qwmin = q0 + w * 16;
    const int nt = 2 * qt + 2;

    for (int kt = 0; kt < nt; kt++) {
        __syncthreads();
        if (kt + 1 < nt)
            attn_load_kv(sb, Kh, Vh, gbase, (kt + 1) * 64, (kt + 1) & 1, tid);
        CP_ASYNC_COMMIT();
        CP_ASYNC_WAIT_1();
        __syncthreads();

        const int k0 = kt * 64;
        const int st = kt & 1;
        if (k0 > qwmin + 15) continue;

        // ---- S = Q K^T ----
        float s[8][4];
        #pragma unroll
        for (int ni = 0; ni < 8; ni++)
            #pragma unroll
            for (int r = 0; r < 4; r++) s[ni][r] = 0.f;

        #pragma unroll
        for (int ks = 0; ks < 8; ks++) {
            const int kbyte = (ks & 3) * 32;
            const int pl = ks >> 2;
            uint32_t aH[4];
            uint32_t aoff = SM_Qb + pl * 16384
                          + SWZ((uint32_t)((w * 16 + a_row) * 128 + kbyte + a_kb));
            ldmatrix_x4(aH, sb + aoff);
            #pragma unroll
            for (int pi = 0; pi < 4; pi++) {
                uint32_t bH[4];
                uint32_t boff = SM_Kb + st * 16384 + pl * 8192
                              + SWZ((uint32_t)((pi * 16 + b_row) * 128 + kbyte + b_kb));
                ldmatrix_x4(bH, sb + boff);
                mma16816(s[2 * pi],     aH, &bH[0]);
                mma16816(s[2 * pi + 1], aH, &bH[2]);
            }
        }

        // ---- causal mask ----
        const int qr0 = qwmin + (lane >> 2);
        const int qr1 = qr0 + 8;
        if (k0 + 63 > qwmin) {
            const int kc = k0 + 2 * (lane & 3);
            #pragma unroll
            for (int ni = 0; ni < 8; ni++) {
                int kb2 = kc + ni * 8;
                if (kb2     > qr0) s[ni][0] = -1e30f;
                if (kb2 + 1 > qr0) s[ni][1] = -1e30f;
                if (kb2     > qr1) s[ni][2] = -1e30f;
                if (kb2 + 1 > qr1) s[ni][3] = -1e30f;
            }
        }

        // ---- online softmax ----
        float mx0 = -1e30f, mx1 = -1e30f;
        #pragma unroll
        for (int ni = 0; ni < 8; ni++) {
            mx0 = fmaxf(mx0, fmaxf(s[ni][0], s[ni][1]));
            mx1 = fmaxf(mx1, fmaxf(s[ni][2], s[ni][3]));
        }
        mx0 = fmaxf(mx0, __shfl_xor_sync(0xffffffffu, mx0, 1));
        mx0 = fmaxf(mx0, __shfl_xor_sync(0xffffffffu, mx0, 2));
        mx1 = fmaxf(mx1, __shfl_xor_sync(0xffffffffu, mx1, 1));
        mx1 = fmaxf(mx1, __shfl_xor_sync(0xffffffffu, mx1, 2));
        float mn0 = fmaxf(m0v, mx0), mn1 = fmaxf(m1v, mx1);
        float corr0 = exp2f((m0v - mn0) * KSC);
        float corr1 = exp2f((m1v - mn1) * KSC);
        m0v = mn0; m1v = mn1;

        float rs0 = 0.f, rs1 = 0.f;
        #pragma unroll
        for (int ni = 0; ni < 8; ni++) {
            s[ni][0] = exp2f((s[ni][0] - mn0) * KSC);
            s[ni][1] = exp2f((s[ni][1] - mn0) * KSC);
            s[ni][2] = exp2f((s[ni][2] - mn1) * KSC);
            s[ni][3] = exp2f((s[ni][3] - mn1) * KSC);
            rs0 += s[ni][0] + s[ni][1];
            rs1 += s[ni][2] + s[ni][3];
        }
        rs0 += __shfl_xor_sync(0xffffffffu, rs0, 1);
        rs0 += __shfl_xor_sync(0xffffffffu, rs0, 2);
        rs1 += __shfl_xor_sync(0xffffffffu, rs1, 1);
        rs1 += __shfl_xor_sync(0xffffffffu, rs1, 2);
        l0v = l0v * corr0 + rs0;
        l1v = l1v * corr1 + rs1;

        #pragma unroll
        for (int n = 0; n < 16; n++) {
            acc_o[n][0] *= corr0; acc_o[n][1] *= corr0;
            acc_o[n][2] *= corr1; acc_o[n][3] *= corr1;
        }

        // ---- O += P V ----
        #pragma unroll
        for (int vks = 0; vks < 4; vks++) {
            uint32_t pH[4];
            #pragma unroll
            for (int half16 = 0; half16 < 2; half16++) {
                const float* sp = s[2 * vks + half16];
                __half2 h01 = __floats2half2_rn(sp[0], sp[1]);
                __half2 h23 = __floats2half2_rn(sp[2], sp[3]);
                pH[2 * half16]     = *(uint32_t*)&h01;
                pH[2 * half16 + 1] = *(uint32_t*)&h23;
            }
            const int vr = vks * 16 + v_row;
            #pragma unroll
            for (int nb = 0; nb < 8; nb++) {
                uint32_t vH[4];
                uint32_t voff = SM_Vb + st * 16384 + (nb >> 2) * 8192
                              + SWZ((uint32_t)(vr * 128 + (nb & 3) * 32 + v_cb));
                ldmatrix_x4_trans(vH, sb + voff);
                mma16816(acc_o[2 * nb],     pH, &vH[0]);
                mma16816(acc_o[2 * nb + 1], pH, &vH[2]);
            }
        }
    }

    // ---- normalize, store plain fp16 ----
    const float inv0 = 1.f / l0v;
    const float inv1 = 1.f / l1v;
    const size_t r0o = gbase + (size_t)(q0 + w * 16 + (lane >> 2)) * DIM;
    const size_t r1o = r0o + 8 * DIM;
    #pragma unroll
    for (int n = 0; n < 16; n++) {
        int col = n * 8 + 2 * (lane & 3);
        *(__half2*)&Ah[r0o + col] =
            __floats2half2_rn(acc_o[n][0] * inv0, acc_o[n][1] * inv0);
        *(__half2*)&Ah[r1o + col] =
            __floats2half2_rn(acc_o[n][2] * inv1, acc_o[n][3] * inv1);
    }
}

// ---------------------------------------------------------------------------
extern "C" void kernel_launch(void* const* d_in, const int* in_sizes, int n_in,
                              void* d_out, int out_size)
{
    const float* x  = (const float*)d_in[0];
    const float* Wq = (const float*)d_in[1];
    const float* bq = (const float*)d_in[2];
    const float* Wk = (const float*)d_in[3];
    const float* bk = (const float*)d_in[4];
    const float* Wv = (const float*)d_in[5];
    const float* bv = (const float*)d_in[6];
    const float* Wo = (const float*)d_in[7];
    const float* bo = (const float*)d_in[8];
    float* out = (float*)d_out;

    __half *Xhi, *Whi, *Wlo, *Qh, *Kh, *Vh, *Ah;
    cudaGetSymbolAddress((void**)&Xhi, g_Xhi);
    cudaGetSymbolAddress((void**)&Whi, g_Whi);
    cudaGetSymbolAddress((void**)&Wlo, g_Wlo);
    cudaGetSymbolAddress((void**)&Qh,  g_Qh);
    cudaGetSymbolAddress((void**)&Kh,  g_Kh);
    cudaGetSymbolAddress((void**)&Vh,  g_Vh);
    cudaGetSymbolAddress((void**)&Ah,  g_Ah);

    cudaFuncSetAttribute(gemm_qkv_kernel,
                         cudaFuncAttributeMaxDynamicSharedMemorySize, QKV_SMEM);
    cudaFuncSetAttribute(gemm_o_kernel,
                         cudaFuncAttributeMaxDynamicSharedMemorySize, O_SMEM);
    cudaFuncSetAttribute(attn_tc_kernel,
                         cudaFuncAttributeMaxDynamicSharedMemorySize, ATTN_SMEM);

    const int nX4 = MTOT * DIM / 4;
    const int nW4 = DIM * DIM / 4;
    const size_t WSZ = (size_t)DIM * DIM;

    splitX_hi_kernel<<<nX4 / 256, 256>>>(x, Xhi, nX4);
    splitW_kernel<<<dim3(nW4 / 256, 4), 256>>>(Wq, Wk, Wv, Wo, Whi, Wlo, nW4);

    // Fused QKV projection (single product, plain fp16 outputs)
    gemm_qkv_kernel<<<dim3(MTOT / QTM, 48), 256, QKV_SMEM>>>(
        Xhi, Whi, bq, bk, bv, Qh, Kh, Vh);

    // Attention (plain fp16 Q/K/V -> plain fp16 A)
    dim3 agrid(SEQ / 128, HEADS, BATCH);
    attn_tc_kernel<<<agrid, 256, ATTN_SMEM>>>(Qh, Kh, Vh, Ah);

    // Output projection (2-product: Ah x (Whi + Wlo))
    gemm_o_kernel<<<dim3(MTOT / QTM, DIM / 128), 256, O_SMEM>>>(
        Ah, Whi + 3 * WSZ, Wlo + 3 * WSZ, bo, out);
}

// round 9
// speedup vs baseline: 9.1727x; 1.1702x over previous
#include <cuda_runtime.h>
#include <cuda_fp16.h>
#include <math.h>
#include <stdint.h>

// Problem constants
#define BATCH 2
#define SEQ   2048
#define DIM   2048
#define HEADS 16
#define DHEAD 128
#define MTOT  (BATCH * SEQ)   // 4096

// ---------------------------------------------------------------------------
// Scratch (allocation-free rule: __device__ globals)
// ---------------------------------------------------------------------------
__device__ __half g_Xhi[MTOT * DIM];
__device__ __half g_Whi[4][DIM * DIM];
__device__ __half g_Qh [MTOT * DIM];
__device__ __half g_Kh [MTOT * DIM];
__device__ __half g_Vh [MTOT * DIM];
__device__ __half g_Ah [MTOT * DIM];

// ---------------------------------------------------------------------------
// PTX helpers
// ---------------------------------------------------------------------------
__device__ __forceinline__ uint32_t smem_u32(const void* p) {
    uint32_t a;
    asm("{ .reg .u64 t; cvta.to.shared.u64 t, %1; cvt.u32.u64 %0, t; }" : "=r"(a) : "l"(p));
    return a;
}

#define CP_ASYNC_16(dst_u32, src_ptr) \
    asm volatile("cp.async.cg.shared.global [%0], [%1], 16;" \
                 :: "r"(dst_u32), "l"(src_ptr) : "memory")
#define CP_ASYNC_COMMIT() asm volatile("cp.async.commit_group;" ::: "memory")
#define CP_ASYNC_WAIT_1() asm volatile("cp.async.wait_group 1;" ::: "memory")
#define CP_ASYNC_WAIT_2() asm volatile("cp.async.wait_group 2;" ::: "memory")

__device__ __forceinline__ void ldmatrix_x4(uint32_t* r, uint32_t addr) {
    asm volatile("ldmatrix.sync.aligned.m8n8.x4.shared.b16 {%0,%1,%2,%3}, [%4];"
        : "=r"(r[0]), "=r"(r[1]), "=r"(r[2]), "=r"(r[3]) : "r"(addr));
}
__device__ __forceinline__ void ldmatrix_x4_trans(uint32_t* r, uint32_t addr) {
    asm volatile("ldmatrix.sync.aligned.m8n8.x4.trans.shared.b16 {%0,%1,%2,%3}, [%4];"
        : "=r"(r[0]), "=r"(r[1]), "=r"(r[2]), "=r"(r[3]) : "r"(addr));
}

__device__ __forceinline__ void mma16816(float* d, const uint32_t* a, const uint32_t* b) {
    asm volatile(
        "mma.sync.aligned.m16n8k16.row.col.f32.f16.f16.f32 "
        "{%0,%1,%2,%3}, {%4,%5,%6,%7}, {%8,%9}, {%0,%1,%2,%3};"
        : "+f"(d[0]), "+f"(d[1]), "+f"(d[2]), "+f"(d[3])
        : "r"(a[0]), "r"(a[1]), "r"(a[2]), "r"(a[3]), "r"(b[0]), "r"(b[1]));
}

#define SWZ(x) ((x) ^ (((x) >> 3) & 0x70))

// ---------------------------------------------------------------------------
// Splits (all plain fp16 now)
// ---------------------------------------------------------------------------
__global__ __launch_bounds__(256) void splitX_hi_kernel(
    const float* __restrict__ in, __half* __restrict__ hi, int n4)
{
    int i = blockIdx.x * 256 + threadIdx.x;
    if (i >= n4) return;
    float4 v = ((const float4*)in)[i];
    ((__half2*)hi)[2 * i]     = __floats2half2_rn(v.x, v.y);
    ((__half2*)hi)[2 * i + 1] = __floats2half2_rn(v.z, v.w);
}

__global__ __launch_bounds__(256) void splitW_kernel(
    const float* __restrict__ w0, const float* __restrict__ w1,
    const float* __restrict__ w2, const float* __restrict__ w3,
    __half* __restrict__ WhiAll, int n4)
{
    int i = blockIdx.x * 256 + threadIdx.x;
    if (i >= n4) return;
    int wsel = blockIdx.y;
    const float* in = (wsel == 0) ? w0 : (wsel == 1) ? w1 : (wsel == 2) ? w2 : w3;
    __half* hi = WhiAll + (size_t)wsel * DIM * DIM;
    float4 v = ((const float4*)in)[i];
    ((__half2*)hi)[2 * i]     = __floats2half2_rn(v.x, v.y);
    ((__half2*)hi)[2 * i + 1] = __floats2half2_rn(v.z, v.w);
}

// ---------------------------------------------------------------------------
// Shared single-product GEMM geometry:
// CTA 256x128, 8 warps (4m x 2n), warp 64x64, K chunk 64, 4-stage 48KB ring.
// ---------------------------------------------------------------------------
#define TKC 64
#define NCHUNK (DIM / TKC)
#define QTM 256
#define QS_A  0
#define QS_B  32768
#define QSTAGE 49152
#define GEMM_SMEM (4 * QSTAGE)   // 196608

__device__ __forceinline__ void load_stage_g(
    uint32_t sb, const __half* __restrict__ Ap, const __half* __restrict__ Bp,
    int m0, int n0, int k0, int tid)
{
    #pragma unroll
    for (int it = 0; it < 8; it++) {
        int t = tid + it * 256;            // 0..2047
        int row = t >> 3;                  // 0..255
        int kk = (t & 7) * 8;
        uint32_t soff = SWZ((uint32_t)(row * 128 + kk * 2));
        CP_ASYNC_16(sb + QS_A + soff, Ap + (size_t)(m0 + row) * DIM + k0 + kk);
    }
    #pragma unroll
    for (int it = 0; it < 4; it++) {
        int t = tid + it * 256;            // 0..1023
        int row = t >> 3;                  // 0..127
        int kk = (t & 7) * 8;
        uint32_t soff = SWZ((uint32_t)(row * 128 + kk * 2));
        CP_ASYNC_16(sb + QS_B + soff, Bp + (size_t)(n0 + row) * DIM + k0 + kk);
    }
}

// ---------------------------------------------------------------------------
// Fused QKV GEMM (single product): Y = Xhi @ Whi^T + bias -> plain fp16
// Grid (16, 48): y/16 selects Q/K/V output, y%16 selects n-block.
// ---------------------------------------------------------------------------
__global__ __launch_bounds__(256, 1) void gemm_qkv_kernel(
    const __half* __restrict__ Xh, const __half* __restrict__ WhiAll,
    const float* __restrict__ bq, const float* __restrict__ bk,
    const float* __restrict__ bv,
    __half* __restrict__ Qh, __half* __restrict__ Kh, __half* __restrict__ Vh)
{
    extern __shared__ char smem[];
    const uint32_t smem_base = smem_u32(smem);
    const int tid = threadIdx.x;
    const int wid = tid >> 5;
    const int lane = tid & 31;
    const int warp_m = wid & 3;
    const int warp_n = wid >> 2;
    const int m0 = blockIdx.x * QTM;
    const int out = blockIdx.y >> 4;   // 0=Q 1=K 2=V
    const int n0 = (blockIdx.y & 15) * 128;

    const __half* Bh = WhiAll + (size_t)out * DIM * DIM;
    const float* bias = (out == 0) ? bq : (out == 1) ? bk : bv;
    __half* Yp = (out == 0) ? Qh : (out == 1) ? Kh : Vh;

    float acc[4][8][4];
    #pragma unroll
    for (int mi = 0; mi < 4; mi++)
        #pragma unroll
        for (int ni = 0; ni < 8; ni++)
            #pragma unroll
            for (int r = 0; r < 4; r++) acc[mi][ni][r] = 0.f;

    load_stage_g(smem_base,              Xh, Bh, m0, n0, 0 * TKC, tid);
    CP_ASYNC_COMMIT();
    load_stage_g(smem_base + QSTAGE,     Xh, Bh, m0, n0, 1 * TKC, tid);
    CP_ASYNC_COMMIT();
    load_stage_g(smem_base + 2 * QSTAGE, Xh, Bh, m0, n0, 2 * TKC, tid);
    CP_ASYNC_COMMIT();

    const int a_row = (lane & 15);
    const int a_kb  = (lane >> 4) << 4;
    const int b_row = ((lane >> 4) << 3) + (lane & 7);
    const int b_kb  = ((lane >> 3) & 1) << 4;

    int slot = 0;
    for (int c = 0; c < NCHUNK; c++) {
        CP_ASYNC_WAIT_2();
        __syncthreads();

        if (c + 3 < NCHUNK) {
            int s2 = (slot + 3) & 3;
            load_stage_g(smem_base + s2 * QSTAGE, Xh, Bh, m0, n0, (c + 3) * TKC, tid);
        }
        CP_ASYNC_COMMIT();

        const uint32_t sb = smem_base + slot * QSTAGE;
        #pragma unroll
        for (int ks = 0; ks < 4; ks++) {
            const int kbyte = ks * 32;
            uint32_t b_h[4][4];
            #pragma unroll
            for (int pi = 0; pi < 4; pi++) {
                uint32_t off = SWZ((uint32_t)((warp_n * 64 + pi * 16 + b_row) * 128 + kbyte + b_kb));
                ldmatrix_x4(b_h[pi], sb + QS_B + off);
            }
            #pragma unroll
            for (int mi = 0; mi < 4; mi++) {
                uint32_t a_h[4];
                uint32_t aoff = SWZ((uint32_t)((warp_m * 64 + mi * 16 + a_row) * 128 + kbyte + a_kb));
                ldmatrix_x4(a_h, sb + QS_A + aoff);
                #pragma unroll
                for (int ni = 0; ni < 8; ni++)
                    mma16816(acc[mi][ni], a_h, &b_h[ni >> 1][(ni & 1) * 2]);
            }
        }
        slot = (slot + 1) & 3;
    }

    const int gm0 = m0 + warp_m * 64;
    const int gn0 = n0 + warp_n * 64;
    #pragma unroll
    for (int mi = 0; mi < 4; mi++) {
        int row = gm0 + mi * 16 + (lane >> 2);
        #pragma unroll
        for (int ni = 0; ni < 8; ni++) {
            int col = gn0 + ni * 8 + 2 * (lane & 3);
            float2 b2 = *(const float2*)&bias[col];
            *(__half2*)&Yp[(size_t)row * DIM + col] =
                __floats2half2_rn(acc[mi][ni][0] + b2.x, acc[mi][ni][1] + b2.y);
            *(__half2*)&Yp[(size_t)(row + 8) * DIM + col] =
                __floats2half2_rn(acc[mi][ni][2] + b2.x, acc[mi][ni][3] + b2.y);
        }
    }
}

// ---------------------------------------------------------------------------
// O-projection GEMM (single product): out = Ah @ Who^T + bias, fp32 output
// Same geometry as QKV kernel. Grid (16, 16).
// ---------------------------------------------------------------------------
__global__ __launch_bounds__(256, 1) void gemm_o_kernel(
    const __half* __restrict__ Ah, const __half* __restrict__ Bh,
    const float* __restrict__ bias, float* __restrict__ Yf)
{
    extern __shared__ char smem[];
    const uint32_t smem_base = smem_u32(smem);
    const int tid = threadIdx.x;
    const int wid = tid >> 5;
    const int lane = tid & 31;
    const int warp_m = wid & 3;
    const int warp_n = wid >> 2;
    const int m0 = blockIdx.x * QTM;
    const int n0 = blockIdx.y * 128;

    float acc[4][8][4];
    #pragma unroll
    for (int mi = 0; mi < 4; mi++)
        #pragma unroll
        for (int ni = 0; ni < 8; ni++)
            #pragma unroll
            for (int r = 0; r < 4; r++) acc[mi][ni][r] = 0.f;

    load_stage_g(smem_base,              Ah, Bh, m0, n0, 0 * TKC, tid);
    CP_ASYNC_COMMIT();
    load_stage_g(smem_base + QSTAGE,     Ah, Bh, m0, n0, 1 * TKC, tid);
    CP_ASYNC_COMMIT();
    load_stage_g(smem_base + 2 * QSTAGE, Ah, Bh, m0, n0, 2 * TKC, tid);
    CP_ASYNC_COMMIT();

    const int a_row = (lane & 15);
    const int a_kb  = (lane >> 4) << 4;
    const int b_row = ((lane >> 4) << 3) + (lane & 7);
    const int b_kb  = ((lane >> 3) & 1) << 4;

    int slot = 0;
    for (int c = 0; c < NCHUNK; c++) {
        CP_ASYNC_WAIT_2();
        __syncthreads();

        if (c + 3 < NCHUNK) {
            int s2 = (slot + 3) & 3;
            load_stage_g(smem_base + s2 * QSTAGE, Ah, Bh, m0, n0, (c + 3) * TKC, tid);
        }
        CP_ASYNC_COMMIT();

        const uint32_t sb = smem_base + slot * QSTAGE;
        #pragma unroll
        for (int ks = 0; ks < 4; ks++) {
            const int kbyte = ks * 32;
            uint32_t b_h[4][4];
            #pragma unroll
            for (int pi = 0; pi < 4; pi++) {
                uint32_t off = SWZ((uint32_t)((warp_n * 64 + pi * 16 + b_row) * 128 + kbyte + b_kb));
                ldmatrix_x4(b_h[pi], sb + QS_B + off);
            }
            #pragma unroll
            for (int mi = 0; mi < 4; mi++) {
                uint32_t a_h[4];
                uint32_t aoff = SWZ((uint32_t)((warp_m * 64 + mi * 16 + a_row) * 128 + kbyte + a_kb));
                ldmatrix_x4(a_h, sb + QS_A + aoff);
                #pragma unroll
                for (int ni = 0; ni < 8; ni++)
                    mma16816(acc[mi][ni], a_h, &b_h[ni >> 1][(ni & 1) * 2]);
            }
        }
        slot = (slot + 1) & 3;
    }

    const int gm0 = m0 + warp_m * 64;
    const int gn0 = n0 + warp_n * 64;
    #pragma unroll
    for (int mi = 0; mi < 4; mi++) {
        int row = gm0 + mi * 16 + (lane >> 2);
        #pragma unroll
        for (int ni = 0; ni < 8; ni++) {
            int col = gn0 + ni * 8 + 2 * (lane & 3);
            float2 b2 = *(const float2*)&bias[col];
            *(float2*)&Yf[(size_t)row * DIM + col] =
                make_float2(acc[mi][ni][0] + b2.x, acc[mi][ni][1] + b2.y);
            *(float2*)&Yf[(size_t)(row + 8) * DIM + col] =
                make_float2(acc[mi][ni][2] + b2.x, acc[mi][ni][3] + b2.y);
        }
    }
}

// ---------------------------------------------------------------------------
// Tensor-core causal flash attention, 2 CTAs/SM.
// CTA: 128 threads (4 warps x 16 q-rows = 64 queries), key tiles of 64.
// Smem: Q 16KB | K 2st x 16KB | V 2st x 16KB = 80KB.
// ---------------------------------------------------------------------------
#define SM_Qb 0
#define SM_Kb 16384
#define SM_Vb 49152
#define ATTN_SMEM 81920
#define KSC 0.12751741219860918f   /* (1/sqrt(128)) * log2(e) */

__device__ __forceinline__ void attn_load_kv(
    uint32_t sb, const __half* __restrict__ Kh, const __half* __restrict__ Vh,
    size_t gbase, int k0, int stage, int tid)
{
    #pragma unroll
    for (int i = 0; i < 16; i++) {
        int t = tid + i * 128;            // 0..2047
        int kv  = t >> 10;                // 0: K, 1: V
        int row = (t >> 4) & 63;
        int ch  = t & 15;
        int pl  = ch >> 3;
        const __half* src = (kv ? Vh : Kh) + gbase + (size_t)(k0 + row) * DIM + ch * 8;
        uint32_t dst = sb + (kv ? SM_Vb : SM_Kb) + stage * 16384
                     + pl * 8192 + SWZ((uint32_t)(row * 128 + (ch & 7) * 16));
        CP_ASYNC_16(dst, src);
    }
}

__global__ __launch_bounds__(128, 2) void attn_tc_kernel(
    const __half* __restrict__ Qh, const __half* __restrict__ Kh,
    const __half* __restrict__ Vh, __half* __restrict__ Ah)
{
    extern __shared__ char smem[];
    const uint32_t sb = smem_u32(smem);
    const int tid = threadIdx.x;
    const int w = tid >> 5;              // 0..3
    const int lane = tid & 31;
    const int qt = gridDim.x - 1 - blockIdx.x;   // big tiles first
    const int h = blockIdx.y;
    const int b = blockIdx.z;
    const int q0 = qt * 64;
    const size_t gbase = (size_t)b * SEQ * DIM + (size_t)h * DHEAD;

    // Load Q tile (64 rows)
    #pragma unroll
    for (int i = 0; i < 8; i++) {
        int t = tid + i * 128;            // 0..1023
        int row = (t >> 4) & 63;
        int ch  = t & 15;
        int pl  = ch >> 3;
        const __half* src = Qh + gbase + (size_t)(q0 + row) * DIM + ch * 8;
        uint32_t dst = sb + SM_Qb + pl * 8192
                     + SWZ((uint32_t)(row * 128 + (ch & 7) * 16));
        CP_ASYNC_16(dst, src);
    }
    attn_load_kv(sb, Kh, Vh, gbase, 0, 0, tid);
    CP_ASYNC_COMMIT();

    float m0v = -1e30f, m1v = -1e30f, l0v = 0.f, l1v = 0.f;
    float acc_o[16][4];
    #pragma unroll
    for (int n = 0; n < 16; n++)
        #pragma unroll
        for (int r = 0; r < 4; r++) acc_o[n][r] = 0.f;

    const int a_row = lane & 15;
    const int a_kb  = (lane >> 4) << 4;
    const int b_row = ((lane >> 4) << 3) + (lane & 7);
    const int b_kb  = ((lane >> 3) & 1) << 4;
    const int v_row = (lane & 7) + ((lane >> 3) & 1) * 8;
    const int v_cb  = ((lane >> 4) & 1) << 4;

    const int qwmin = q0 + w * 16;
    const int nt = qt + 1;

    for (int kt = 0; kt < nt; kt++) {
        __syncthreads();
        if (kt + 1 < nt)
            attn_load_kv(sb, Kh, Vh, gbase, (kt + 1) * 64, (kt + 1) & 1, tid);
        CP_ASYNC_COMMIT();
        CP_ASYNC_WAIT_1();
        __syncthreads();

        const int k0 = kt * 64;
        const int st = kt & 1;
        if (k0 > qwmin + 15) continue;

        // ---- S = Q K^T ----
        float s[8][4];
        #pragma unroll
        for (int ni = 0; ni < 8; ni++)
            #pragma unroll
            for (int r = 0; r < 4; r++) s[ni][r] = 0.f;

        #pragma unroll
        for (int ks = 0; ks < 8; ks++) {
            const int kbyte = (ks & 3) * 32;
            const int pl = ks >> 2;
            uint32_t aH[4];
            uint32_t aoff = SM_Qb + pl * 8192
                          + SWZ((uint32_t)((w * 16 + a_row) * 128 + kbyte + a_kb));
            ldmatrix_x4(aH, sb + aoff);
            #pragma unroll
            for (int pi = 0; pi < 4; pi++) {
                uint32_t bH[4];
                uint32_t boff = SM_Kb + st * 16384 + pl * 8192
                              + SWZ((uint32_t)((pi * 16 + b_row) * 128 + kbyte + b_kb));
                ldmatrix_x4(bH, sb + boff);
                mma16816(s[2 * pi],     aH, &bH[0]);
                mma16816(s[2 * pi + 1], aH, &bH[2]);
            }
        }

        // ---- causal mask ----
        const int qr0 = qwmin + (lane >> 2);
        const int qr1 = qr0 + 8;
        if (k0 + 63 > qwmin) {
            const int kc = k0 + 2 * (lane & 3);
            #pragma unroll
            for (int ni = 0; ni < 8; ni++) {
                int kb2 = kc + ni * 8;
                if (kb2     > qr0) s[ni][0] = -1e30f;
                if (kb2 + 1 > qr0) s[ni][1] = -1e30f;
                if (kb2     > qr1) s[ni][2] = -1e30f;
                if (kb2 + 1 > qr1) s[ni][3] = -1e30f;
            }
        }

        // ---- online softmax ----
        float mx0 = -1e30f, mx1 = -1e30f;
        #pragma unroll
        for (int ni = 0; ni < 8; ni++) {
            mx0 = fmaxf(mx0, fmaxf(s[ni][0], s[ni][1]));
            mx1 = fmaxf(mx1, fmaxf(s[ni][2], s[ni][3]));
        }
        mx0 = fmaxf(mx0, __shfl_xor_sync(0xffffffffu, mx0, 1));
        mx0 = fmaxf(mx0, __shfl_xor_sync(0xffffffffu, mx0, 2));
        mx1 = fmaxf(mx1, __shfl_xor_sync(0xffffffffu, mx1, 1));
        mx1 = fmaxf(mx1, __shfl_xor_sync(0xffffffffu, mx1, 2));
        float mn0 = fmaxf(m0v, mx0), mn1 = fmaxf(m1v, mx1);
        float corr0 = exp2f((m0v - mn0) * KSC);
        float corr1 = exp2f((m1v - mn1) * KSC);
        m0v = mn0; m1v = mn1;

        float rs0 = 0.f, rs1 = 0.f;
        #pragma unroll
        for (int ni = 0; ni < 8; ni++) {
            s[ni][0] = exp2f((s[ni][0] - mn0) * KSC);
            s[ni][1] = exp2f((s[ni][1] - mn0) * KSC);
            s[ni][2] = exp2f((s[ni][2] - mn1) * KSC);
            s[ni][3] = exp2f((s[ni][3] - mn1) * KSC);
            rs0 += s[ni][0] + s[ni][1];
            rs1 += s[ni][2] + s[ni][3];
        }
        rs0 += __shfl_xor_sync(0xffffffffu, rs0, 1);
        rs0 += __shfl_xor_sync(0xffffffffu, rs0, 2);
        rs1 += __shfl_xor_sync(0xffffffffu, rs1, 1);
        rs1 += __shfl_xor_sync(0xffffffffu, rs1, 2);
        l0v = l0v * corr0 + rs0;
        l1v = l1v * corr1 + rs1;

        #pragma unroll
        for (int n = 0; n < 16; n++) {
            acc_o[n][0] *= corr0; acc_o[n][1] *= corr0;
            acc_o[n][2] *= corr1; acc_o[n][3] *= corr1;
        }

        // ---- O += P V ----
        #pragma unroll
        for (int vks = 0; vks < 4; vks++) {
            uint32_t pH[4];
            #pragma unroll
            for (int half16 = 0; half16 < 2; half16++) {
                const float* sp = s[2 * vks + half16];
                __half2 h01 = __floats2half2_rn(sp[0], sp[1]);
                __half2 h23 = __floats2half2_rn(sp[2], sp[3]);
                pH[2 * half16]     = *(uint32_t*)&h01;
                pH[2 * half16 + 1] = *(uint32_t*)&h23;
            }
            const int vr = vks * 16 + v_row;
            #pragma unroll
            for (int nb = 0; nb < 8; nb++) {
                uint32_t vH[4];
                uint32_t voff = SM_Vb + st * 16384 + (nb >> 2) * 8192
                              + SWZ((uint32_t)(vr * 128 + (nb & 3) * 32 + v_cb));
                ldmatrix_x4_trans(vH, sb + voff);
                mma16816(acc_o[2 * nb],     pH, &vH[0]);
                mma16816(acc_o[2 * nb + 1], pH, &vH[2]);
            }
        }
    }

    // ---- normalize, store plain fp16 ----
    const float inv0 = 1.f / l0v;
    const float inv1 = 1.f / l1v;
    const size_t r0o = gbase + (size_t)(q0 + w * 16 + (lane >> 2)) * DIM;
    const size_t r1o = r0o + 8 * DIM;
    #pragma unroll
    for (int n = 0; n < 16; n++) {
        int col = n * 8 + 2 * (lane & 3);
        *(__half2*)&Ah[r0o + col] =
            __floats2half2_rn(acc_o[n][0] * inv0, acc_o[n][1] * inv0);
        *(__half2*)&Ah[r1o + col] =
            __floats2half2_rn(acc_o[n][2] * inv1, acc_o[n][3] * inv1);
    }
}

// ---------------------------------------------------------------------------
extern "C" void kernel_launch(void* const* d_in, const int* in_sizes, int n_in,
                              void* d_out, int out_size)
{
    const float* x  = (const float*)d_in[0];
    const float* Wq = (const float*)d_in[1];
    const float* bq = (const float*)d_in[2];
    const float* Wk = (const float*)d_in[3];
    const float* bk = (const float*)d_in[4];
    const float* Wv = (const float*)d_in[5];
    const float* bv = (const float*)d_in[6];
    const float* Wo = (const float*)d_in[7];
    const float* bo = (const float*)d_in[8];
    float* out = (float*)d_out;

    __half *Xhi, *Whi, *Qh, *Kh, *Vh, *Ah;
    cudaGetSymbolAddress((void**)&Xhi, g_Xhi);
    cudaGetSymbolAddress((void**)&Whi, g_Whi);
    cudaGetSymbolAddress((void**)&Qh,  g_Qh);
    cudaGetSymbolAddress((void**)&Kh,  g_Kh);
    cudaGetSymbolAddress((void**)&Vh,  g_Vh);
    cudaGetSymbolAddress((void**)&Ah,  g_Ah);

    cudaFuncSetAttribute(gemm_qkv_kernel,
                         cudaFuncAttributeMaxDynamicSharedMemorySize, GEMM_SMEM);
    cudaFuncSetAttribute(gemm_o_kernel,
                         cudaFuncAttributeMaxDynamicSharedMemorySize, GEMM_SMEM);
    cudaFuncSetAttribute(attn_tc_kernel,
                         cudaFuncAttributeMaxDynamicSharedMemorySize, ATTN_SMEM);

    const int nX4 = MTOT * DIM / 4;
    const int nW4 = DIM * DIM / 4;
    const size_t WSZ = (size_t)DIM * DIM;

    splitX_hi_kernel<<<nX4 / 256, 256>>>(x, Xhi, nX4);
    splitW_kernel<<<dim3(nW4 / 256, 4), 256>>>(Wq, Wk, Wv, Wo, Whi, nW4);

    // Fused QKV projection (single product, plain fp16 outputs)
    gemm_qkv_kernel<<<dim3(MTOT / QTM, 48), 256, GEMM_SMEM>>>(
        Xhi, Whi, bq, bk, bv, Qh, Kh, Vh);

    // Attention (64-query CTAs, 2 CTAs/SM)
    dim3 agrid(SEQ / 64, HEADS, BATCH);
    attn_tc_kernel<<<agrid, 128, ATTN_SMEM>>>(Qh, Kh, Vh, Ah);

    // Output projection (single product, fp32 out)
    gemm_o_kernel<<<dim3(MTOT / QTM, DIM / 128), 256, GEMM_SMEM>>>(
        Ah, Whi + 3 * WSZ, bo, out);
}

// round 10
// speedup vs baseline: 10.1353x; 1.1049x over previous
#include <cuda_runtime.h>
#include <cuda_fp16.h>
#include <math.h>
#include <stdint.h>

// Problem constants
#define BATCH 2
#define SEQ   2048
#define DIM   2048
#define HEADS 16
#define DHEAD 128
#define MTOT  (BATCH * SEQ)   // 4096

// ---------------------------------------------------------------------------
// Scratch (allocation-free rule: __device__ globals)
// ---------------------------------------------------------------------------
__device__ __half g_Xhi[MTOT * DIM];
__device__ __half g_Whi[4][DIM * DIM];
__device__ __half g_Qh [MTOT * DIM];
__device__ __half g_Kh [MTOT * DIM];
__device__ __half g_Vh [MTOT * DIM];
__device__ __half g_Ah [MTOT * DIM];

// ---------------------------------------------------------------------------
// PTX helpers
// ---------------------------------------------------------------------------
__device__ __forceinline__ uint32_t smem_u32(const void* p) {
    uint32_t a;
    asm("{ .reg .u64 t; cvta.to.shared.u64 t, %1; cvt.u32.u64 %0, t; }" : "=r"(a) : "l"(p));
    return a;
}

#define CP_ASYNC_16(dst_u32, src_ptr) \
    asm volatile("cp.async.cg.shared.global [%0], [%1], 16;" \
                 :: "r"(dst_u32), "l"(src_ptr) : "memory")
#define CP_ASYNC_COMMIT() asm volatile("cp.async.commit_group;" ::: "memory")
#define CP_ASYNC_WAIT_1() asm volatile("cp.async.wait_group 1;" ::: "memory")

__device__ __forceinline__ void ldmatrix_x4(uint32_t* r, uint32_t addr) {
    asm volatile("ldmatrix.sync.aligned.m8n8.x4.shared.b16 {%0,%1,%2,%3}, [%4];"
        : "=r"(r[0]), "=r"(r[1]), "=r"(r[2]), "=r"(r[3]) : "r"(addr));
}
__device__ __forceinline__ void ldmatrix_x4_trans(uint32_t* r, uint32_t addr) {
    asm volatile("ldmatrix.sync.aligned.m8n8.x4.trans.shared.b16 {%0,%1,%2,%3}, [%4];"
        : "=r"(r[0]), "=r"(r[1]), "=r"(r[2]), "=r"(r[3]) : "r"(addr));
}

__device__ __forceinline__ void mma16816(float* d, const uint32_t* a, const uint32_t* b) {
    asm volatile(
        "mma.sync.aligned.m16n8k16.row.col.f32.f16.f16.f32 "
        "{%0,%1,%2,%3}, {%4,%5,%6,%7}, {%8,%9}, {%0,%1,%2,%3};"
        : "+f"(d[0]), "+f"(d[1]), "+f"(d[2]), "+f"(d[3])
        : "r"(a[0]), "r"(a[1]), "r"(a[2]), "r"(a[3]), "r"(b[0]), "r"(b[1]));
}

#define SWZ(x) ((x) ^ (((x) >> 3) & 0x70))

// ---------------------------------------------------------------------------
// Splits (fp32 -> fp16), MLP-4 grid-stride
// ---------------------------------------------------------------------------
__global__ __launch_bounds__(256) void splitX_hi_kernel(
    const float* __restrict__ in, __half* __restrict__ hi, int n4)
{
    int T = (n4 >> 2);                   // threads total
    int i = blockIdx.x * 256 + threadIdx.x;
    if (i >= T) return;
    float4 v0 = ((const float4*)in)[i];
    float4 v1 = ((const float4*)in)[i + T];
    float4 v2 = ((const float4*)in)[i + 2 * T];
    float4 v3 = ((const float4*)in)[i + 3 * T];
    ((__half2*)hi)[2 * i]                 = __floats2half2_rn(v0.x, v0.y);
    ((__half2*)hi)[2 * i + 1]             = __floats2half2_rn(v0.z, v0.w);
    ((__half2*)hi)[2 * (i + T)]           = __floats2half2_rn(v1.x, v1.y);
    ((__half2*)hi)[2 * (i + T) + 1]       = __floats2half2_rn(v1.z, v1.w);
    ((__half2*)hi)[2 * (i + 2 * T)]       = __floats2half2_rn(v2.x, v2.y);
    ((__half2*)hi)[2 * (i + 2 * T) + 1]   = __floats2half2_rn(v2.z, v2.w);
    ((__half2*)hi)[2 * (i + 3 * T)]       = __floats2half2_rn(v3.x, v3.y);
    ((__half2*)hi)[2 * (i + 3 * T) + 1]   = __floats2half2_rn(v3.z, v3.w);
}

__global__ __launch_bounds__(256) void splitW_kernel(
    const float* __restrict__ w0, const float* __restrict__ w1,
    const float* __restrict__ w2, const float* __restrict__ w3,
    __half* __restrict__ WhiAll, int n4)
{
    int T = (n4 >> 2);
    int i = blockIdx.x * 256 + threadIdx.x;
    if (i >= T) return;
    int wsel = blockIdx.y;
    const float* in = (wsel == 0) ? w0 : (wsel == 1) ? w1 : (wsel == 2) ? w2 : w3;
    __half* hi = WhiAll + (size_t)wsel * DIM * DIM;
    float4 v0 = ((const float4*)in)[i];
    float4 v1 = ((const float4*)in)[i + T];
    float4 v2 = ((const float4*)in)[i + 2 * T];
    float4 v3 = ((const float4*)in)[i + 3 * T];
    ((__half2*)hi)[2 * i]                 = __floats2half2_rn(v0.x, v0.y);
    ((__half2*)hi)[2 * i + 1]             = __floats2half2_rn(v0.z, v0.w);
    ((__half2*)hi)[2 * (i + T)]           = __floats2half2_rn(v1.x, v1.y);
    ((__half2*)hi)[2 * (i + T) + 1]       = __floats2half2_rn(v1.z, v1.w);
    ((__half2*)hi)[2 * (i + 2 * T)]       = __floats2half2_rn(v2.x, v2.y);
    ((__half2*)hi)[2 * (i + 2 * T) + 1]   = __floats2half2_rn(v2.z, v2.w);
    ((__half2*)hi)[2 * (i + 3 * T)]       = __floats2half2_rn(v3.x, v3.y);
    ((__half2*)hi)[2 * (i + 3 * T) + 1]   = __floats2half2_rn(v3.z, v3.w);
}

// ---------------------------------------------------------------------------
// Single-product GEMM, 2 CTAs/SM:
// CTA 128x128, 8 warps (4m x 2n), warp tile 32x64, K chunk 64,
// 3-stage 32KB ring (96KB smem/CTA).
// ---------------------------------------------------------------------------
#define TKC 64
#define NCHUNK (DIM / TKC)
#define GTM 128
#define GS_A  0
#define GS_B  16384
#define GSTAGE 32768
#define GEMM_SMEM (3 * GSTAGE)   // 98304

__device__ __forceinline__ void load_stage_g(
    uint32_t sb, const __half* __restrict__ Ap, const __half* __restrict__ Bp,
    int m0, int n0, int k0, int tid)
{
    #pragma unroll
    for (int it = 0; it < 4; it++) {
        int t = tid + it * 256;            // 0..1023
        int row = t >> 3;                  // 0..127
        int kk = (t & 7) * 8;
        uint32_t soff = SWZ((uint32_t)(row * 128 + kk * 2));
        CP_ASYNC_16(sb + GS_A + soff, Ap + (size_t)(m0 + row) * DIM + k0 + kk);
        CP_ASYNC_16(sb + GS_B + soff, Bp + (size_t)(n0 + row) * DIM + k0 + kk);
    }
}

template <bool F16OUT>
__global__ __launch_bounds__(256, 2) void gemm_sp_kernel(
    const __half* __restrict__ Ap, const __half* __restrict__ WhiAll,
    const float* __restrict__ b0, const float* __restrict__ b1,
    const float* __restrict__ b2,
    __half* __restrict__ Y0, __half* __restrict__ Y1, __half* __restrict__ Y2,
    float* __restrict__ Yf, int n_nblk)
{
    extern __shared__ char smem[];
    const uint32_t smem_base = smem_u32(smem);
    const int tid = threadIdx.x;
    const int wid = tid >> 5;
    const int lane = tid & 31;
    const int warp_m = wid & 3;        // 32 rows each
    const int warp_n = wid >> 2;       // 64 cols each
    const int m0 = blockIdx.x * GTM;
    const int out = blockIdx.y / n_nblk;   // 0..2 (QKV) or 0 (O)
    const int n0 = (blockIdx.y % n_nblk) * 128;

    const __half* Bp = WhiAll + (size_t)out * DIM * DIM;
    const float* bias = (out == 0) ? b0 : (out == 1) ? b1 : b2;
    __half* Yh = (out == 0) ? Y0 : (out == 1) ? Y1 : Y2;

    float acc[2][8][4];
    #pragma unroll
    for (int mi = 0; mi < 2; mi++)
        #pragma unroll
        for (int ni = 0; ni < 8; ni++)
            #pragma unroll
            for (int r = 0; r < 4; r++) acc[mi][ni][r] = 0.f;

    load_stage_g(smem_base,          Ap, Bp, m0, n0, 0 * TKC, tid);
    CP_ASYNC_COMMIT();
    load_stage_g(smem_base + GSTAGE, Ap, Bp, m0, n0, 1 * TKC, tid);
    CP_ASYNC_COMMIT();

    const int a_row = (lane & 15);
    const int a_kb  = (lane >> 4) << 4;
    const int b_row = ((lane >> 4) << 3) + (lane & 7);
    const int b_kb  = ((lane >> 3) & 1) << 4;

    int slot = 0;
    for (int c = 0; c < NCHUNK; c++) {
        CP_ASYNC_WAIT_1_SAFE:
        CP_ASYNC_WAIT_1();
        __syncthreads();

        if (c + 2 < NCHUNK) {
            int s2 = slot + 2; if (s2 >= 3) s2 -= 3;
            load_stage_g(smem_base + s2 * GSTAGE, Ap, Bp, m0, n0, (c + 2) * TKC, tid);
        }
        CP_ASYNC_COMMIT();

        const uint32_t sb = smem_base + slot * GSTAGE;
        #pragma unroll
        for (int ks = 0; ks < 4; ks++) {
            const int kbyte = ks * 32;
            uint32_t b_h[4][4];
            #pragma unroll
            for (int pi = 0; pi < 4; pi++) {
                uint32_t off = SWZ((uint32_t)((warp_n * 64 + pi * 16 + b_row) * 128 + kbyte + b_kb));
                ldmatrix_x4(b_h[pi], sb + GS_B + off);
            }
            #pragma unroll
            for (int mi = 0; mi < 2; mi++) {
                uint32_t a_h[4];
                uint32_t aoff = SWZ((uint32_t)((warp_m * 32 + mi * 16 + a_row) * 128 + kbyte + a_kb));
                ldmatrix_x4(a_h, sb + GS_A + aoff);
                #pragma unroll
                for (int ni = 0; ni < 8; ni++)
                    mma16816(acc[mi][ni], a_h, &b_h[ni >> 1][(ni & 1) * 2]);
            }
        }
        slot++; if (slot >= 3) slot = 0;
    }

    const int gm0 = m0 + warp_m * 32;
    const int gn0 = n0 + warp_n * 64;
    #pragma unroll
    for (int mi = 0; mi < 2; mi++) {
        int row = gm0 + mi * 16 + (lane >> 2);
        #pragma unroll
        for (int ni = 0; ni < 8; ni++) {
            int col = gn0 + ni * 8 + 2 * (lane & 3);
            float2 bb = *(const float2*)&bias[col];
            float y0 = acc[mi][ni][0] + bb.x, y1 = acc[mi][ni][1] + bb.y;
            float y2 = acc[mi][ni][2] + bb.x, y3 = acc[mi][ni][3] + bb.y;
            if (F16OUT) {
                *(__half2*)&Yh[(size_t)row * DIM + col]       = __floats2half2_rn(y0, y1);
                *(__half2*)&Yh[(size_t)(row + 8) * DIM + col] = __floats2half2_rn(y2, y3);
            } else {
                *(float2*)&Yf[(size_t)row * DIM + col]       = make_float2(y0, y1);
                *(float2*)&Yf[(size_t)(row + 8) * DIM + col] = make_float2(y2, y3);
            }
        }
    }
}

// ---------------------------------------------------------------------------
// Tensor-core causal flash attention, 2 CTAs/SM (unchanged from R9).
// CTA: 128 threads (4 warps x 16 q-rows = 64 queries), key tiles of 64.
// Smem: Q 16KB | K 2st x 16KB | V 2st x 16KB = 80KB.
// ---------------------------------------------------------------------------
#define SM_Qb 0
#define SM_Kb 16384
#define SM_Vb 49152
#define ATTN_SMEM 81920
#define KSC 0.12751741219860918f   /* (1/sqrt(128)) * log2(e) */

__device__ __forceinline__ void attn_load_kv(
    uint32_t sb, const __half* __restrict__ Kh, const __half* __restrict__ Vh,
    size_t gbase, int k0, int stage, int tid)
{
    #pragma unroll
    for (int i = 0; i < 16; i++) {
        int t = tid + i * 128;            // 0..2047
        int kv  = t >> 10;                // 0: K, 1: V
        int row = (t >> 4) & 63;
        int ch  = t & 15;
        int pl  = ch >> 3;
        const __half* src = (kv ? Vh : Kh) + gbase + (size_t)(k0 + row) * DIM + ch * 8;
        uint32_t dst = sb + (kv ? SM_Vb : SM_Kb) + stage * 16384
                     + pl * 8192 + SWZ((uint32_t)(row * 128 + (ch & 7) * 16));
        CP_ASYNC_16(dst, src);
    }
}

__global__ __launch_bounds__(128, 2) void attn_tc_kernel(
    const __half* __restrict__ Qh, const __half* __restrict__ Kh,
    const __half* __restrict__ Vh, __half* __restrict__ Ah)
{
    extern __shared__ char smem[];
    const uint32_t sb = smem_u32(smem);
    const int tid = threadIdx.x;
    const int w = tid >> 5;
    const int lane = tid & 31;
    const int qt = gridDim.x - 1 - blockIdx.x;   // big tiles first
    const int h = blockIdx.y;
    const int b = blockIdx.z;
    const int q0 = qt * 64;
    const size_t gbase = (size_t)b * SEQ * DIM + (size_t)h * DHEAD;

    // Load Q tile (64 rows)
    #pragma unroll
    for (int i = 0; i < 8; i++) {
        int t = tid + i * 128;
        int row = (t >> 4) & 63;
        int ch  = t & 15;
        int pl  = ch >> 3;
        const __half* src = Qh + gbase + (size_t)(q0 + row) * DIM + ch * 8;
        uint32_t dst = sb + SM_Qb + pl * 8192
                     + SWZ((uint32_t)(row * 128 + (ch & 7) * 16));
        CP_ASYNC_16(dst, src);
    }
    attn_load_kv(sb, Kh, Vh, gbase, 0, 0, tid);
    CP_ASYNC_COMMIT();

    float m0v = -1e30f, m1v = -1e30f, l0v = 0.f, l1v = 0.f;
    float acc_o[16][4];
    #pragma unroll
    for (int n = 0; n < 16; n++)
        #pragma unroll
        for (int r = 0; r < 4; r++) acc_o[n][r] = 0.f;

    const int a_row = lane & 15;
    const int a_kb  = (lane >> 4) << 4;
    const int b_row = ((lane >> 4) << 3) + (lane & 7);
    const int b_kb  = ((lane >> 3) & 1) << 4;
    const int v_row = (lane & 7) + ((lane >> 3) & 1) * 8;
    const int v_cb  = ((lane >> 4) & 1) << 4;

    const int qwmin = q0 + w * 16;
    const int nt = qt + 1;

    for (int kt = 0; kt < nt; kt++) {
        __syncthreads();
        if (kt + 1 < nt)
            attn_load_kv(sb, Kh, Vh, gbase, (kt + 1) * 64, (kt + 1) & 1, tid);
        CP_ASYNC_COMMIT();
        CP_ASYNC_WAIT_1();
        __syncthreads();

        const int k0 = kt * 64;
        const int st = kt & 1;
        if (k0 > qwmin + 15) continue;

        // ---- S = Q K^T ----
        float s[8][4];
        #pragma unroll
        for (int ni = 0; ni < 8; ni++)
            #pragma unroll
            for (int r = 0; r < 4; r++) s[ni][r] = 0.f;

        #pragma unroll
        for (int ks = 0; ks < 8; ks++) {
            const int kbyte = (ks & 3) * 32;
            const int pl = ks >> 2;
            uint32_t aH[4];
            uint32_t aoff = SM_Qb + pl * 8192
                          + SWZ((uint32_t)((w * 16 + a_row) * 128 + kbyte + a_kb));
            ldmatrix_x4(aH, sb + aoff);
            #pragma unroll
            for (int pi = 0; pi < 4; pi++) {
                uint32_t bH[4];
                uint32_t boff = SM_Kb + st * 16384 + pl * 8192
                              + SWZ((uint32_t)((pi * 16 + b_row) * 128 + kbyte + b_kb));
                ldmatrix_x4(bH, sb + boff);
                mma16816(s[2 * pi],     aH, &bH[0]);
                mma16816(s[2 * pi + 1], aH, &bH[2]);
            }
        }

        // ---- causal mask ----
        const int qr0 = qwmin + (lane >> 2);
        const int qr1 = qr0 + 8;
        if (k0 + 63 > qwmin) {
            const int kc = k0 + 2 * (lane & 3);
            #pragma unroll
            for (int ni = 0; ni < 8; ni++) {
                int kb2 = kc + ni * 8;
                if (kb2     > qr0) s[ni][0] = -1e30f;
                if (kb2 + 1 > qr0) s[ni][1] = -1e30f;
                if (kb2     > qr1) s[ni][2] = -1e30f;
                if (kb2 + 1 > qr1) s[ni][3] = -1e30f;
            }
        }

        // ---- online softmax ----
        float mx0 = -1e30f, mx1 = -1e30f;
        #pragma unroll
        for (int ni = 0; ni < 8; ni++) {
            mx0 = fmaxf(mx0, fmaxf(s[ni][0], s[ni][1]));
            mx1 = fmaxf(mx1, fmaxf(s[ni][2], s[ni][3]));
        }
        mx0 = fmaxf(mx0, __shfl_xor_sync(0xffffffffu, mx0, 1));
        mx0 = fmaxf(mx0, __shfl_xor_sync(0xffffffffu, mx0, 2));
        mx1 = fmaxf(mx1, __shfl_xor_sync(0xffffffffu, mx1, 1));
        mx1 = fmaxf(mx1, __shfl_xor_sync(0xffffffffu, mx1, 2));
        float mn0 = fmaxf(m0v, mx0), mn1 = fmaxf(m1v, mx1);
        float corr0 = exp2f((m0v - mn0) * KSC);
        float corr1 = exp2f((m1v - mn1) * KSC);
        m0v = mn0; m1v = mn1;

        float rs0 = 0.f, rs1 = 0.f;
        #pragma unroll
        for (int ni = 0; ni < 8; ni++) {
            s[ni][0] = exp2f((s[ni][0] - mn0) * KSC);
            s[ni][1] = exp2f((s[ni][1] - mn0) * KSC);
            s[ni][2] = exp2f((s[ni][2] - mn1) * KSC);
            s[ni][3] = exp2f((s[ni][3] - mn1) * KSC);
            rs0 += s[ni][0] + s[ni][1];
            rs1 += s[ni][2] + s[ni][3];
        }
        rs0 += __shfl_xor_sync(0xffffffffu, rs0, 1);
        rs0 += __shfl_xor_sync(0xffffffffu, rs0, 2);
        rs1 += __shfl_xor_sync(0xffffffffu, rs1, 1);
        rs1 += __shfl_xor_sync(0xffffffffu, rs1, 2);
        l0v = l0v * corr0 + rs0;
        l1v = l1v * corr1 + rs1;

        #pragma unroll
        for (int n = 0; n < 16; n++) {
            acc_o[n][0] *= corr0; acc_o[n][1] *= corr0;
            acc_o[n][2] *= corr1; acc_o[n][3] *= corr1;
        }

        // ---- O += P V ----
        #pragma unroll
        for (int vks = 0; vks < 4; vks++) {
            uint32_t pH[4];
            #pragma unroll
            for (int half16 = 0; half16 < 2; half16++) {
                const float* sp = s[2 * vks + half16];
                __half2 h01 = __floats2half2_rn(sp[0], sp[1]);
                __half2 h23 = __floats2half2_rn(sp[2], sp[3]);
                pH[2 * half16]     = *(uint32_t*)&h01;
                pH[2 * half16 + 1] = *(uint32_t*)&h23;
            }
            const int vr = vks * 16 + v_row;
            #pragma unroll
            for (int nb = 0; nb < 8; nb++) {
                uint32_t vH[4];
                uint32_t voff = SM_Vb + st * 16384 + (nb >> 2) * 8192
                              + SWZ((uint32_t)(vr * 128 + (nb & 3) * 32 + v_cb));
                ldmatrix_x4_trans(vH, sb + voff);
                mma16816(acc_o[2 * nb],     pH, &vH[0]);
                mma16816(acc_o[2 * nb + 1], pH, &vH[2]);
            }
        }
    }

    // ---- normalize, store plain fp16 ----
    const float inv0 = 1.f / l0v;
    const float inv1 = 1.f / l1v;
    const size_t r0o = gbase + (size_t)(q0 + w * 16 + (lane >> 2)) * DIM;
    const size_t r1o = r0o + 8 * DIM;
    #pragma unroll
    for (int n = 0; n < 16; n++) {
        int col = n * 8 + 2 * (lane & 3);
        *(__half2*)&Ah[r0o + col] =
            __floats2half2_rn(acc_o[n][0] * inv0, acc_o[n][1] * inv0);
        *(__half2*)&Ah[r1o + col] =
            __floats2half2_rn(acc_o[n][2] * inv1, acc_o[n][3] * inv1);
    }
}

// ---------------------------------------------------------------------------
extern "C" void kernel_launch(void* const* d_in, const int* in_sizes, int n_in,
                              void* d_out, int out_size)
{
    const float* x  = (const float*)d_in[0];
    const float* Wq = (const float*)d_in[1];
    const float* bq = (const float*)d_in[2];
    const float* Wk = (const float*)d_in[3];
    const float* bk = (const float*)d_in[4];
    const float* Wv = (const float*)d_in[5];
    const float* bv = (const float*)d_in[6];
    const float* Wo = (const float*)d_in[7];
    const float* bo = (const float*)d_in[8];
    float* out = (float*)d_out;

    __half *Xhi, *Whi, *Qh, *Kh, *Vh, *Ah;
    cudaGetSymbolAddress((void**)&Xhi, g_Xhi);
    cudaGetSymbolAddress((void**)&Whi, g_Whi);
    cudaGetSymbolAddress((void**)&Qh,  g_Qh);
    cudaGetSymbolAddress((void**)&Kh,  g_Kh);
    cudaGetSymbolAddress((void**)&Vh,  g_Vh);
    cudaGetSymbolAddress((void**)&Ah,  g_Ah);

    cudaFuncSetAttribute(gemm_sp_kernel<true>,
                         cudaFuncAttributeMaxDynamicSharedMemorySize, GEMM_SMEM);
    cudaFuncSetAttribute(gemm_sp_kernel<false>,
                         cudaFuncAttributeMaxDynamicSharedMemorySize, GEMM_SMEM);
    cudaFuncSetAttribute(attn_tc_kernel,
                         cudaFuncAttributeMaxDynamicSharedMemorySize, ATTN_SMEM);

    const int nX4 = MTOT * DIM / 4;     // 2,097,152
    const int nW4 = DIM * DIM / 4;      // 1,048,576
    const size_t WSZ = (size_t)DIM * DIM;

    splitX_hi_kernel<<<nX4 / 4 / 256, 256>>>(x, Xhi, nX4);
    splitW_kernel<<<dim3(nW4 / 4 / 256, 4), 256>>>(Wq, Wk, Wv, Wo, Whi, nW4);

    // Fused QKV projection (single product, 2 CTAs/SM)
    gemm_sp_kernel<true><<<dim3(MTOT / GTM, 48), 256, GEMM_SMEM>>>(
        Xhi, Whi, bq, bk, bv, Qh, Kh, Vh, nullptr, 16);

    // Attention (64-query CTAs, 2 CTAs/SM)
    dim3 agrid(SEQ / 64, HEADS, BATCH);
    attn_tc_kernel<<<agrid, 128, ATTN_SMEM>>>(Qh, Kh, Vh, Ah);

    // Output projection (single product, fp32 out, 2 CTAs/SM)
    gemm_sp_kernel<false><<<dim3(MTOT / GTM, 16), 256, GEMM_SMEM>>>(
        Ah, Whi + 3 * WSZ, bo, nullptr, nullptr, nullptr, nullptr, nullptr, out, 16);
}

// round 11
// speedup vs baseline: 10.8140x; 1.0670x over previous
#include <cuda_runtime.h>
#include <cuda_fp16.h>
#include <math.h>
#include <stdint.h>

// Problem constants
#define BATCH 2
#define SEQ   2048
#define DIM   2048
#define HEADS 16
#define DHEAD 128
#define MTOT  (BATCH * SEQ)   // 4096

// ---------------------------------------------------------------------------
// Scratch (allocation-free rule: __device__ globals)
// ---------------------------------------------------------------------------
__device__ __half g_Xhi[MTOT * DIM];
__device__ __half g_Whi[4][DIM * DIM];
__device__ __half g_Qh [MTOT * DIM];
__device__ __half g_Kh [MTOT * DIM];
__device__ __half g_Vh [MTOT * DIM];
__device__ __half g_Ah [MTOT * DIM];

// ---------------------------------------------------------------------------
// PTX helpers
// ---------------------------------------------------------------------------
__device__ __forceinline__ uint32_t smem_u32(const void* p) {
    uint32_t a;
    asm("{ .reg .u64 t; cvta.to.shared.u64 t, %1; cvt.u32.u64 %0, t; }" : "=r"(a) : "l"(p));
    return a;
}

#define CP_ASYNC_16(dst_u32, src_ptr) \
    asm volatile("cp.async.cg.shared.global [%0], [%1], 16;" \
                 :: "r"(dst_u32), "l"(src_ptr) : "memory")
#define CP_ASYNC_COMMIT() asm volatile("cp.async.commit_group;" ::: "memory")
#define CP_ASYNC_WAIT_1() asm volatile("cp.async.wait_group 1;" ::: "memory")

__device__ __forceinline__ void ldmatrix_x4(uint32_t* r, uint32_t addr) {
    asm volatile("ldmatrix.sync.aligned.m8n8.x4.shared.b16 {%0,%1,%2,%3}, [%4];"
        : "=r"(r[0]), "=r"(r[1]), "=r"(r[2]), "=r"(r[3]) : "r"(addr));
}
__device__ __forceinline__ void ldmatrix_x4_trans(uint32_t* r, uint32_t addr) {
    asm volatile("ldmatrix.sync.aligned.m8n8.x4.trans.shared.b16 {%0,%1,%2,%3}, [%4];"
        : "=r"(r[0]), "=r"(r[1]), "=r"(r[2]), "=r"(r[3]) : "r"(addr));
}

__device__ __forceinline__ void mma16816(float* d, const uint32_t* a, const uint32_t* b) {
    asm volatile(
        "mma.sync.aligned.m16n8k16.row.col.f32.f16.f16.f32 "
        "{%0,%1,%2,%3}, {%4,%5,%6,%7}, {%8,%9}, {%0,%1,%2,%3};"
        : "+f"(d[0]), "+f"(d[1]), "+f"(d[2]), "+f"(d[3])
        : "r"(a[0]), "r"(a[1]), "r"(a[2]), "r"(a[3]), "r"(b[0]), "r"(b[1]));
}

#define SWZ(x) ((x) ^ (((x) >> 3) & 0x70))

// ---------------------------------------------------------------------------
// Splits (fp32 -> fp16), MLP-4
// ---------------------------------------------------------------------------
__global__ __launch_bounds__(256) void splitX_hi_kernel(
    const float* __restrict__ in, __half* __restrict__ hi, int n4)
{
    int T = (n4 >> 2);
    int i = blockIdx.x * 256 + threadIdx.x;
    if (i >= T) return;
    float4 v0 = ((const float4*)in)[i];
    float4 v1 = ((const float4*)in)[i + T];
    float4 v2 = ((const float4*)in)[i + 2 * T];
    float4 v3 = ((const float4*)in)[i + 3 * T];
    ((__half2*)hi)[2 * i]                 = __floats2half2_rn(v0.x, v0.y);
    ((__half2*)hi)[2 * i + 1]             = __floats2half2_rn(v0.z, v0.w);
    ((__half2*)hi)[2 * (i + T)]           = __floats2half2_rn(v1.x, v1.y);
    ((__half2*)hi)[2 * (i + T) + 1]       = __floats2half2_rn(v1.z, v1.w);
    ((__half2*)hi)[2 * (i + 2 * T)]       = __floats2half2_rn(v2.x, v2.y);
    ((__half2*)hi)[2 * (i + 2 * T) + 1]   = __floats2half2_rn(v2.z, v2.w);
    ((__half2*)hi)[2 * (i + 3 * T)]       = __floats2half2_rn(v3.x, v3.y);
    ((__half2*)hi)[2 * (i + 3 * T) + 1]   = __floats2half2_rn(v3.z, v3.w);
}

__global__ __launch_bounds__(256) void splitW_kernel(
    const float* __restrict__ w0, const float* __restrict__ w1,
    const float* __restrict__ w2, const float* __restrict__ w3,
    __half* __restrict__ WhiAll, int n4)
{
    int T = (n4 >> 2);
    int i = blockIdx.x * 256 + threadIdx.x;
    if (i >= T) return;
    int wsel = blockIdx.y;
    const float* in = (wsel == 0) ? w0 : (wsel == 1) ? w1 : (wsel == 2) ? w2 : w3;
    __half* hi = WhiAll + (size_t)wsel * DIM * DIM;
    float4 v0 = ((const float4*)in)[i];
    float4 v1 = ((const float4*)in)[i + T];
    float4 v2 = ((const float4*)in)[i + 2 * T];
    float4 v3 = ((const float4*)in)[i + 3 * T];
    ((__half2*)hi)[2 * i]                 = __floats2half2_rn(v0.x, v0.y);
    ((__half2*)hi)[2 * i + 1]             = __floats2half2_rn(v0.z, v0.w);
    ((__half2*)hi)[2 * (i + T)]           = __floats2half2_rn(v1.x, v1.y);
    ((__half2*)hi)[2 * (i + T) + 1]       = __floats2half2_rn(v1.z, v1.w);
    ((__half2*)hi)[2 * (i + 2 * T)]       = __floats2half2_rn(v2.x, v2.y);
    ((__half2*)hi)[2 * (i + 2 * T) + 1]   = __floats2half2_rn(v2.z, v2.w);
    ((__half2*)hi)[2 * (i + 3 * T)]       = __floats2half2_rn(v3.x, v3.y);
    ((__half2*)hi)[2 * (i + 3 * T) + 1]   = __floats2half2_rn(v3.z, v3.w);
}

// ---------------------------------------------------------------------------
// Single-product GEMM, 2 CTAs/SM. CTA 128x128, 8 warps, warp tile 32x64,
// K chunk 64, 3-stage 32KB ring. m_base selects the batch-half.
// ---------------------------------------------------------------------------
#define TKC 64
#define NCHUNK (DIM / TKC)
#define GTM 128
#define GS_A  0
#define GS_B  16384
#define GSTAGE 32768
#define GEMM_SMEM (3 * GSTAGE)   // 98304

__device__ __forceinline__ void load_stage_g(
    uint32_t sb, const __half* __restrict__ Ap, const __half* __restrict__ Bp,
    int m0, int n0, int k0, int tid)
{
    #pragma unroll
    for (int it = 0; it < 4; it++) {
        int t = tid + it * 256;
        int row = t >> 3;
        int kk = (t & 7) * 8;
        uint32_t soff = SWZ((uint32_t)(row * 128 + kk * 2));
        CP_ASYNC_16(sb + GS_A + soff, Ap + (size_t)(m0 + row) * DIM + k0 + kk);
        CP_ASYNC_16(sb + GS_B + soff, Bp + (size_t)(n0 + row) * DIM + k0 + kk);
    }
}

template <bool F16OUT>
__global__ __launch_bounds__(256, 2) void gemm_sp_kernel(
    const __half* __restrict__ Ap, const __half* __restrict__ WhiAll,
    const float* __restrict__ b0, const float* __restrict__ b1,
    const float* __restrict__ b2,
    __half* __restrict__ Y0, __half* __restrict__ Y1, __half* __restrict__ Y2,
    float* __restrict__ Yf, int n_nblk, int m_base)
{
    extern __shared__ char smem[];
    const uint32_t smem_base = smem_u32(smem);
    const int tid = threadIdx.x;
    const int wid = tid >> 5;
    const int lane = tid & 31;
    const int warp_m = wid & 3;
    const int warp_n = wid >> 2;
    const int m0 = m_base + blockIdx.x * GTM;
    const int out = blockIdx.y / n_nblk;
    const int n0 = (blockIdx.y % n_nblk) * 128;

    const __half* Bp = WhiAll + (size_t)out * DIM * DIM;
    const float* bias = (out == 0) ? b0 : (out == 1) ? b1 : b2;
    __half* Yh = (out == 0) ? Y0 : (out == 1) ? Y1 : Y2;

    float acc[2][8][4];
    #pragma unroll
    for (int mi = 0; mi < 2; mi++)
        #pragma unroll
        for (int ni = 0; ni < 8; ni++)
            #pragma unroll
            for (int r = 0; r < 4; r++) acc[mi][ni][r] = 0.f;

    load_stage_g(smem_base,          Ap, Bp, m0, n0, 0 * TKC, tid);
    CP_ASYNC_COMMIT();
    load_stage_g(smem_base + GSTAGE, Ap, Bp, m0, n0, 1 * TKC, tid);
    CP_ASYNC_COMMIT();

    const int a_row = (lane & 15);
    const int a_kb  = (lane >> 4) << 4;
    const int b_row = ((lane >> 4) << 3) + (lane & 7);
    const int b_kb  = ((lane >> 3) & 1) << 4;

    int slot = 0;
    for (int c = 0; c < NCHUNK; c++) {
        CP_ASYNC_WAIT_1();
        __syncthreads();

        if (c + 2 < NCHUNK) {
            int s2 = slot + 2; if (s2 >= 3) s2 -= 3;
            load_stage_g(smem_base + s2 * GSTAGE, Ap, Bp, m0, n0, (c + 2) * TKC, tid);
        }
        CP_ASYNC_COMMIT();

        const uint32_t sb = smem_base + slot * GSTAGE;
        #pragma unroll
        for (int ks = 0; ks < 4; ks++) {
            const int kbyte = ks * 32;
            uint32_t b_h[4][4];
            #pragma unroll
            for (int pi = 0; pi < 4; pi++) {
                uint32_t off = SWZ((uint32_t)((warp_n * 64 + pi * 16 + b_row) * 128 + kbyte + b_kb));
                ldmatrix_x4(b_h[pi], sb + GS_B + off);
            }
            #pragma unroll
            for (int mi = 0; mi < 2; mi++) {
                uint32_t a_h[4];
                uint32_t aoff = SWZ((uint32_t)((warp_m * 32 + mi * 16 + a_row) * 128 + kbyte + a_kb));
                ldmatrix_x4(a_h, sb + GS_A + aoff);
                #pragma unroll
                for (int ni = 0; ni < 8; ni++)
                    mma16816(acc[mi][ni], a_h, &b_h[ni >> 1][(ni & 1) * 2]);
            }
        }
        slot++; if (slot >= 3) slot = 0;
    }

    const int gm0 = m0 + warp_m * 32;
    const int gn0 = n0 + warp_n * 64;
    #pragma unroll
    for (int mi = 0; mi < 2; mi++) {
        int row = gm0 + mi * 16 + (lane >> 2);
        #pragma unroll
        for (int ni = 0; ni < 8; ni++) {
            int col = gn0 + ni * 8 + 2 * (lane & 3);
            float2 bb = *(const float2*)&bias[col];
            float y0 = acc[mi][ni][0] + bb.x, y1 = acc[mi][ni][1] + bb.y;
            float y2 = acc[mi][ni][2] + bb.x, y3 = acc[mi][ni][3] + bb.y;
            if (F16OUT) {
                *(__half2*)&Yh[(size_t)row * DIM + col]       = __floats2half2_rn(y0, y1);
                *(__half2*)&Yh[(size_t)(row + 8) * DIM + col] = __floats2half2_rn(y2, y3);
            } else {
                *(float2*)&Yf[(size_t)row * DIM + col]       = make_float2(y0, y1);
                *(float2*)&Yf[(size_t)(row + 8) * DIM + col] = make_float2(y2, y3);
            }
        }
    }
}

// ---------------------------------------------------------------------------
// Tensor-core causal flash attention, 2 CTAs/SM. Batch fixed per launch.
// CTA: 128 threads (4 warps x 16 q-rows = 64 queries), key tiles of 64.
// Smem: Q 16KB | K 2st x 16KB | V 2st x 16KB = 80KB.
// ---------------------------------------------------------------------------
#define SM_Qb 0
#define SM_Kb 16384
#define SM_Vb 49152
#define ATTN_SMEM 81920
#define KSC 0.12751741219860918f   /* (1/sqrt(128)) * log2(e) */

__device__ __forceinline__ void attn_load_kv(
    uint32_t sb, const __half* __restrict__ Kh, const __half* __restrict__ Vh,
    size_t gbase, int k0, int stage, int tid)
{
    #pragma unroll
    for (int i = 0; i < 16; i++) {
        int t = tid + i * 128;
        int kv  = t >> 10;
        int row = (t >> 4) & 63;
        int ch  = t & 15;
        int pl  = ch >> 3;
        const __half* src = (kv ? Vh : Kh) + gbase + (size_t)(k0 + row) * DIM + ch * 8;
        uint32_t dst = sb + (kv ? SM_Vb : SM_Kb) + stage * 16384
                     + pl * 8192 + SWZ((uint32_t)(row * 128 + (ch & 7) * 16));
        CP_ASYNC_16(dst, src);
    }
}

__global__ __launch_bounds__(128, 2) void attn_tc_kernel(
    const __half* __restrict__ Qh, const __half* __restrict__ Kh,
    const __half* __restrict__ Vh, __half* __restrict__ Ah, int b_fix)
{
    extern __shared__ char smem[];
    const uint32_t sb = smem_u32(smem);
    const int tid = threadIdx.x;
    const int w = tid >> 5;
    const int lane = tid & 31;
    const int qt = gridDim.x - 1 - blockIdx.x;   // big tiles first
    const int h = blockIdx.y;
    const int q0 = qt * 64;
    const size_t gbase = (size_t)b_fix * SEQ * DIM + (size_t)h * DHEAD;

    // Load Q tile (64 rows)
    #pragma unroll
    for (int i = 0; i < 8; i++) {
        int t = tid + i * 128;
        int row = (t >> 4) & 63;
        int ch  = t & 15;
        int pl  = ch >> 3;
        const __half* src = Qh + gbase + (size_t)(q0 + row) * DIM + ch * 8;
        uint32_t dst = sb + SM_Qb + pl * 8192
                     + SWZ((uint32_t)(row * 128 + (ch & 7) * 16));
        CP_ASYNC_16(dst, src);
    }
    attn_load_kv(sb, Kh, Vh, gbase, 0, 0, tid);
    CP_ASYNC_COMMIT();

    float m0v = -1e30f, m1v = -1e30f, l0v = 0.f, l1v = 0.f;
    float acc_o[16][4];
    #pragma unroll
    for (int n = 0; n < 16; n++)
        #pragma unroll
        for (int r = 0; r < 4; r++) acc_o[n][r] = 0.f;

    const int a_row = lane & 15;
    const int a_kb  = (lane >> 4) << 4;
    const int b_row = ((lane >> 4) << 3) + (lane & 7);
    const int b_kb  = ((lane >> 3) & 1) << 4;
    const int v_row = (lane & 7) + ((lane >> 3) & 1) * 8;
    const int v_cb  = ((lane >> 4) & 1) << 4;

    const int qwmin = q0 + w * 16;
    const int nt = qt + 1;

    for (int kt = 0; kt < nt; kt++) {
        __syncthreads();
        if (kt + 1 < nt)
            attn_load_kv(sb, Kh, Vh, gbase, (kt + 1) * 64, (kt + 1) & 1, tid);
        CP_ASYNC_COMMIT();
        CP_ASYNC_WAIT_1();
        __syncthreads();

        const int k0 = kt * 64;
        const int st = kt & 1;
        if (k0 > qwmin + 15) continue;

        // ---- S = Q K^T ----
        float s[8][4];
        #pragma unroll
        for (int ni = 0; ni < 8; ni++)
            #pragma unroll
            for (int r = 0; r < 4; r++) s[ni][r] = 0.f;

        #pragma unroll
        for (int ks = 0; ks < 8; ks++) {
            const int kbyte = (ks & 3) * 32;
            const int pl = ks >> 2;
            uint32_t aH[4];
            uint32_t aoff = SM_Qb + pl * 8192
                          + SWZ((uint32_t)((w * 16 + a_row) * 128 + kbyte + a_kb));
            ldmatrix_x4(aH, sb + aoff);
            #pragma unroll
            for (int pi = 0; pi < 4; pi++) {
                uint32_t bH[4];
                uint32_t boff = SM_Kb + st * 16384 + pl * 8192
                              + SWZ((uint32_t)((pi * 16 + b_row) * 128 + kbyte + b_kb));
                ldmatrix_x4(bH, sb + boff);
                mma16816(s[2 * pi],     aH, &bH[0]);
                mma16816(s[2 * pi + 1], aH, &bH[2]);
            }
        }

        // ---- causal mask ----
        const int qr0 = qwmin + (lane >> 2);
        const int qr1 = qr0 + 8;
        if (k0 + 63 > qwmin) {
            const int kc = k0 + 2 * (lane & 3);
            #pragma unroll
            for (int ni = 0; ni < 8; ni++) {
                int kb2 = kc + ni * 8;
                if (kb2     > qr0) s[ni][0] = -1e30f;
                if (kb2 + 1 > qr0) s[ni][1] = -1e30f;
                if (kb2     > qr1) s[ni][2] = -1e30f;
                if (kb2 + 1 > qr1) s[ni][3] = -1e30f;
            }
        }

        // ---- online softmax ----
        float mx0 = -1e30f, mx1 = -1e30f;
        #pragma unroll
        for (int ni = 0; ni < 8; ni++) {
            mx0 = fmaxf(mx0, fmaxf(s[ni][0], s[ni][1]));
            mx1 = fmaxf(mx1, fmaxf(s[ni][2], s[ni][3]));
        }
        mx0 = fmaxf(mx0, __shfl_xor_sync(0xffffffffu, mx0, 1));
        mx0 = fmaxf(mx0, __shfl_xor_sync(0xffffffffu, mx0, 2));
        mx1 = fmaxf(mx1, __shfl_xor_sync(0xffffffffu, mx1, 1));
        mx1 = fmaxf(mx1, __shfl_xor_sync(0xffffffffu, mx1, 2));
        float mn0 = fmaxf(m0v, mx0), mn1 = fmaxf(m1v, mx1);
        float corr0 = exp2f((m0v - mn0) * KSC);
        float corr1 = exp2f((m1v - mn1) * KSC);
        m0v = mn0; m1v = mn1;

        float rs0 = 0.f, rs1 = 0.f;
        #pragma unroll
        for (int ni = 0; ni < 8; ni++) {
            s[ni][0] = exp2f((s[ni][0] - mn0) * KSC);
            s[ni][1] = exp2f((s[ni][1] - mn0) * KSC);
            s[ni][2] = exp2f((s[ni][2] - mn1) * KSC);
            s[ni][3] = exp2f((s[ni][3] - mn1) * KSC);
            rs0 += s[ni][0] + s[ni][1];
            rs1 += s[ni][2] + s[ni][3];
        }
        rs0 += __shfl_xor_sync(0xffffffffu, rs0, 1);
        rs0 += __shfl_xor_sync(0xffffffffu, rs0, 2);
        rs1 += __shfl_xor_sync(0xffffffffu, rs1, 1);
        rs1 += __shfl_xor_sync(0xffffffffu, rs1, 2);
        l0v = l0v * corr0 + rs0;
        l1v = l1v * corr1 + rs1;

        #pragma unroll
        for (int n = 0; n < 16; n++) {
            acc_o[n][0] *= corr0; acc_o[n][1] *= corr0;
            acc_o[n][2] *= corr1; acc_o[n][3] *= corr1;
        }

        // ---- O += P V ----
        #pragma unroll
        for (int vks = 0; vks < 4; vks++) {
            uint32_t pH[4];
            #pragma unroll
            for (int half16 = 0; half16 < 2; half16++) {
                const float* sp = s[2 * vks + half16];
                __half2 h01 = __floats2half2_rn(sp[0], sp[1]);
                __half2 h23 = __floats2half2_rn(sp[2], sp[3]);
                pH[2 * half16]     = *(uint32_t*)&h01;
                pH[2 * half16 + 1] = *(uint32_t*)&h23;
            }
            const int vr = vks * 16 + v_row;
            #pragma unroll
            for (int nb = 0; nb < 8; nb++) {
                uint32_t vH[4];
                uint32_t voff = SM_Vb + st * 16384 + (nb >> 2) * 8192
                              + SWZ((uint32_t)(vr * 128 + (nb & 3) * 32 + v_cb));
                ldmatrix_x4_trans(vH, sb + voff);
                mma16816(acc_o[2 * nb],     pH, &vH[0]);
                mma16816(acc_o[2 * nb + 1], pH, &vH[2]);
            }
        }
    }

    // ---- normalize, store plain fp16 ----
    const float inv0 = 1.f / l0v;
    const float inv1 = 1.f / l1v;
    const size_t r0o = gbase + (size_t)(q0 + w * 16 + (lane >> 2)) * DIM;
    const size_t r1o = r0o + 8 * DIM;
    #pragma unroll
    for (int n = 0; n < 16; n++) {
        int col = n * 8 + 2 * (lane & 3);
        *(__half2*)&Ah[r0o + col] =
            __floats2half2_rn(acc_o[n][0] * inv0, acc_o[n][1] * inv0);
        *(__half2*)&Ah[r1o + col] =
            __floats2half2_rn(acc_o[n][2] * inv1, acc_o[n][3] * inv1);
    }
}

// ---------------------------------------------------------------------------
extern "C" void kernel_launch(void* const* d_in, const int* in_sizes, int n_in,
                              void* d_out, int out_size)
{
    const float* x  = (const float*)d_in[0];
    const float* Wq = (const float*)d_in[1];
    const float* bq = (const float*)d_in[2];
    const float* Wk = (const float*)d_in[3];
    const float* bk = (const float*)d_in[4];
    const float* Wv = (const float*)d_in[5];
    const float* bv = (const float*)d_in[6];
    const float* Wo = (const float*)d_in[7];
    const float* bo = (const float*)d_in[8];
    float* out = (float*)d_out;

    __half *Xhi, *Whi, *Qh, *Kh, *Vh, *Ah;
    cudaGetSymbolAddress((void**)&Xhi, g_Xhi);
    cudaGetSymbolAddress((void**)&Whi, g_Whi);
    cudaGetSymbolAddress((void**)&Qh,  g_Qh);
    cudaGetSymbolAddress((void**)&Kh,  g_Kh);
    cudaGetSymbolAddress((void**)&Vh,  g_Vh);
    cudaGetSymbolAddress((void**)&Ah,  g_Ah);

    cudaFuncSetAttribute(gemm_sp_kernel<true>,
                         cudaFuncAttributeMaxDynamicSharedMemorySize, GEMM_SMEM);
    cudaFuncSetAttribute(gemm_sp_kernel<false>,
                         cudaFuncAttributeMaxDynamicSharedMemorySize, GEMM_SMEM);
    cudaFuncSetAttribute(attn_tc_kernel,
                         cudaFuncAttributeMaxDynamicSharedMemorySize, ATTN_SMEM);

    // One-time stream/event creation (first call is the uncaptured
    // correctness run; subsequent captured calls launch an identical DAG).
    static cudaStream_t s2 = nullptr;
    static cudaEvent_t e0 = nullptr, eJoin = nullptr;
    if (!s2) {
        cudaStreamCreateWithFlags(&s2, cudaStreamNonBlocking);
        cudaEventCreateWithFlags(&e0, cudaEventDisableTiming);
        cudaEventCreateWithFlags(&eJoin, cudaEventDisableTiming);
    }

    const int nX4 = MTOT * DIM / 4;
    const int nW4 = DIM * DIM / 4;
    const size_t WSZ = (size_t)DIM * DIM;
    const int MB_HALF = SEQ / GTM;   // 16 m-blocks per batch half

    // Default stream: splits + batch-0 pipeline
    splitX_hi_kernel<<<nX4 / 4 / 256, 256>>>(x, Xhi, nX4);
    splitW_kernel<<<dim3(nW4 / 4 / 256, 4), 256>>>(Wq, Wk, Wv, Wo, Whi, nW4);

    gemm_sp_kernel<true><<<dim3(MB_HALF, 48), 256, GEMM_SMEM>>>(
        Xhi, Whi, bq, bk, bv, Qh, Kh, Vh, nullptr, 16, 0);
    cudaEventRecord(e0, 0);

    // Stream 2: batch-1 pipeline, starts after batch-0 QKV is done
    cudaStreamWaitEvent(s2, e0, 0);
    gemm_sp_kernel<true><<<dim3(MB_HALF, 48), 256, GEMM_SMEM, s2>>>(
        Xhi, Whi, bq, bk, bv, Qh, Kh, Vh, nullptr, 16, SEQ);

    // Default stream: attention + O-proj for batch 0 (overlaps QKV b1)
    attn_tc_kernel<<<dim3(SEQ / 64, HEADS), 128, ATTN_SMEM>>>(Qh, Kh, Vh, Ah, 0);
    gemm_sp_kernel<false><<<dim3(MB_HALF, 16), 256, GEMM_SMEM>>>(
        Ah, Whi + 3 * WSZ, bo, nullptr, nullptr, nullptr, nullptr, nullptr, out, 16, 0);

    // Stream 2: attention + O-proj for batch 1
    attn_tc_kernel<<<dim3(SEQ / 64, HEADS), 128, ATTN_SMEM, s2>>>(Qh, Kh, Vh, Ah, 1);
    gemm_sp_kernel<false><<<dim3(MB_HALF, 16), 256, GEMM_SMEM, s2>>>(
        Ah, Whi + 3 * WSZ, bo, nullptr, nullptr, nullptr, nullptr, nullptr, out, 16, SEQ);

    // Join
    cudaEventRecord(eJoin, s2);
    cudaStreamWaitEvent(0, eJoin, 0);
}